// round 1
// baseline (speedup 1.0000x reference)
#include <cuda_runtime.h>
#include <math.h>

#define SEQ 2048
#define HID 1024
#define NH 16
#define NKV 4
#define HD 64
#define SCALING 0.125f

// Scratch (device globals: no runtime allocation allowed)
__device__ float g_Q[NH * SEQ * HD];    // [h][m][d], pre-scaled by 0.125
__device__ float g_K[NKV * SEQ * HD];   // [kvh][m][d]
__device__ float g_V[NKV * SEQ * HD];   // [kvh][m][d]
__device__ float g_AO[SEQ * HID];       // [m][h*64+d]

// ---------------------------------------------------------------------------
// Kernel 1: fused QKV projection + RoPE.
// C = X(2048x1024) @ [Wq | Wk | Wv] (1024 x 1536), tiles 64x64, BK=16,
// 256 threads, 4x4 microtile. RoPE applied in epilogue via shared exchange.
// ---------------------------------------------------------------------------
__global__ __launch_bounds__(256) void qkv_rope_kernel(
    const float* __restrict__ X,
    const float* __restrict__ Wq,
    const float* __restrict__ Wk,
    const float* __restrict__ Wv,
    const float* __restrict__ cs,   // [2048][64]
    const float* __restrict__ sn)   // [2048][64]
{
    const int ntile = blockIdx.x;          // 0..23
    const int m0 = blockIdx.y * 64;        // 0..2047
    const int n0g = ntile * 64;

    const float* Bmat;
    int ldb, ncol0, kind;                  // kind: 0=Q, 1=K, 2=V
    if (n0g < 1024)       { Bmat = Wq; ldb = 1024; ncol0 = n0g;        kind = 0; }
    else if (n0g < 1280)  { Bmat = Wk; ldb = 256;  ncol0 = n0g - 1024; kind = 1; }
    else                  { Bmat = Wv; ldb = 256;  ncol0 = n0g - 1280; kind = 2; }

    __shared__ float As[16][65];   // [k][m]
    __shared__ float Bs[16][65];   // [k][n]
    __shared__ float Cs[64][65];   // epilogue exchange

    const int tid = threadIdx.y * 16 + threadIdx.x;
    const int r0 = threadIdx.y * 4;
    const int c0 = threadIdx.x * 4;

    float acc[4][4] = {};

    for (int k0 = 0; k0 < 1024; k0 += 16) {
        #pragma unroll
        for (int t = 0; t < 4; t++) {
            int idx = tid + t * 256;
            int r = idx >> 4, kk = idx & 15;
            As[kk][r] = X[(m0 + r) * 1024 + k0 + kk];
        }
        #pragma unroll
        for (int t = 0; t < 4; t++) {
            int idx = tid + t * 256;
            int kk = idx >> 6, c = idx & 63;
            Bs[kk][c] = Bmat[(k0 + kk) * ldb + ncol0 + c];
        }
        __syncthreads();
        #pragma unroll
        for (int kk = 0; kk < 16; kk++) {
            float a[4], b[4];
            #pragma unroll
            for (int i = 0; i < 4; i++) a[i] = As[kk][r0 + i];
            #pragma unroll
            for (int j = 0; j < 4; j++) b[j] = Bs[kk][c0 + j];
            #pragma unroll
            for (int i = 0; i < 4; i++)
                #pragma unroll
                for (int j = 0; j < 4; j++)
                    acc[i][j] = fmaf(a[i], b[j], acc[i][j]);
        }
        __syncthreads();
    }

    // Stage tile into shared for RoPE partner exchange
    #pragma unroll
    for (int i = 0; i < 4; i++)
        #pragma unroll
        for (int j = 0; j < 4; j++)
            Cs[r0 + i][c0 + j] = acc[i][j];
    __syncthreads();

    const int head_local = (kind == 0) ? (n0g >> 6) : (ncol0 >> 6);
    #pragma unroll
    for (int i = 0; i < 4; i++) {
        const int r = r0 + i;
        const int m = m0 + r;
        #pragma unroll
        for (int j = 0; j < 4; j++) {
            const int d = c0 + j;
            float val = Cs[r][d];
            float outv;
            if (kind == 2) {
                outv = val;   // V: no RoPE
            } else {
                float partner = (d < 32) ? -Cs[r][d + 32] : Cs[r][d - 32];
                outv = val * cs[m * HD + d] + partner * sn[m * HD + d];
                if (kind == 0) outv *= SCALING;
            }
            const int dst = head_local * SEQ * HD + m * HD + d;
            if (kind == 0)      g_Q[dst] = outv;
            else if (kind == 1) g_K[dst] = outv;
            else                g_V[dst] = outv;
        }
    }
}

// ---------------------------------------------------------------------------
// Kernel 2: flash attention. One block per (query-tile of 64, head).
// Online softmax over 32 KV tiles of 64. No mask (all-true).
// Dynamic smem: Qs[64][65] + Kt[64][65] (transposed) + Vs[64][65] + Ss[64][65]
// ---------------------------------------------------------------------------
__global__ __launch_bounds__(256) void flash_kernel()
{
    const int q0 = blockIdx.x * 64;
    const int h  = blockIdx.y;
    const int kvh = h >> 2;                // n_rep = 4

    extern __shared__ float sm[];
    float* Qs = sm;                        // [r][d] stride 65
    float* Kt = sm + 64 * 65;              // [d][r] stride 65 (transposed)
    float* Vs = sm + 2 * 64 * 65;          // [k][d] stride 65
    float* Ss = sm + 3 * 64 * 65;          // [r][k] stride 65
    __shared__ float row_m[64], row_l[64], row_scale[64];

    const int tid = threadIdx.x;
    const float* Qg = g_Q + h * SEQ * HD;
    const float* Kg = g_K + kvh * SEQ * HD;
    const float* Vg = g_V + kvh * SEQ * HD;

    #pragma unroll
    for (int t = 0; t < 16; t++) {
        int idx = tid + t * 256;
        int r = idx >> 6, d = idx & 63;
        Qs[r * 65 + d] = Qg[(q0 + r) * HD + d];
    }
    if (tid < 64) { row_m[tid] = -INFINITY; row_l[tid] = 0.0f; }

    const int r0 = (tid >> 4) * 4;
    const int c0 = (tid & 15) * 4;
    float acc[4][4] = {};

    for (int kt = 0; kt < 32; kt++) {
        __syncthreads();   // protect Kt/Vs/Ss reuse across iterations
        const int k0 = kt * 64;
        #pragma unroll
        for (int t = 0; t < 16; t++) {
            int idx = tid + t * 256;
            int r = idx >> 6, d = idx & 63;
            Kt[d * 65 + r] = Kg[(k0 + r) * HD + d];   // transposed store
            Vs[r * 65 + d] = Vg[(k0 + r) * HD + d];
        }
        __syncthreads();

        // S = (Q*0.125) @ K^T  (Q pre-scaled)
        float s[4][4] = {};
        #pragma unroll 8
        for (int d = 0; d < 64; d++) {
            float a[4], b[4];
            #pragma unroll
            for (int i = 0; i < 4; i++) a[i] = Qs[(r0 + i) * 65 + d];
            #pragma unroll
            for (int j = 0; j < 4; j++) b[j] = Kt[d * 65 + c0 + j];
            #pragma unroll
            for (int i = 0; i < 4; i++)
                #pragma unroll
                for (int j = 0; j < 4; j++)
                    s[i][j] = fmaf(a[i], b[j], s[i][j]);
        }
        #pragma unroll
        for (int i = 0; i < 4; i++)
            #pragma unroll
            for (int j = 0; j < 4; j++)
                Ss[(r0 + i) * 65 + c0 + j] = s[i][j];
        __syncthreads();

        // Online softmax stats per row
        if (tid < 64) {
            const int r = tid;
            float mold = row_m[r];
            float mnew = mold;
            #pragma unroll 8
            for (int k = 0; k < 64; k++) mnew = fmaxf(mnew, Ss[r * 65 + k]);
            float sc = (mold == -INFINITY) ? 0.0f : __expf(mold - mnew);
            float sum = 0.0f;
            #pragma unroll 8
            for (int k = 0; k < 64; k++) {
                float p = __expf(Ss[r * 65 + k] - mnew);
                Ss[r * 65 + k] = p;
                sum += p;
            }
            row_l[r] = row_l[r] * sc + sum;
            row_m[r] = mnew;
            row_scale[r] = sc;
        }
        __syncthreads();

        // O = O*scale + P @ V
        float scs[4];
        #pragma unroll
        for (int i = 0; i < 4; i++) scs[i] = row_scale[r0 + i];
        #pragma unroll
        for (int i = 0; i < 4; i++)
            #pragma unroll
            for (int j = 0; j < 4; j++)
                acc[i][j] *= scs[i];
        #pragma unroll 8
        for (int k = 0; k < 64; k++) {
            float p[4], v[4];
            #pragma unroll
            for (int i = 0; i < 4; i++) p[i] = Ss[(r0 + i) * 65 + k];
            #pragma unroll
            for (int j = 0; j < 4; j++) v[j] = Vs[k * 65 + c0 + j];
            #pragma unroll
            for (int i = 0; i < 4; i++)
                #pragma unroll
                for (int j = 0; j < 4; j++)
                    acc[i][j] = fmaf(p[i], v[j], acc[i][j]);
        }
    }
    __syncthreads();

    float inv[4];
    #pragma unroll
    for (int i = 0; i < 4; i++) inv[i] = 1.0f / row_l[r0 + i];
    #pragma unroll
    for (int i = 0; i < 4; i++)
        #pragma unroll
        for (int j = 0; j < 4; j++)
            g_AO[(q0 + r0 + i) * HID + h * HD + c0 + j] = acc[i][j] * inv[i];
}

// ---------------------------------------------------------------------------
// Kernel 3: output projection. out = AO(2048x1024) @ Wo(1024x1024).
// ---------------------------------------------------------------------------
__global__ __launch_bounds__(256) void oproj_kernel(
    const float* __restrict__ Wo, float* __restrict__ out)
{
    const int n0 = blockIdx.x * 64;
    const int m0 = blockIdx.y * 64;

    __shared__ float As[16][65];
    __shared__ float Bs[16][65];

    const int tid = threadIdx.y * 16 + threadIdx.x;
    const int r0 = threadIdx.y * 4;
    const int c0 = threadIdx.x * 4;

    float acc[4][4] = {};

    for (int k0 = 0; k0 < 1024; k0 += 16) {
        #pragma unroll
        for (int t = 0; t < 4; t++) {
            int idx = tid + t * 256;
            int r = idx >> 4, kk = idx & 15;
            As[kk][r] = g_AO[(m0 + r) * 1024 + k0 + kk];
        }
        #pragma unroll
        for (int t = 0; t < 4; t++) {
            int idx = tid + t * 256;
            int kk = idx >> 6, c = idx & 63;
            Bs[kk][c] = Wo[(k0 + kk) * 1024 + n0 + c];
        }
        __syncthreads();
        #pragma unroll
        for (int kk = 0; kk < 16; kk++) {
            float a[4], b[4];
            #pragma unroll
            for (int i = 0; i < 4; i++) a[i] = As[kk][r0 + i];
            #pragma unroll
            for (int j = 0; j < 4; j++) b[j] = Bs[kk][c0 + j];
            #pragma unroll
            for (int i = 0; i < 4; i++)
                #pragma unroll
                for (int j = 0; j < 4; j++)
                    acc[i][j] = fmaf(a[i], b[j], acc[i][j]);
        }
        __syncthreads();
    }

    #pragma unroll
    for (int i = 0; i < 4; i++)
        #pragma unroll
        for (int j = 0; j < 4; j++)
            out[(m0 + r0 + i) * 1024 + n0 + c0 + j] = acc[i][j];
}

// ---------------------------------------------------------------------------
// Launch. Inputs (metadata order): hidden_states, cos, sin, attention_mask,
// Wq, Wk, Wv, Wo. attention_mask is all-true -> ignored.
// ---------------------------------------------------------------------------
extern "C" void kernel_launch(void* const* d_in, const int* in_sizes, int n_in,
                              void* d_out, int out_size)
{
    const float* X  = (const float*)d_in[0];
    const float* cs = (const float*)d_in[1];
    const float* sn = (const float*)d_in[2];
    // d_in[3] = attention_mask (all ones) — unused
    const float* Wq = (const float*)d_in[4];
    const float* Wk = (const float*)d_in[5];
    const float* Wv = (const float*)d_in[6];
    const float* Wo = (const float*)d_in[7];
    float* out = (float*)d_out;

    dim3 blk(16, 16);

    // 1. QKV + RoPE
    qkv_rope_kernel<<<dim3(24, 32), blk>>>(X, Wq, Wk, Wv, cs, sn);

    // 2. Flash attention
    const size_t smem = 4 * 64 * 65 * sizeof(float);   // 66560 B
    cudaFuncSetAttribute(flash_kernel,
                         cudaFuncAttributeMaxDynamicSharedMemorySize, (int)smem);
    flash_kernel<<<dim3(32, 16), 256, smem>>>();

    // 3. Output projection
    oproj_kernel<<<dim3(16, 32), blk>>>(Wo, out);
}

// round 4
// speedup vs baseline: 2.4624x; 2.4624x over previous
#include <cuda_runtime.h>
#include <math.h>
#include <stdint.h>

#define SEQ 2048
#define HID 1024
#define NH 16
#define NKV 4
#define HD 64
#define SCALING 0.125f

// Scratch (device globals; 16B-aligned: targets of float4 access)
__device__ __align__(16) float g_Q[NH * SEQ * HD];    // [h][m][d], RoPE'd, pre-scaled, tf32
__device__ __align__(16) float g_K[NKV * SEQ * HD];   // [kvh][m][d], RoPE'd, tf32
__device__ __align__(16) float g_V[NKV * SEQ * HD];   // [kvh][m][d], tf32
__device__ __align__(16) float g_AO[SEQ * HID];       // [m][h*64+d] fp32

// ---------------------------------------------------------------------------
// Helpers: tf32 rounding + m16n8k8 tf32 MMA
// ---------------------------------------------------------------------------
__device__ __forceinline__ float f2tff(float x) {
    uint32_t r;
    asm("cvt.rna.tf32.f32 %0, %1;" : "=r"(r) : "f"(x));
    return __uint_as_float(r);
}

__device__ __forceinline__ void mma8(float c[4],
                                     uint32_t a0, uint32_t a1, uint32_t a2, uint32_t a3,
                                     uint32_t b0, uint32_t b1) {
    asm volatile(
        "mma.sync.aligned.m16n8k8.row.col.f32.tf32.tf32.f32 "
        "{%0,%1,%2,%3}, {%4,%5,%6,%7}, {%8,%9}, {%0,%1,%2,%3};"
        : "+f"(c[0]), "+f"(c[1]), "+f"(c[2]), "+f"(c[3])
        : "r"(a0), "r"(a1), "r"(a2), "r"(a3), "r"(b0), "r"(b1));
}

// ---------------------------------------------------------------------------
// Kernel 1: fused QKV projection + RoPE (tf32 tensor cores).
// C = X(2048x1024) @ [Wq|Wk|Wv](1024x1536). Block tile 64x64, BK=32.
// 8 warps in 4x2 grid, warp tile 16x32. RoPE in epilogue via smem exchange.
// ---------------------------------------------------------------------------
__global__ __launch_bounds__(256) void qkv_rope_kernel(
    const float* __restrict__ X,
    const float* __restrict__ Wq,
    const float* __restrict__ Wk,
    const float* __restrict__ Wv,
    const float* __restrict__ cs,
    const float* __restrict__ sn)
{
    const int n0g = blockIdx.x * 64;
    const int m0  = blockIdx.y * 64;

    const float* Bmat;
    int ldb, ncol0, kind;                  // 0=Q, 1=K, 2=V
    if (n0g < 1024)       { Bmat = Wq; ldb = 1024; ncol0 = n0g;        kind = 0; }
    else if (n0g < 1280)  { Bmat = Wk; ldb = 256;  ncol0 = n0g - 1024; kind = 1; }
    else                  { Bmat = Wv; ldb = 256;  ncol0 = n0g - 1280; kind = 2; }

    __shared__ float As[64][36];   // [m][k]
    __shared__ float Bs[32][68];   // [k][n]
    __shared__ float Cs[64][68];   // epilogue exchange

    const int tid  = threadIdx.x;
    const int lane = tid & 31, warp = tid >> 5;
    const int wm = warp & 3, wn = warp >> 2;
    const int g = lane >> 2, t = lane & 3;

    float cfr[4][4] = {};

    for (int k0 = 0; k0 < 1024; k0 += 32) {
        #pragma unroll
        for (int it = 0; it < 2; it++) {
            int id = tid + it * 256;
            int r = id >> 3, c4 = (id & 7) * 4;
            float4 v = *(const float4*)&X[(m0 + r) * 1024 + k0 + c4];
            As[r][c4 + 0] = f2tff(v.x); As[r][c4 + 1] = f2tff(v.y);
            As[r][c4 + 2] = f2tff(v.z); As[r][c4 + 3] = f2tff(v.w);
        }
        #pragma unroll
        for (int it = 0; it < 2; it++) {
            int id = tid + it * 256;
            int r = id >> 4, c4 = (id & 15) * 4;
            float4 v = *(const float4*)&Bmat[(k0 + r) * ldb + ncol0 + c4];
            Bs[r][c4 + 0] = f2tff(v.x); Bs[r][c4 + 1] = f2tff(v.y);
            Bs[r][c4 + 2] = f2tff(v.z); Bs[r][c4 + 3] = f2tff(v.w);
        }
        __syncthreads();
        #pragma unroll
        for (int ks = 0; ks < 4; ks++) {
            const int kk = ks * 8;
            uint32_t a0 = __float_as_uint(As[wm * 16 + g    ][kk + t    ]);
            uint32_t a1 = __float_as_uint(As[wm * 16 + g + 8][kk + t    ]);
            uint32_t a2 = __float_as_uint(As[wm * 16 + g    ][kk + t + 4]);
            uint32_t a3 = __float_as_uint(As[wm * 16 + g + 8][kk + t + 4]);
            #pragma unroll
            for (int j = 0; j < 4; j++) {
                int nb = wn * 32 + j * 8 + g;
                uint32_t b0 = __float_as_uint(Bs[kk + t    ][nb]);
                uint32_t b1 = __float_as_uint(Bs[kk + t + 4][nb]);
                mma8(cfr[j], a0, a1, a2, a3, b0, b1);
            }
        }
        __syncthreads();
    }

    // Fragments -> Cs for RoPE partner exchange
    #pragma unroll
    for (int j = 0; j < 4; j++) {
        int col = wn * 32 + j * 8 + 2 * t;
        Cs[wm * 16 + g    ][col    ] = cfr[j][0];
        Cs[wm * 16 + g    ][col + 1] = cfr[j][1];
        Cs[wm * 16 + g + 8][col    ] = cfr[j][2];
        Cs[wm * 16 + g + 8][col + 1] = cfr[j][3];
    }
    __syncthreads();

    const int head_local = (kind == 0) ? (n0g >> 6) : (ncol0 >> 6);
    const int r0e = (tid >> 4) * 4;
    const int c0e = (tid & 15) * 4;
    #pragma unroll
    for (int i = 0; i < 4; i++) {
        const int r = r0e + i;
        const int m = m0 + r;
        #pragma unroll
        for (int j = 0; j < 4; j++) {
            const int d = c0e + j;
            float val = Cs[r][d];
            float outv;
            if (kind == 2) {
                outv = val;
            } else {
                float partner = (d < 32) ? -Cs[r][d + 32] : Cs[r][d - 32];
                outv = val * cs[m * HD + d] + partner * sn[m * HD + d];
                if (kind == 0) outv *= SCALING;
            }
            outv = f2tff(outv);    // pre-round for downstream tf32 MMA
            const int dst = head_local * SEQ * HD + m * HD + d;
            if (kind == 0)      g_Q[dst] = outv;
            else if (kind == 1) g_K[dst] = outv;
            else                g_V[dst] = outv;
        }
    }
}

// ---------------------------------------------------------------------------
// Kernel 2: flash attention (tf32 tensor cores).
// Block = (qtile 64, head). 8 warps: warp tile 16x32 of the 64x64 S / O tiles.
// Online softmax: 4 threads per row, shuffle reductions.
// ---------------------------------------------------------------------------
__global__ __launch_bounds__(256) void flash_kernel()
{
    const int q0  = blockIdx.x * 64;
    const int h   = blockIdx.y;
    const int kvh = h >> 2;

    extern __shared__ float smf[];
    float* Qs = smf;                 // [64][68]
    float* Ks = smf + 64 * 68;       // [kk][d]
    float* Vs = smf + 2 * 64 * 68;   // [k][d]
    float* SP = smf + 3 * 64 * 68;   // S (fp32), then P (tf32-rounded)
    __shared__ float row_m[64], row_l[64], row_scale[64];

    const int tid  = threadIdx.x;
    const int lane = tid & 31, warp = tid >> 5;
    const int wm = warp & 3, wn = warp >> 2;
    const int g = lane >> 2, t = lane & 3;

    const float* Qg = g_Q + h * SEQ * HD + q0 * HD;
    const float* Kg = g_K + kvh * SEQ * HD;
    const float* Vg = g_V + kvh * SEQ * HD;

    #pragma unroll
    for (int it = 0; it < 4; it++) {
        int id = tid + it * 256;
        int r = id >> 4, c4 = (id & 15) * 4;
        *(float4*)&Qs[r * 68 + c4] = *(const float4*)&Qg[r * 64 + c4];
    }
    if (tid < 64) { row_m[tid] = -INFINITY; row_l[tid] = 0.0f; }

    float ofr[4][4] = {};

    for (int kt = 0; kt < 32; kt++) {
        __syncthreads();    // protect Ks/Vs/SP reuse
        const float* Kp = Kg + kt * 64 * 64;
        const float* Vp = Vg + kt * 64 * 64;
        #pragma unroll
        for (int it = 0; it < 4; it++) {
            int id = tid + it * 256;
            int r = id >> 4, c4 = (id & 15) * 4;
            *(float4*)&Ks[r * 68 + c4] = *(const float4*)&Kp[r * 64 + c4];
            *(float4*)&Vs[r * 68 + c4] = *(const float4*)&Vp[r * 64 + c4];
        }
        __syncthreads();

        // S = Q @ K^T (Q pre-scaled). k-dim = d (64) -> 8 MMA k-steps.
        float sfr[4][4] = {};
        #pragma unroll
        for (int ks = 0; ks < 8; ks++) {
            const int kk = ks * 8;
            uint32_t a0 = __float_as_uint(Qs[(wm * 16 + g    ) * 68 + kk + t    ]);
            uint32_t a1 = __float_as_uint(Qs[(wm * 16 + g + 8) * 68 + kk + t    ]);
            uint32_t a2 = __float_as_uint(Qs[(wm * 16 + g    ) * 68 + kk + t + 4]);
            uint32_t a3 = __float_as_uint(Qs[(wm * 16 + g + 8) * 68 + kk + t + 4]);
            #pragma unroll
            for (int j = 0; j < 4; j++) {
                int nb = wn * 32 + j * 8 + g;
                uint32_t b0 = __float_as_uint(Ks[nb * 68 + kk + t    ]);
                uint32_t b1 = __float_as_uint(Ks[nb * 68 + kk + t + 4]);
                mma8(sfr[j], a0, a1, a2, a3, b0, b1);
            }
        }

        #pragma unroll
        for (int j = 0; j < 4; j++) {
            int col = wn * 32 + j * 8 + 2 * t;
            SP[(wm * 16 + g    ) * 68 + col    ] = sfr[j][0];
            SP[(wm * 16 + g    ) * 68 + col + 1] = sfr[j][1];
            SP[(wm * 16 + g + 8) * 68 + col    ] = sfr[j][2];
            SP[(wm * 16 + g + 8) * 68 + col + 1] = sfr[j][3];
        }
        __syncthreads();

        // Online softmax: 4 threads per row, 16 cols each.
        {
            const int row = tid >> 2, part = tid & 3;
            float* Sr = SP + row * 68 + part * 16;
            float mloc = -INFINITY;
            #pragma unroll
            for (int i = 0; i < 16; i++) mloc = fmaxf(mloc, Sr[i]);
            mloc = fmaxf(mloc, __shfl_xor_sync(0xffffffffu, mloc, 1));
            mloc = fmaxf(mloc, __shfl_xor_sync(0xffffffffu, mloc, 2));
            float mold = row_m[row];
            float mnew = fmaxf(mold, mloc);
            float ssum = 0.0f;
            #pragma unroll
            for (int i = 0; i < 16; i++) {
                float p = __expf(Sr[i] - mnew);
                ssum += p;
                Sr[i] = f2tff(p);       // P rounded for tf32 MMA
            }
            ssum += __shfl_xor_sync(0xffffffffu, ssum, 1);
            ssum += __shfl_xor_sync(0xffffffffu, ssum, 2);
            if (part == 0) {
                float sc = __expf(mold - mnew);   // first iter: exp(-inf)=0
                row_scale[row] = sc;
                row_l[row] = row_l[row] * sc + ssum;
                row_m[row] = mnew;
            }
        }
        __syncthreads();

        // O = O*scale + P @ V
        float s1 = row_scale[wm * 16 + g];
        float s2 = row_scale[wm * 16 + g + 8];
        #pragma unroll
        for (int j = 0; j < 4; j++) {
            ofr[j][0] *= s1; ofr[j][1] *= s1;
            ofr[j][2] *= s2; ofr[j][3] *= s2;
        }
        #pragma unroll
        for (int ks = 0; ks < 8; ks++) {
            const int kk = ks * 8;
            uint32_t a0 = __float_as_uint(SP[(wm * 16 + g    ) * 68 + kk + t    ]);
            uint32_t a1 = __float_as_uint(SP[(wm * 16 + g + 8) * 68 + kk + t    ]);
            uint32_t a2 = __float_as_uint(SP[(wm * 16 + g    ) * 68 + kk + t + 4]);
            uint32_t a3 = __float_as_uint(SP[(wm * 16 + g + 8) * 68 + kk + t + 4]);
            #pragma unroll
            for (int j = 0; j < 4; j++) {
                int nb = wn * 32 + j * 8 + g;
                uint32_t b0 = __float_as_uint(Vs[(kk + t    ) * 68 + nb]);
                uint32_t b1 = __float_as_uint(Vs[(kk + t + 4) * 68 + nb]);
                mma8(ofr[j], a0, a1, a2, a3, b0, b1);
            }
        }
    }

    // Normalize, stage through SP, coalesced store.
    float l1 = 1.0f / row_l[wm * 16 + g];
    float l2 = 1.0f / row_l[wm * 16 + g + 8];
    __syncthreads();
    #pragma unroll
    for (int j = 0; j < 4; j++) {
        int col = wn * 32 + j * 8 + 2 * t;
        SP[(wm * 16 + g    ) * 68 + col    ] = ofr[j][0] * l1;
        SP[(wm * 16 + g    ) * 68 + col + 1] = ofr[j][1] * l1;
        SP[(wm * 16 + g + 8) * 68 + col    ] = ofr[j][2] * l2;
        SP[(wm * 16 + g + 8) * 68 + col + 1] = ofr[j][3] * l2;
    }
    __syncthreads();
    #pragma unroll
    for (int it = 0; it < 4; it++) {
        int id = tid + it * 256;
        int r = id >> 4, c4 = (id & 15) * 4;
        *(float4*)&g_AO[(q0 + r) * 1024 + h * 64 + c4] = *(const float4*)&SP[r * 68 + c4];
    }
}

// ---------------------------------------------------------------------------
// Kernel 3: output projection (tf32). out = AO(2048x1024) @ Wo(1024x1024).
// ---------------------------------------------------------------------------
__global__ __launch_bounds__(256) void oproj_kernel(
    const float* __restrict__ Wo, float* __restrict__ out)
{
    const int n0 = blockIdx.x * 64;
    const int m0 = blockIdx.y * 64;

    __shared__ float As[64][36];
    __shared__ float Bs[32][68];
    __shared__ float Cs[64][68];

    const int tid  = threadIdx.x;
    const int lane = tid & 31, warp = tid >> 5;
    const int wm = warp & 3, wn = warp >> 2;
    const int g = lane >> 2, t = lane & 3;

    float cfr[4][4] = {};

    for (int k0 = 0; k0 < 1024; k0 += 32) {
        #pragma unroll
        for (int it = 0; it < 2; it++) {
            int id = tid + it * 256;
            int r = id >> 3, c4 = (id & 7) * 4;
            float4 v = *(const float4*)&g_AO[(m0 + r) * 1024 + k0 + c4];
            As[r][c4 + 0] = f2tff(v.x); As[r][c4 + 1] = f2tff(v.y);
            As[r][c4 + 2] = f2tff(v.z); As[r][c4 + 3] = f2tff(v.w);
        }
        #pragma unroll
        for (int it = 0; it < 2; it++) {
            int id = tid + it * 256;
            int r = id >> 4, c4 = (id & 15) * 4;
            float4 v = *(const float4*)&Wo[(k0 + r) * 1024 + n0 + c4];
            Bs[r][c4 + 0] = f2tff(v.x); Bs[r][c4 + 1] = f2tff(v.y);
            Bs[r][c4 + 2] = f2tff(v.z); Bs[r][c4 + 3] = f2tff(v.w);
        }
        __syncthreads();
        #pragma unroll
        for (int ks = 0; ks < 4; ks++) {
            const int kk = ks * 8;
            uint32_t a0 = __float_as_uint(As[wm * 16 + g    ][kk + t    ]);
            uint32_t a1 = __float_as_uint(As[wm * 16 + g + 8][kk + t    ]);
            uint32_t a2 = __float_as_uint(As[wm * 16 + g    ][kk + t + 4]);
            uint32_t a3 = __float_as_uint(As[wm * 16 + g + 8][kk + t + 4]);
            #pragma unroll
            for (int j = 0; j < 4; j++) {
                int nb = wn * 32 + j * 8 + g;
                uint32_t b0 = __float_as_uint(Bs[kk + t    ][nb]);
                uint32_t b1 = __float_as_uint(Bs[kk + t + 4][nb]);
                mma8(cfr[j], a0, a1, a2, a3, b0, b1);
            }
        }
        __syncthreads();
    }

    #pragma unroll
    for (int j = 0; j < 4; j++) {
        int col = wn * 32 + j * 8 + 2 * t;
        Cs[wm * 16 + g    ][col    ] = cfr[j][0];
        Cs[wm * 16 + g    ][col + 1] = cfr[j][1];
        Cs[wm * 16 + g + 8][col    ] = cfr[j][2];
        Cs[wm * 16 + g + 8][col + 1] = cfr[j][3];
    }
    __syncthreads();
    #pragma unroll
    for (int it = 0; it < 4; it++) {
        int id = tid + it * 256;
        int r = id >> 4, c4 = (id & 15) * 4;
        // FIXED: was &Cs[r*68+c4] on a float[64][68] (out-of-bounds by 68x).
        *(float4*)&out[(m0 + r) * 1024 + n0 + c4] = *(const float4*)&Cs[r][c4];
    }
}

// ---------------------------------------------------------------------------
// Launch. Inputs: hidden_states, cos, sin, attention_mask (all-true, unused),
// Wq, Wk, Wv, Wo.
// ---------------------------------------------------------------------------
extern "C" void kernel_launch(void* const* d_in, const int* in_sizes, int n_in,
                              void* d_out, int out_size)
{
    const float* X  = (const float*)d_in[0];
    const float* cs = (const float*)d_in[1];
    const float* sn = (const float*)d_in[2];
    const float* Wq = (const float*)d_in[4];
    const float* Wk = (const float*)d_in[5];
    const float* Wv = (const float*)d_in[6];
    const float* Wo = (const float*)d_in[7];
    float* out = (float*)d_out;

    qkv_rope_kernel<<<dim3(24, 32), 256>>>(X, Wq, Wk, Wv, cs, sn);

    const size_t smem = 4 * 64 * 68 * sizeof(float);   // 69632 B
    cudaFuncSetAttribute(flash_kernel,
                         cudaFuncAttributeMaxDynamicSharedMemorySize, (int)smem);
    flash_kernel<<<dim3(32, 16), 256, smem>>>();

    oproj_kernel<<<dim3(16, 32), 256>>>(Wo, out);
}

// round 5
// speedup vs baseline: 3.3499x; 1.3604x over previous
#include <cuda_runtime.h>
#include <math.h>
#include <stdint.h>

#define SEQ 2048
#define HID 1024
#define NH 16
#define NKV 4
#define HD 64
#define SCALING 0.125f

// Scratch (device globals; 16B-aligned: targets of float4 access)
__device__ __align__(16) float g_Q[NH * SEQ * HD];    // [h][m][d], RoPE'd, pre-scaled, tf32
__device__ __align__(16) float g_K[NKV * SEQ * HD];   // [kvh][m][d], RoPE'd, tf32
__device__ __align__(16) float g_V[NKV * SEQ * HD];   // [kvh][m][d], tf32
__device__ __align__(16) float g_AO[SEQ * HID];       // [m][h*64+d] fp32

// ---------------------------------------------------------------------------
// Helpers
// ---------------------------------------------------------------------------
__device__ __forceinline__ float f2tff(float x) {
    uint32_t r;
    asm("cvt.rna.tf32.f32 %0, %1;" : "=r"(r) : "f"(x));
    return __uint_as_float(r);
}

__device__ __forceinline__ void mma8(float c[4],
                                     uint32_t a0, uint32_t a1, uint32_t a2, uint32_t a3,
                                     uint32_t b0, uint32_t b1) {
    asm volatile(
        "mma.sync.aligned.m16n8k8.row.col.f32.tf32.tf32.f32 "
        "{%0,%1,%2,%3}, {%4,%5,%6,%7}, {%8,%9}, {%0,%1,%2,%3};"
        : "+f"(c[0]), "+f"(c[1]), "+f"(c[2]), "+f"(c[3])
        : "r"(a0), "r"(a1), "r"(a2), "r"(a3), "r"(b0), "r"(b1));
}

// ---------------------------------------------------------------------------
// Kernel 1: fused QKV projection + RoPE (tf32).
// Block tile 128x64, BK=32, 8 warps (4m x 2n), warp tile 32x32.
// Dynamic smem: As[128][36] + Bs[32][68], epilogue Cs[128][68] overlaps.
// ---------------------------------------------------------------------------
__global__ __launch_bounds__(256, 2) void qkv_rope_kernel(
    const float* __restrict__ X,
    const float* __restrict__ Wq,
    const float* __restrict__ Wk,
    const float* __restrict__ Wv,
    const float* __restrict__ cs,
    const float* __restrict__ sn)
{
    const int n0g = blockIdx.x * 64;
    const int m0  = blockIdx.y * 128;

    const float* Bmat;
    int ldb, ncol0, kind;                  // 0=Q, 1=K, 2=V
    if (n0g < 1024)       { Bmat = Wq; ldb = 1024; ncol0 = n0g;        kind = 0; }
    else if (n0g < 1280)  { Bmat = Wk; ldb = 256;  ncol0 = n0g - 1024; kind = 1; }
    else                  { Bmat = Wv; ldb = 256;  ncol0 = n0g - 1280; kind = 2; }

    extern __shared__ float dyn[];
    float* As = dyn;                   // [128][36]
    float* Bs = dyn + 128 * 36;        // [32][68]
    float* Cs = dyn;                   // [128][68] (overlaps; used after mainloop)

    const int tid  = threadIdx.x;
    const int lane = tid & 31, warp = tid >> 5;
    const int wm = warp & 3, wn = warp >> 2;
    const int g = lane >> 2, t = lane & 3;

    float cfr[2][4][4] = {};

    for (int k0 = 0; k0 < 1024; k0 += 32) {
        #pragma unroll
        for (int it = 0; it < 4; it++) {
            int id = tid + it * 256;
            int r = id >> 3, c4 = (id & 7) * 4;
            float4 v = *(const float4*)&X[(m0 + r) * 1024 + k0 + c4];
            float* a = &As[r * 36 + c4];
            a[0] = f2tff(v.x); a[1] = f2tff(v.y); a[2] = f2tff(v.z); a[3] = f2tff(v.w);
        }
        #pragma unroll
        for (int it = 0; it < 2; it++) {
            int id = tid + it * 256;
            int r = id >> 4, c4 = (id & 15) * 4;
            float4 v = *(const float4*)&Bmat[(k0 + r) * ldb + ncol0 + c4];
            float* b = &Bs[r * 68 + c4];
            b[0] = f2tff(v.x); b[1] = f2tff(v.y); b[2] = f2tff(v.z); b[3] = f2tff(v.w);
        }
        __syncthreads();
        #pragma unroll
        for (int ks = 0; ks < 4; ks++) {
            const int kk = ks * 8;
            uint32_t af[2][4];
            #pragma unroll
            for (int f = 0; f < 2; f++) {
                int rb = wm * 32 + f * 16 + g;
                af[f][0] = __float_as_uint(As[(rb    ) * 36 + kk + t    ]);
                af[f][1] = __float_as_uint(As[(rb + 8) * 36 + kk + t    ]);
                af[f][2] = __float_as_uint(As[(rb    ) * 36 + kk + t + 4]);
                af[f][3] = __float_as_uint(As[(rb + 8) * 36 + kk + t + 4]);
            }
            #pragma unroll
            for (int j = 0; j < 4; j++) {
                int nb = wn * 32 + j * 8 + g;
                uint32_t b0 = __float_as_uint(Bs[(kk + t    ) * 68 + nb]);
                uint32_t b1 = __float_as_uint(Bs[(kk + t + 4) * 68 + nb]);
                mma8(cfr[0][j], af[0][0], af[0][1], af[0][2], af[0][3], b0, b1);
                mma8(cfr[1][j], af[1][0], af[1][1], af[1][2], af[1][3], b0, b1);
            }
        }
        __syncthreads();
    }

    // Fragments -> Cs (overlapping As/Bs; mainloop done) for RoPE exchange
    #pragma unroll
    for (int f = 0; f < 2; f++) {
        int rb = wm * 32 + f * 16 + g;
        #pragma unroll
        for (int j = 0; j < 4; j++) {
            int col = wn * 32 + j * 8 + 2 * t;
            Cs[(rb    ) * 68 + col    ] = cfr[f][j][0];
            Cs[(rb    ) * 68 + col + 1] = cfr[f][j][1];
            Cs[(rb + 8) * 68 + col    ] = cfr[f][j][2];
            Cs[(rb + 8) * 68 + col + 1] = cfr[f][j][3];
        }
    }
    __syncthreads();

    const int head_local = (kind == 0) ? (n0g >> 6) : (ncol0 >> 6);
    const int r0e = (tid >> 4) * 8;
    const int c0e = (tid & 15) * 4;
    #pragma unroll
    for (int i = 0; i < 8; i++) {
        const int r = r0e + i;
        const int m = m0 + r;
        #pragma unroll
        for (int j = 0; j < 4; j++) {
            const int d = c0e + j;
            float val = Cs[r * 68 + d];
            float outv;
            if (kind == 2) {
                outv = val;
            } else {
                float partner = (d < 32) ? -Cs[r * 68 + d + 32] : Cs[r * 68 + d - 32];
                outv = val * cs[m * HD + d] + partner * sn[m * HD + d];
                if (kind == 0) outv *= SCALING;
            }
            outv = f2tff(outv);
            const int dst = head_local * SEQ * HD + m * HD + d;
            if (kind == 0)      g_Q[dst] = outv;
            else if (kind == 1) g_K[dst] = outv;
            else                g_V[dst] = outv;
        }
    }
}

// ---------------------------------------------------------------------------
// Kernel 2: flash attention (tf32). Block = (128 queries, head).
// 8 warps (4m x 2n), warp tile 32x32 over the 128x64 S/O tiles.
// Softmax: 2 threads/row, float4 smem access.
// ---------------------------------------------------------------------------
__global__ __launch_bounds__(256, 2) void flash_kernel()
{
    const int q0  = blockIdx.x * 128;
    const int h   = blockIdx.y;
    const int kvh = h >> 2;

    extern __shared__ float smf[];
    float* Qs = smf;                     // [128][68]
    float* Ks = smf + 128 * 68;          // [64][68]
    float* Vs = smf + (128 + 64) * 68;   // [64][68]
    float* SP = smf + (128 + 128) * 68;  // [128][68]
    __shared__ float row_m[128], row_l[128], row_scale[128];

    const int tid  = threadIdx.x;
    const int lane = tid & 31, warp = tid >> 5;
    const int wm = warp & 3, wn = warp >> 2;
    const int g = lane >> 2, t = lane & 3;

    const float* Qg = g_Q + h * SEQ * HD + q0 * HD;
    const float* Kg = g_K + kvh * SEQ * HD;
    const float* Vg = g_V + kvh * SEQ * HD;

    #pragma unroll
    for (int it = 0; it < 8; it++) {
        int id = tid + it * 256;
        int r = id >> 4, c4 = (id & 15) * 4;
        *(float4*)&Qs[r * 68 + c4] = *(const float4*)&Qg[r * 64 + c4];
    }
    if (tid < 128) { row_m[tid] = -INFINITY; row_l[tid] = 0.0f; }

    float ofr[2][4][4] = {};

    for (int kt = 0; kt < 32; kt++) {
        __syncthreads();    // protect Ks/Vs/SP reuse
        const float* Kp = Kg + kt * 64 * 64;
        const float* Vp = Vg + kt * 64 * 64;
        #pragma unroll
        for (int it = 0; it < 4; it++) {
            int id = tid + it * 256;
            int r = id >> 4, c4 = (id & 15) * 4;
            *(float4*)&Ks[r * 68 + c4] = *(const float4*)&Kp[r * 64 + c4];
            *(float4*)&Vs[r * 68 + c4] = *(const float4*)&Vp[r * 64 + c4];
        }
        __syncthreads();

        // S = Q @ K^T, 8 k-steps over d=64
        float sfr[2][4][4] = {};
        #pragma unroll
        for (int ks = 0; ks < 8; ks++) {
            const int kk = ks * 8;
            uint32_t af[2][4];
            #pragma unroll
            for (int f = 0; f < 2; f++) {
                int rb = wm * 32 + f * 16 + g;
                af[f][0] = __float_as_uint(Qs[(rb    ) * 68 + kk + t    ]);
                af[f][1] = __float_as_uint(Qs[(rb + 8) * 68 + kk + t    ]);
                af[f][2] = __float_as_uint(Qs[(rb    ) * 68 + kk + t + 4]);
                af[f][3] = __float_as_uint(Qs[(rb + 8) * 68 + kk + t + 4]);
            }
            #pragma unroll
            for (int j = 0; j < 4; j++) {
                int nb = wn * 32 + j * 8 + g;
                uint32_t b0 = __float_as_uint(Ks[nb * 68 + kk + t    ]);
                uint32_t b1 = __float_as_uint(Ks[nb * 68 + kk + t + 4]);
                mma8(sfr[0][j], af[0][0], af[0][1], af[0][2], af[0][3], b0, b1);
                mma8(sfr[1][j], af[1][0], af[1][1], af[1][2], af[1][3], b0, b1);
            }
        }

        #pragma unroll
        for (int f = 0; f < 2; f++) {
            int rb = wm * 32 + f * 16 + g;
            #pragma unroll
            for (int j = 0; j < 4; j++) {
                int col = wn * 32 + j * 8 + 2 * t;
                SP[(rb    ) * 68 + col    ] = sfr[f][j][0];
                SP[(rb    ) * 68 + col + 1] = sfr[f][j][1];
                SP[(rb + 8) * 68 + col    ] = sfr[f][j][2];
                SP[(rb + 8) * 68 + col + 1] = sfr[f][j][3];
            }
        }
        __syncthreads();

        // Online softmax: 2 threads/row, 32 cols each, float4 access.
        {
            const int row = tid >> 1, part = tid & 1;
            float* Sr = SP + row * 68 + part * 32;
            float4 v[8];
            #pragma unroll
            for (int i = 0; i < 8; i++) v[i] = *(const float4*)&Sr[i * 4];
            float mloc = -INFINITY;
            #pragma unroll
            for (int i = 0; i < 8; i++) {
                mloc = fmaxf(mloc, fmaxf(fmaxf(v[i].x, v[i].y), fmaxf(v[i].z, v[i].w)));
            }
            mloc = fmaxf(mloc, __shfl_xor_sync(0xffffffffu, mloc, 1));
            float mold = row_m[row];
            float mnew = fmaxf(mold, mloc);
            float ssum = 0.0f;
            #pragma unroll
            for (int i = 0; i < 8; i++) {
                v[i].x = __expf(v[i].x - mnew); v[i].y = __expf(v[i].y - mnew);
                v[i].z = __expf(v[i].z - mnew); v[i].w = __expf(v[i].w - mnew);
                ssum += v[i].x + v[i].y + v[i].z + v[i].w;
                v[i].x = f2tff(v[i].x); v[i].y = f2tff(v[i].y);
                v[i].z = f2tff(v[i].z); v[i].w = f2tff(v[i].w);
                *(float4*)&Sr[i * 4] = v[i];
            }
            ssum += __shfl_xor_sync(0xffffffffu, ssum, 1);
            if (part == 0) {
                float sc = __expf(mold - mnew);   // first iter: exp(-inf)=0
                row_scale[row] = sc;
                row_l[row] = row_l[row] * sc + ssum;
                row_m[row] = mnew;
            }
        }
        __syncthreads();

        // O = O*scale + P @ V
        #pragma unroll
        for (int f = 0; f < 2; f++) {
            int rb = wm * 32 + f * 16 + g;
            float s1 = row_scale[rb];
            float s2 = row_scale[rb + 8];
            #pragma unroll
            for (int j = 0; j < 4; j++) {
                ofr[f][j][0] *= s1; ofr[f][j][1] *= s1;
                ofr[f][j][2] *= s2; ofr[f][j][3] *= s2;
            }
        }
        #pragma unroll
        for (int ks = 0; ks < 8; ks++) {
            const int kk = ks * 8;
            uint32_t af[2][4];
            #pragma unroll
            for (int f = 0; f < 2; f++) {
                int rb = wm * 32 + f * 16 + g;
                af[f][0] = __float_as_uint(SP[(rb    ) * 68 + kk + t    ]);
                af[f][1] = __float_as_uint(SP[(rb + 8) * 68 + kk + t    ]);
                af[f][2] = __float_as_uint(SP[(rb    ) * 68 + kk + t + 4]);
                af[f][3] = __float_as_uint(SP[(rb + 8) * 68 + kk + t + 4]);
            }
            #pragma unroll
            for (int j = 0; j < 4; j++) {
                int nb = wn * 32 + j * 8 + g;
                uint32_t b0 = __float_as_uint(Vs[(kk + t    ) * 68 + nb]);
                uint32_t b1 = __float_as_uint(Vs[(kk + t + 4) * 68 + nb]);
                mma8(ofr[0][j], af[0][0], af[0][1], af[0][2], af[0][3], b0, b1);
                mma8(ofr[1][j], af[1][0], af[1][1], af[1][2], af[1][3], b0, b1);
            }
        }
    }

    // Normalize, stage via SP (done with P), coalesced store.
    __syncthreads();
    #pragma unroll
    for (int f = 0; f < 2; f++) {
        int rb = wm * 32 + f * 16 + g;
        float l1 = 1.0f / row_l[rb];
        float l2 = 1.0f / row_l[rb + 8];
        #pragma unroll
        for (int j = 0; j < 4; j++) {
            int col = wn * 32 + j * 8 + 2 * t;
            SP[(rb    ) * 68 + col    ] = ofr[f][j][0] * l1;
            SP[(rb    ) * 68 + col + 1] = ofr[f][j][1] * l1;
            SP[(rb + 8) * 68 + col    ] = ofr[f][j][2] * l2;
            SP[(rb + 8) * 68 + col + 1] = ofr[f][j][3] * l2;
        }
    }
    __syncthreads();
    #pragma unroll
    for (int it = 0; it < 8; it++) {
        int id = tid + it * 256;
        int r = id >> 4, c4 = (id & 15) * 4;
        *(float4*)&g_AO[(q0 + r) * 1024 + h * 64 + c4] = *(const float4*)&SP[r * 68 + c4];
    }
}

// ---------------------------------------------------------------------------
// Kernel 3: output projection (tf32). Block tile 128x64, warp tile 32x32.
// ---------------------------------------------------------------------------
__global__ __launch_bounds__(256, 2) void oproj_kernel(
    const float* __restrict__ Wo, float* __restrict__ out)
{
    const int n0 = blockIdx.x * 64;
    const int m0 = blockIdx.y * 128;

    extern __shared__ float dyn[];
    float* As = dyn;                   // [128][36]
    float* Bs = dyn + 128 * 36;        // [32][68]
    float* Cs = dyn;                   // [128][68] overlap

    const int tid  = threadIdx.x;
    const int lane = tid & 31, warp = tid >> 5;
    const int wm = warp & 3, wn = warp >> 2;
    const int g = lane >> 2, t = lane & 3;

    float cfr[2][4][4] = {};

    for (int k0 = 0; k0 < 1024; k0 += 32) {
        #pragma unroll
        for (int it = 0; it < 4; it++) {
            int id = tid + it * 256;
            int r = id >> 3, c4 = (id & 7) * 4;
            float4 v = *(const float4*)&g_AO[(m0 + r) * 1024 + k0 + c4];
            float* a = &As[r * 36 + c4];
            a[0] = f2tff(v.x); a[1] = f2tff(v.y); a[2] = f2tff(v.z); a[3] = f2tff(v.w);
        }
        #pragma unroll
        for (int it = 0; it < 2; it++) {
            int id = tid + it * 256;
            int r = id >> 4, c4 = (id & 15) * 4;
            float4 v = *(const float4*)&Wo[(k0 + r) * 1024 + n0 + c4];
            float* b = &Bs[r * 68 + c4];
            b[0] = f2tff(v.x); b[1] = f2tff(v.y); b[2] = f2tff(v.z); b[3] = f2tff(v.w);
        }
        __syncthreads();
        #pragma unroll
        for (int ks = 0; ks < 4; ks++) {
            const int kk = ks * 8;
            uint32_t af[2][4];
            #pragma unroll
            for (int f = 0; f < 2; f++) {
                int rb = wm * 32 + f * 16 + g;
                af[f][0] = __float_as_uint(As[(rb    ) * 36 + kk + t    ]);
                af[f][1] = __float_as_uint(As[(rb + 8) * 36 + kk + t    ]);
                af[f][2] = __float_as_uint(As[(rb    ) * 36 + kk + t + 4]);
                af[f][3] = __float_as_uint(As[(rb + 8) * 36 + kk + t + 4]);
            }
            #pragma unroll
            for (int j = 0; j < 4; j++) {
                int nb = wn * 32 + j * 8 + g;
                uint32_t b0 = __float_as_uint(Bs[(kk + t    ) * 68 + nb]);
                uint32_t b1 = __float_as_uint(Bs[(kk + t + 4) * 68 + nb]);
                mma8(cfr[0][j], af[0][0], af[0][1], af[0][2], af[0][3], b0, b1);
                mma8(cfr[1][j], af[1][0], af[1][1], af[1][2], af[1][3], b0, b1);
            }
        }
        __syncthreads();
    }

    #pragma unroll
    for (int f = 0; f < 2; f++) {
        int rb = wm * 32 + f * 16 + g;
        #pragma unroll
        for (int j = 0; j < 4; j++) {
            int col = wn * 32 + j * 8 + 2 * t;
            Cs[(rb    ) * 68 + col    ] = cfr[f][j][0];
            Cs[(rb    ) * 68 + col + 1] = cfr[f][j][1];
            Cs[(rb + 8) * 68 + col    ] = cfr[f][j][2];
            Cs[(rb + 8) * 68 + col + 1] = cfr[f][j][3];
        }
    }
    __syncthreads();
    #pragma unroll
    for (int it = 0; it < 8; it++) {
        int id = tid + it * 256;
        int r = id >> 4, c4 = (id & 15) * 4;
        *(float4*)&out[(m0 + r) * 1024 + n0 + c4] = *(const float4*)&Cs[r * 68 + c4];
    }
}

// ---------------------------------------------------------------------------
// Launch.
// ---------------------------------------------------------------------------
extern "C" void kernel_launch(void* const* d_in, const int* in_sizes, int n_in,
                              void* d_out, int out_size)
{
    const float* X  = (const float*)d_in[0];
    const float* cs = (const float*)d_in[1];
    const float* sn = (const float*)d_in[2];
    // d_in[3] = attention_mask (all ones) — unused
    const float* Wq = (const float*)d_in[4];
    const float* Wk = (const float*)d_in[5];
    const float* Wv = (const float*)d_in[6];
    const float* Wo = (const float*)d_in[7];
    float* out = (float*)d_out;

    const size_t smem_gemm = 128 * 68 * sizeof(float);   // 34816 B (Cs overlaps As+Bs)

    qkv_rope_kernel<<<dim3(24, 16), 256, smem_gemm>>>(X, Wq, Wk, Wv, cs, sn);

    const size_t smem_flash = (128 + 64 + 64 + 128) * 68 * sizeof(float);  // 104448 B
    cudaFuncSetAttribute(flash_kernel,
                         cudaFuncAttributeMaxDynamicSharedMemorySize, (int)smem_flash);
    flash_kernel<<<dim3(16, 16), 256, smem_flash>>>();

    oproj_kernel<<<dim3(16, 16), 256, smem_gemm>>>(Wo, out);
}

// round 6
// speedup vs baseline: 3.5297x; 1.0537x over previous
#include <cuda_runtime.h>
#include <math.h>
#include <stdint.h>

#define SEQ 2048
#define HID 1024
#define NH 16
#define NKV 4
#define HD 64
#define SCALING 0.125f

// Scratch (device globals; 16B-aligned: targets of float4 access)
__device__ __align__(16) float g_Q[NH * SEQ * HD];    // [h][m][d], RoPE'd, pre-scaled, tf32
__device__ __align__(16) float g_K[NKV * SEQ * HD];   // [kvh][m][d], RoPE'd, tf32
__device__ __align__(16) float g_V[NKV * SEQ * HD];   // [kvh][m][d], tf32
__device__ __align__(16) float g_AO[SEQ * HID];       // [m][h*64+d] fp32

// ---------------------------------------------------------------------------
// Helpers
// ---------------------------------------------------------------------------
__device__ __forceinline__ float f2tff(float x) {
    uint32_t r;
    asm("cvt.rna.tf32.f32 %0, %1;" : "=r"(r) : "f"(x));
    return __uint_as_float(r);
}

__device__ __forceinline__ void mma8(float c[4],
                                     uint32_t a0, uint32_t a1, uint32_t a2, uint32_t a3,
                                     uint32_t b0, uint32_t b1) {
    asm volatile(
        "mma.sync.aligned.m16n8k8.row.col.f32.tf32.tf32.f32 "
        "{%0,%1,%2,%3}, {%4,%5,%6,%7}, {%8,%9}, {%0,%1,%2,%3};"
        : "+f"(c[0]), "+f"(c[1]), "+f"(c[2]), "+f"(c[3])
        : "r"(a0), "r"(a1), "r"(a2), "r"(a3), "r"(b0), "r"(b1));
}

__device__ __forceinline__ void cp16(float* smem_dst, const float* gsrc) {
    uint32_t s = (uint32_t)__cvta_generic_to_shared(smem_dst);
    asm volatile("cp.async.ca.shared.global [%0], [%1], 16;" :: "r"(s), "l"(gsrc));
}

// ---------------------------------------------------------------------------
// Kernel 1: fused QKV projection + RoPE (tf32), register-staged pipeline.
// Block tile 128x64, BK=32, 8 warps (4m x 2n), warp tile 32x32.
// ---------------------------------------------------------------------------
__global__ __launch_bounds__(256, 2) void qkv_rope_kernel(
    const float* __restrict__ X,
    const float* __restrict__ Wq,
    const float* __restrict__ Wk,
    const float* __restrict__ Wv,
    const float* __restrict__ cs,
    const float* __restrict__ sn)
{
    const int n0g = blockIdx.x * 64;
    const int m0  = blockIdx.y * 128;

    const float* Bmat;
    int ldb, ncol0, kind;                  // 0=Q, 1=K, 2=V
    if (n0g < 1024)       { Bmat = Wq; ldb = 1024; ncol0 = n0g;        kind = 0; }
    else if (n0g < 1280)  { Bmat = Wk; ldb = 256;  ncol0 = n0g - 1024; kind = 1; }
    else                  { Bmat = Wv; ldb = 256;  ncol0 = n0g - 1280; kind = 2; }

    extern __shared__ float dyn[];
    float* As = dyn;                   // [128][36]
    float* Bs = dyn + 128 * 36;        // [32][68]
    float* Cs = dyn;                   // [128][68] (overlaps; used after mainloop)

    const int tid  = threadIdx.x;
    const int lane = tid & 31, warp = tid >> 5;
    const int wm = warp & 3, wn = warp >> 2;
    const int g = lane >> 2, t = lane & 3;

    // Per-thread staging coordinates
    const int arA[4] = { (tid + 0) >> 3, (tid + 256) >> 3, (tid + 512) >> 3, (tid + 768) >> 3 };
    const int acA    = (tid & 7) * 4;
    const int brB[2] = { tid >> 4, (tid + 256) >> 4 };
    const int bcB    = (tid & 15) * 4;

    float cfr[2][4][4] = {};
    float4 ra[4], rb[2];

    // Prologue: load tile k0=0
    #pragma unroll
    for (int it = 0; it < 4; it++) ra[it] = *(const float4*)&X[(m0 + arA[it]) * 1024 + acA];
    #pragma unroll
    for (int it = 0; it < 2; it++) rb[it] = *(const float4*)&Bmat[brB[it] * ldb + ncol0 + bcB];
    #pragma unroll
    for (int it = 0; it < 4; it++) {
        float* a = &As[arA[it] * 36 + acA];
        a[0] = f2tff(ra[it].x); a[1] = f2tff(ra[it].y); a[2] = f2tff(ra[it].z); a[3] = f2tff(ra[it].w);
    }
    #pragma unroll
    for (int it = 0; it < 2; it++) {
        float* b = &Bs[brB[it] * 68 + bcB];
        b[0] = f2tff(rb[it].x); b[1] = f2tff(rb[it].y); b[2] = f2tff(rb[it].z); b[3] = f2tff(rb[it].w);
    }
    __syncthreads();

    for (int k0 = 0; k0 < 1024; k0 += 32) {
        const bool has_next = (k0 + 32) < 1024;
        if (has_next) {
            const int kn = k0 + 32;
            #pragma unroll
            for (int it = 0; it < 4; it++) ra[it] = *(const float4*)&X[(m0 + arA[it]) * 1024 + kn + acA];
            #pragma unroll
            for (int it = 0; it < 2; it++) rb[it] = *(const float4*)&Bmat[(kn + brB[it]) * ldb + ncol0 + bcB];
        }
        #pragma unroll
        for (int ks = 0; ks < 4; ks++) {
            const int kk = ks * 8;
            uint32_t af[2][4];
            #pragma unroll
            for (int f = 0; f < 2; f++) {
                int rbm = wm * 32 + f * 16 + g;
                af[f][0] = __float_as_uint(As[(rbm    ) * 36 + kk + t    ]);
                af[f][1] = __float_as_uint(As[(rbm + 8) * 36 + kk + t    ]);
                af[f][2] = __float_as_uint(As[(rbm    ) * 36 + kk + t + 4]);
                af[f][3] = __float_as_uint(As[(rbm + 8) * 36 + kk + t + 4]);
            }
            #pragma unroll
            for (int j = 0; j < 4; j++) {
                int nb = wn * 32 + j * 8 + g;
                uint32_t b0 = __float_as_uint(Bs[(kk + t    ) * 68 + nb]);
                uint32_t b1 = __float_as_uint(Bs[(kk + t + 4) * 68 + nb]);
                mma8(cfr[0][j], af[0][0], af[0][1], af[0][2], af[0][3], b0, b1);
                mma8(cfr[1][j], af[1][0], af[1][1], af[1][2], af[1][3], b0, b1);
            }
        }
        __syncthreads();
        if (has_next) {
            #pragma unroll
            for (int it = 0; it < 4; it++) {
                float* a = &As[arA[it] * 36 + acA];
                a[0] = f2tff(ra[it].x); a[1] = f2tff(ra[it].y); a[2] = f2tff(ra[it].z); a[3] = f2tff(ra[it].w);
            }
            #pragma unroll
            for (int it = 0; it < 2; it++) {
                float* b = &Bs[brB[it] * 68 + bcB];
                b[0] = f2tff(rb[it].x); b[1] = f2tff(rb[it].y); b[2] = f2tff(rb[it].z); b[3] = f2tff(rb[it].w);
            }
            __syncthreads();
        }
    }

    // Fragments -> Cs (overlaps As/Bs) for RoPE exchange
    #pragma unroll
    for (int f = 0; f < 2; f++) {
        int rbm = wm * 32 + f * 16 + g;
        #pragma unroll
        for (int j = 0; j < 4; j++) {
            int col = wn * 32 + j * 8 + 2 * t;
            Cs[(rbm    ) * 68 + col    ] = cfr[f][j][0];
            Cs[(rbm    ) * 68 + col + 1] = cfr[f][j][1];
            Cs[(rbm + 8) * 68 + col    ] = cfr[f][j][2];
            Cs[(rbm + 8) * 68 + col + 1] = cfr[f][j][3];
        }
    }
    __syncthreads();

    const int head_local = (kind == 0) ? (n0g >> 6) : (ncol0 >> 6);
    const int r0e = (tid >> 4) * 8;
    const int c0e = (tid & 15) * 4;
    #pragma unroll
    for (int i = 0; i < 8; i++) {
        const int r = r0e + i;
        const int m = m0 + r;
        #pragma unroll
        for (int j = 0; j < 4; j++) {
            const int d = c0e + j;
            float val = Cs[r * 68 + d];
            float outv;
            if (kind == 2) {
                outv = val;
            } else {
                float partner = (d < 32) ? -Cs[r * 68 + d + 32] : Cs[r * 68 + d - 32];
                outv = val * cs[m * HD + d] + partner * sn[m * HD + d];
                if (kind == 0) outv *= SCALING;
            }
            outv = f2tff(outv);
            const int dst = head_local * SEQ * HD + m * HD + d;
            if (kind == 0)      g_Q[dst] = outv;
            else if (kind == 1) g_K[dst] = outv;
            else                g_V[dst] = outv;
        }
    }
}

// ---------------------------------------------------------------------------
// Kernel 2: flash attention (tf32), pipelined.
// Block = (128 queries, head). K prefetched via regs; V via cp.async.
// Vs stride 72 (conflict-free PV B-reads).
// ---------------------------------------------------------------------------
__global__ __launch_bounds__(256, 2) void flash_kernel()
{
    const int q0  = blockIdx.x * 128;
    const int h   = blockIdx.y;
    const int kvh = h >> 2;

    extern __shared__ float smf[];
    float* Qs = smf;                          // [128][68]
    float* Ks = smf + 128 * 68;               // [64][68]
    float* Vs = smf + 128 * 68 + 64 * 68;     // [64][72]
    float* SP = smf + 128 * 68 + 64 * 68 + 64 * 72;  // [128][68]
    __shared__ float row_m[128], row_l[128], row_scale[128];

    const int tid  = threadIdx.x;
    const int lane = tid & 31, warp = tid >> 5;
    const int wm = warp & 3, wn = warp >> 2;
    const int g = lane >> 2, t = lane & 3;

    const float* Qg = g_Q + h * SEQ * HD + q0 * HD;
    const float* Kg = g_K + kvh * SEQ * HD;
    const float* Vg = g_V + kvh * SEQ * HD;

    // KV staging coordinates: 4 chunks x 256 threads x float4 covers 64x64
    const int kvR[4] = { (tid + 0) >> 4, (tid + 256) >> 4, (tid + 512) >> 4, (tid + 768) >> 4 };
    const int kvC    = (tid & 15) * 4;

    #pragma unroll
    for (int it = 0; it < 8; it++) {
        int id = tid + it * 256;
        int r = id >> 4, c4 = (id & 15) * 4;
        *(float4*)&Qs[r * 68 + c4] = *(const float4*)&Qg[r * 64 + c4];
    }
    if (tid < 128) { row_m[tid] = -INFINITY; row_l[tid] = 0.0f; }

    // Prefetch K tile 0 into registers
    float4 rk[4];
    #pragma unroll
    for (int it = 0; it < 4; it++) rk[it] = *(const float4*)&Kg[kvR[it] * 64 + kvC];

    float ofr[2][4][4] = {};

    for (int kt = 0; kt < 32; kt++) {
        __syncthreads();    // prev iter's Ks/Vs/SP reads complete

        // Stage K(kt) from regs; start V(kt) cp.async; prefetch K(kt+1)
        #pragma unroll
        for (int it = 0; it < 4; it++) *(float4*)&Ks[kvR[it] * 68 + kvC] = rk[it];
        const float* Vp = Vg + kt * 64 * 64;
        #pragma unroll
        for (int it = 0; it < 4; it++) cp16(&Vs[kvR[it] * 72 + kvC], &Vp[kvR[it] * 64 + kvC]);
        asm volatile("cp.async.commit_group;");
        if (kt + 1 < 32) {
            const float* Kp = Kg + (kt + 1) * 64 * 64;
            #pragma unroll
            for (int it = 0; it < 4; it++) rk[it] = *(const float4*)&Kp[kvR[it] * 64 + kvC];
        }
        __syncthreads();    // Ks(kt) visible

        // S = Q @ K^T, 8 k-steps over d=64
        float sfr[2][4][4] = {};
        #pragma unroll
        for (int ks = 0; ks < 8; ks++) {
            const int kk = ks * 8;
            uint32_t af[2][4];
            #pragma unroll
            for (int f = 0; f < 2; f++) {
                int rbm = wm * 32 + f * 16 + g;
                af[f][0] = __float_as_uint(Qs[(rbm    ) * 68 + kk + t    ]);
                af[f][1] = __float_as_uint(Qs[(rbm + 8) * 68 + kk + t    ]);
                af[f][2] = __float_as_uint(Qs[(rbm    ) * 68 + kk + t + 4]);
                af[f][3] = __float_as_uint(Qs[(rbm + 8) * 68 + kk + t + 4]);
            }
            #pragma unroll
            for (int j = 0; j < 4; j++) {
                int nb = wn * 32 + j * 8 + g;
                uint32_t b0 = __float_as_uint(Ks[nb * 68 + kk + t    ]);
                uint32_t b1 = __float_as_uint(Ks[nb * 68 + kk + t + 4]);
                mma8(sfr[0][j], af[0][0], af[0][1], af[0][2], af[0][3], b0, b1);
                mma8(sfr[1][j], af[1][0], af[1][1], af[1][2], af[1][3], b0, b1);
            }
        }

        #pragma unroll
        for (int f = 0; f < 2; f++) {
            int rbm = wm * 32 + f * 16 + g;
            #pragma unroll
            for (int j = 0; j < 4; j++) {
                int col = wn * 32 + j * 8 + 2 * t;
                SP[(rbm    ) * 68 + col    ] = sfr[f][j][0];
                SP[(rbm    ) * 68 + col + 1] = sfr[f][j][1];
                SP[(rbm + 8) * 68 + col    ] = sfr[f][j][2];
                SP[(rbm + 8) * 68 + col + 1] = sfr[f][j][3];
            }
        }
        asm volatile("cp.async.wait_group 0;" ::: "memory");   // V(kt) landed
        __syncthreads();    // SP(S) + Vs visible

        // Online softmax: 2 threads/row, 32 cols each, float4 access.
        {
            const int row = tid >> 1, part = tid & 1;
            float* Sr = SP + row * 68 + part * 32;
            float4 v[8];
            #pragma unroll
            for (int i = 0; i < 8; i++) v[i] = *(const float4*)&Sr[i * 4];
            float mloc = -INFINITY;
            #pragma unroll
            for (int i = 0; i < 8; i++)
                mloc = fmaxf(mloc, fmaxf(fmaxf(v[i].x, v[i].y), fmaxf(v[i].z, v[i].w)));
            mloc = fmaxf(mloc, __shfl_xor_sync(0xffffffffu, mloc, 1));
            float mold = row_m[row];
            float mnew = fmaxf(mold, mloc);
            float ssum = 0.0f;
            #pragma unroll
            for (int i = 0; i < 8; i++) {
                v[i].x = __expf(v[i].x - mnew); v[i].y = __expf(v[i].y - mnew);
                v[i].z = __expf(v[i].z - mnew); v[i].w = __expf(v[i].w - mnew);
                ssum += v[i].x + v[i].y + v[i].z + v[i].w;
                v[i].x = f2tff(v[i].x); v[i].y = f2tff(v[i].y);
                v[i].z = f2tff(v[i].z); v[i].w = f2tff(v[i].w);
                *(float4*)&Sr[i * 4] = v[i];
            }
            ssum += __shfl_xor_sync(0xffffffffu, ssum, 1);
            if (part == 0) {
                float sc = __expf(mold - mnew);   // first iter: exp(-inf)=0
                row_scale[row] = sc;
                row_l[row] = row_l[row] * sc + ssum;
                row_m[row] = mnew;
            }
        }
        __syncthreads();

        // O = O*scale + P @ V
        #pragma unroll
        for (int f = 0; f < 2; f++) {
            int rbm = wm * 32 + f * 16 + g;
            float s1 = row_scale[rbm];
            float s2 = row_scale[rbm + 8];
            #pragma unroll
            for (int j = 0; j < 4; j++) {
                ofr[f][j][0] *= s1; ofr[f][j][1] *= s1;
                ofr[f][j][2] *= s2; ofr[f][j][3] *= s2;
            }
        }
        #pragma unroll
        for (int ks = 0; ks < 8; ks++) {
            const int kk = ks * 8;
            uint32_t af[2][4];
            #pragma unroll
            for (int f = 0; f < 2; f++) {
                int rbm = wm * 32 + f * 16 + g;
                af[f][0] = __float_as_uint(SP[(rbm    ) * 68 + kk + t    ]);
                af[f][1] = __float_as_uint(SP[(rbm + 8) * 68 + kk + t    ]);
                af[f][2] = __float_as_uint(SP[(rbm    ) * 68 + kk + t + 4]);
                af[f][3] = __float_as_uint(SP[(rbm + 8) * 68 + kk + t + 4]);
            }
            #pragma unroll
            for (int j = 0; j < 4; j++) {
                int nb = wn * 32 + j * 8 + g;
                uint32_t b0 = __float_as_uint(Vs[(kk + t    ) * 72 + nb]);
                uint32_t b1 = __float_as_uint(Vs[(kk + t + 4) * 72 + nb]);
                mma8(ofr[0][j], af[0][0], af[0][1], af[0][2], af[0][3], b0, b1);
                mma8(ofr[1][j], af[1][0], af[1][1], af[1][2], af[1][3], b0, b1);
            }
        }
    }

    // Normalize, stage via SP, coalesced store.
    __syncthreads();
    #pragma unroll
    for (int f = 0; f < 2; f++) {
        int rbm = wm * 32 + f * 16 + g;
        float l1 = 1.0f / row_l[rbm];
        float l2 = 1.0f / row_l[rbm + 8];
        #pragma unroll
        for (int j = 0; j < 4; j++) {
            int col = wn * 32 + j * 8 + 2 * t;
            SP[(rbm    ) * 68 + col    ] = ofr[f][j][0] * l1;
            SP[(rbm    ) * 68 + col + 1] = ofr[f][j][1] * l1;
            SP[(rbm + 8) * 68 + col    ] = ofr[f][j][2] * l2;
            SP[(rbm + 8) * 68 + col + 1] = ofr[f][j][3] * l2;
        }
    }
    __syncthreads();
    #pragma unroll
    for (int it = 0; it < 8; it++) {
        int id = tid + it * 256;
        int r = id >> 4, c4 = (id & 15) * 4;
        *(float4*)&g_AO[(q0 + r) * 1024 + h * 64 + c4] = *(const float4*)&SP[r * 68 + c4];
    }
}

// ---------------------------------------------------------------------------
// Kernel 3: output projection (tf32), register-staged pipeline.
// ---------------------------------------------------------------------------
__global__ __launch_bounds__(256, 2) void oproj_kernel(
    const float* __restrict__ Wo, float* __restrict__ out)
{
    const int n0 = blockIdx.x * 64;
    const int m0 = blockIdx.y * 128;

    extern __shared__ float dyn[];
    float* As = dyn;                   // [128][36]
    float* Bs = dyn + 128 * 36;        // [32][68]
    float* Cs = dyn;                   // [128][68] overlap

    const int tid  = threadIdx.x;
    const int lane = tid & 31, warp = tid >> 5;
    const int wm = warp & 3, wn = warp >> 2;
    const int g = lane >> 2, t = lane & 3;

    const int arA[4] = { (tid + 0) >> 3, (tid + 256) >> 3, (tid + 512) >> 3, (tid + 768) >> 3 };
    const int acA    = (tid & 7) * 4;
    const int brB[2] = { tid >> 4, (tid + 256) >> 4 };
    const int bcB    = (tid & 15) * 4;

    float cfr[2][4][4] = {};
    float4 ra[4], rb[2];

    #pragma unroll
    for (int it = 0; it < 4; it++) ra[it] = *(const float4*)&g_AO[(m0 + arA[it]) * 1024 + acA];
    #pragma unroll
    for (int it = 0; it < 2; it++) rb[it] = *(const float4*)&Wo[brB[it] * 1024 + n0 + bcB];
    #pragma unroll
    for (int it = 0; it < 4; it++) {
        float* a = &As[arA[it] * 36 + acA];
        a[0] = f2tff(ra[it].x); a[1] = f2tff(ra[it].y); a[2] = f2tff(ra[it].z); a[3] = f2tff(ra[it].w);
    }
    #pragma unroll
    for (int it = 0; it < 2; it++) {
        float* b = &Bs[brB[it] * 68 + bcB];
        b[0] = f2tff(rb[it].x); b[1] = f2tff(rb[it].y); b[2] = f2tff(rb[it].z); b[3] = f2tff(rb[it].w);
    }
    __syncthreads();

    for (int k0 = 0; k0 < 1024; k0 += 32) {
        const bool has_next = (k0 + 32) < 1024;
        if (has_next) {
            const int kn = k0 + 32;
            #pragma unroll
            for (int it = 0; it < 4; it++) ra[it] = *(const float4*)&g_AO[(m0 + arA[it]) * 1024 + kn + acA];
            #pragma unroll
            for (int it = 0; it < 2; it++) rb[it] = *(const float4*)&Wo[(kn + brB[it]) * 1024 + n0 + bcB];
        }
        #pragma unroll
        for (int ks = 0; ks < 4; ks++) {
            const int kk = ks * 8;
            uint32_t af[2][4];
            #pragma unroll
            for (int f = 0; f < 2; f++) {
                int rbm = wm * 32 + f * 16 + g;
                af[f][0] = __float_as_uint(As[(rbm    ) * 36 + kk + t    ]);
                af[f][1] = __float_as_uint(As[(rbm + 8) * 36 + kk + t    ]);
                af[f][2] = __float_as_uint(As[(rbm    ) * 36 + kk + t + 4]);
                af[f][3] = __float_as_uint(As[(rbm + 8) * 36 + kk + t + 4]);
            }
            #pragma unroll
            for (int j = 0; j < 4; j++) {
                int nb = wn * 32 + j * 8 + g;
                uint32_t b0 = __float_as_uint(Bs[(kk + t    ) * 68 + nb]);
                uint32_t b1 = __float_as_uint(Bs[(kk + t + 4) * 68 + nb]);
                mma8(cfr[0][j], af[0][0], af[0][1], af[0][2], af[0][3], b0, b1);
                mma8(cfr[1][j], af[1][0], af[1][1], af[1][2], af[1][3], b0, b1);
            }
        }
        __syncthreads();
        if (has_next) {
            #pragma unroll
            for (int it = 0; it < 4; it++) {
                float* a = &As[arA[it] * 36 + acA];
                a[0] = f2tff(ra[it].x); a[1] = f2tff(ra[it].y); a[2] = f2tff(ra[it].z); a[3] = f2tff(ra[it].w);
            }
            #pragma unroll
            for (int it = 0; it < 2; it++) {
                float* b = &Bs[brB[it] * 68 + bcB];
                b[0] = f2tff(rb[it].x); b[1] = f2tff(rb[it].y); b[2] = f2tff(rb[it].z); b[3] = f2tff(rb[it].w);
            }
            __syncthreads();
        }
    }

    #pragma unroll
    for (int f = 0; f < 2; f++) {
        int rbm = wm * 32 + f * 16 + g;
        #pragma unroll
        for (int j = 0; j < 4; j++) {
            int col = wn * 32 + j * 8 + 2 * t;
            Cs[(rbm    ) * 68 + col    ] = cfr[f][j][0];
            Cs[(rbm    ) * 68 + col + 1] = cfr[f][j][1];
            Cs[(rbm + 8) * 68 + col    ] = cfr[f][j][2];
            Cs[(rbm + 8) * 68 + col + 1] = cfr[f][j][3];
        }
    }
    __syncthreads();
    #pragma unroll
    for (int it = 0; it < 8; it++) {
        int id = tid + it * 256;
        int r = id >> 4, c4 = (id & 15) * 4;
        *(float4*)&out[(m0 + r) * 1024 + n0 + c4] = *(const float4*)&Cs[r * 68 + c4];
    }
}

// ---------------------------------------------------------------------------
// Launch.
// ---------------------------------------------------------------------------
extern "C" void kernel_launch(void* const* d_in, const int* in_sizes, int n_in,
                              void* d_out, int out_size)
{
    const float* X  = (const float*)d_in[0];
    const float* cs = (const float*)d_in[1];
    const float* sn = (const float*)d_in[2];
    // d_in[3] = attention_mask (all ones) — unused
    const float* Wq = (const float*)d_in[4];
    const float* Wk = (const float*)d_in[5];
    const float* Wv = (const float*)d_in[6];
    const float* Wo = (const float*)d_in[7];
    float* out = (float*)d_out;

    const size_t smem_gemm = 128 * 68 * sizeof(float);   // 34816 B (Cs overlaps As+Bs)

    qkv_rope_kernel<<<dim3(24, 16), 256, smem_gemm>>>(X, Wq, Wk, Wv, cs, sn);

    // Qs[128][68] + Ks[64][68] + Vs[64][72] + SP[128][68]
    const size_t smem_flash = (128 * 68 + 64 * 68 + 64 * 72 + 128 * 68) * sizeof(float); // 105472 B
    cudaFuncSetAttribute(flash_kernel,
                         cudaFuncAttributeMaxDynamicSharedMemorySize, (int)smem_flash);
    flash_kernel<<<dim3(16, 16), 256, smem_flash>>>();

    oproj_kernel<<<dim3(16, 16), 256, smem_gemm>>>(Wo, out);
}

// round 7
// speedup vs baseline: 3.5494x; 1.0056x over previous
#include <cuda_runtime.h>
#include <math.h>
#include <stdint.h>

#define SEQ 2048
#define HID 1024
#define NH 16
#define NKV 4
#define HD 64
#define SCALING 0.125f

// GEMM double-buffer stage size (floats): As[128][36] + Bs[32][68]
#define GSTAGE (128 * 36 + 32 * 68)   // 6784

// Scratch (device globals; 16B-aligned: targets of float4 access)
__device__ __align__(16) float g_Q[NH * SEQ * HD];    // [h][m][d], RoPE'd, pre-scaled, tf32
__device__ __align__(16) float g_K[NKV * SEQ * HD];   // [kvh][m][d], RoPE'd, tf32
__device__ __align__(16) float g_V[NKV * SEQ * HD];   // [kvh][m][d], tf32
__device__ __align__(16) float g_AO[SEQ * HID];       // [m][h*64+d] fp32

// ---------------------------------------------------------------------------
// Helpers
// ---------------------------------------------------------------------------
__device__ __forceinline__ float f2tff(float x) {
    uint32_t r;
    asm("cvt.rna.tf32.f32 %0, %1;" : "=r"(r) : "f"(x));
    return __uint_as_float(r);
}

__device__ __forceinline__ void mma8(float c[4],
                                     uint32_t a0, uint32_t a1, uint32_t a2, uint32_t a3,
                                     uint32_t b0, uint32_t b1) {
    asm volatile(
        "mma.sync.aligned.m16n8k8.row.col.f32.tf32.tf32.f32 "
        "{%0,%1,%2,%3}, {%4,%5,%6,%7}, {%8,%9}, {%0,%1,%2,%3};"
        : "+f"(c[0]), "+f"(c[1]), "+f"(c[2]), "+f"(c[3])
        : "r"(a0), "r"(a1), "r"(a2), "r"(a3), "r"(b0), "r"(b1));
}

__device__ __forceinline__ void cp16(float* smem_dst, const float* gsrc) {
    uint32_t s = (uint32_t)__cvta_generic_to_shared(smem_dst);
    asm volatile("cp.async.ca.shared.global [%0], [%1], 16;" :: "r"(s), "l"(gsrc));
}

// Stage helpers for the projection GEMMs
__device__ __forceinline__ void stageA(float* As, const int* arA, int acA, const float4* ra) {
    #pragma unroll
    for (int it = 0; it < 4; it++) {
        float* a = &As[arA[it] * 36 + acA];
        a[0] = f2tff(ra[it].x); a[1] = f2tff(ra[it].y);
        a[2] = f2tff(ra[it].z); a[3] = f2tff(ra[it].w);
    }
}
__device__ __forceinline__ void stageB(float* Bs, const int* brB, int bcB, const float4* rb) {
    #pragma unroll
    for (int it = 0; it < 2; it++) {
        float* b = &Bs[brB[it] * 68 + bcB];
        b[0] = f2tff(rb[it].x); b[1] = f2tff(rb[it].y);
        b[2] = f2tff(rb[it].z); b[3] = f2tff(rb[it].w);
    }
}

// One 32-k-step MMA phase over the given stage buffers
__device__ __forceinline__ void mma_phase(const float* As, const float* Bs,
                                          int wm, int wn, int g, int t,
                                          float cfr[2][4][4]) {
    #pragma unroll
    for (int ks = 0; ks < 4; ks++) {
        const int kk = ks * 8;
        uint32_t af[2][4];
        #pragma unroll
        for (int f = 0; f < 2; f++) {
            int rbm = wm * 32 + f * 16 + g;
            af[f][0] = __float_as_uint(As[(rbm    ) * 36 + kk + t    ]);
            af[f][1] = __float_as_uint(As[(rbm + 8) * 36 + kk + t    ]);
            af[f][2] = __float_as_uint(As[(rbm    ) * 36 + kk + t + 4]);
            af[f][3] = __float_as_uint(As[(rbm + 8) * 36 + kk + t + 4]);
        }
        #pragma unroll
        for (int j = 0; j < 4; j++) {
            int nb = wn * 32 + j * 8 + g;
            uint32_t b0 = __float_as_uint(Bs[(kk + t    ) * 68 + nb]);
            uint32_t b1 = __float_as_uint(Bs[(kk + t + 4) * 68 + nb]);
            mma8(cfr[0][j], af[0][0], af[0][1], af[0][2], af[0][3], b0, b1);
            mma8(cfr[1][j], af[1][0], af[1][1], af[1][2], af[1][3], b0, b1);
        }
    }
}

// ---------------------------------------------------------------------------
// Kernel 1: fused QKV projection + RoPE (tf32), double-buffered smem pipeline.
// Block tile 128x64, BK=32, 8 warps (4m x 2n), warp tile 32x32. 1 sync/iter.
// ---------------------------------------------------------------------------
__global__ __launch_bounds__(256, 2) void qkv_rope_kernel(
    const float* __restrict__ X,
    const float* __restrict__ Wq,
    const float* __restrict__ Wk,
    const float* __restrict__ Wv,
    const float* __restrict__ cs,
    const float* __restrict__ sn)
{
    const int n0g = blockIdx.x * 64;
    const int m0  = blockIdx.y * 128;

    const float* Bmat;
    int ldb, ncol0, kind;                  // 0=Q, 1=K, 2=V
    if (n0g < 1024)       { Bmat = Wq; ldb = 1024; ncol0 = n0g;        kind = 0; }
    else if (n0g < 1280)  { Bmat = Wk; ldb = 256;  ncol0 = n0g - 1024; kind = 1; }
    else                  { Bmat = Wv; ldb = 256;  ncol0 = n0g - 1280; kind = 2; }

    extern __shared__ float dyn[];
    // stage s: As = dyn + s*GSTAGE, Bs = As + 128*36
    float* Cs = dyn;                       // [128][68] epilogue overlap (stage 0)

    const int tid  = threadIdx.x;
    const int lane = tid & 31, warp = tid >> 5;
    const int wm = warp & 3, wn = warp >> 2;
    const int g = lane >> 2, t = lane & 3;

    const int arA[4] = { (tid + 0) >> 3, (tid + 256) >> 3, (tid + 512) >> 3, (tid + 768) >> 3 };
    const int acA    = (tid & 7) * 4;
    const int brB[2] = { tid >> 4, (tid + 256) >> 4 };
    const int bcB    = (tid & 15) * 4;

    float cfr[2][4][4] = {};
    float4 ra[4], rb[2];

    // Prologue: tile 0 -> stage 0
    #pragma unroll
    for (int it = 0; it < 4; it++) ra[it] = *(const float4*)&X[(m0 + arA[it]) * 1024 + acA];
    #pragma unroll
    for (int it = 0; it < 2; it++) rb[it] = *(const float4*)&Bmat[brB[it] * ldb + ncol0 + bcB];
    stageA(dyn, arA, acA, ra);
    stageB(dyn + 128 * 36, brB, bcB, rb);
    __syncthreads();

    #pragma unroll 2
    for (int k0 = 0; k0 < 1024; k0 += 32) {
        const int cur = (k0 >> 5) & 1;
        float* As  = dyn + (cur ? GSTAGE : 0);
        float* Bs  = As + 128 * 36;
        float* Asn = dyn + (cur ? 0 : GSTAGE);
        float* Bsn = Asn + 128 * 36;
        const bool has_next = (k0 + 32) < 1024;

        if (has_next) {
            const int kn = k0 + 32;
            #pragma unroll
            for (int it = 0; it < 4; it++) ra[it] = *(const float4*)&X[(m0 + arA[it]) * 1024 + kn + acA];
            #pragma unroll
            for (int it = 0; it < 2; it++) rb[it] = *(const float4*)&Bmat[(kn + brB[it]) * ldb + ncol0 + bcB];
        }

        mma_phase(As, Bs, wm, wn, g, t, cfr);

        if (has_next) {
            stageA(Asn, arA, acA, ra);
            stageB(Bsn, brB, bcB, rb);
        }
        __syncthreads();
    }

    // Fragments -> Cs for RoPE exchange
    #pragma unroll
    for (int f = 0; f < 2; f++) {
        int rbm = wm * 32 + f * 16 + g;
        #pragma unroll
        for (int j = 0; j < 4; j++) {
            int col = wn * 32 + j * 8 + 2 * t;
            Cs[(rbm    ) * 68 + col    ] = cfr[f][j][0];
            Cs[(rbm    ) * 68 + col + 1] = cfr[f][j][1];
            Cs[(rbm + 8) * 68 + col    ] = cfr[f][j][2];
            Cs[(rbm + 8) * 68 + col + 1] = cfr[f][j][3];
        }
    }
    __syncthreads();

    const int head_local = (kind == 0) ? (n0g >> 6) : (ncol0 >> 6);
    const int r0e = (tid >> 4) * 8;
    const int c0e = (tid & 15) * 4;
    #pragma unroll
    for (int i = 0; i < 8; i++) {
        const int r = r0e + i;
        const int m = m0 + r;
        #pragma unroll
        for (int j = 0; j < 4; j++) {
            const int d = c0e + j;
            float val = Cs[r * 68 + d];
            float outv;
            if (kind == 2) {
                outv = val;
            } else {
                float partner = (d < 32) ? -Cs[r * 68 + d + 32] : Cs[r * 68 + d - 32];
                outv = val * cs[m * HD + d] + partner * sn[m * HD + d];
                if (kind == 0) outv *= SCALING;
            }
            outv = f2tff(outv);
            const int dst = head_local * SEQ * HD + m * HD + d;
            if (kind == 0)      g_Q[dst] = outv;
            else if (kind == 1) g_K[dst] = outv;
            else                g_V[dst] = outv;
        }
    }
}

// ---------------------------------------------------------------------------
// Kernel 2: flash attention (tf32), pipelined (unchanged from round 6).
// ---------------------------------------------------------------------------
__global__ __launch_bounds__(256, 2) void flash_kernel()
{
    const int q0  = blockIdx.x * 128;
    const int h   = blockIdx.y;
    const int kvh = h >> 2;

    extern __shared__ float smf[];
    float* Qs = smf;                          // [128][68]
    float* Ks = smf + 128 * 68;               // [64][68]
    float* Vs = smf + 128 * 68 + 64 * 68;     // [64][72]
    float* SP = smf + 128 * 68 + 64 * 68 + 64 * 72;  // [128][68]
    __shared__ float row_m[128], row_l[128], row_scale[128];

    const int tid  = threadIdx.x;
    const int lane = tid & 31, warp = tid >> 5;
    const int wm = warp & 3, wn = warp >> 2;
    const int g = lane >> 2, t = lane & 3;

    const float* Qg = g_Q + h * SEQ * HD + q0 * HD;
    const float* Kg = g_K + kvh * SEQ * HD;
    const float* Vg = g_V + kvh * SEQ * HD;

    const int kvR[4] = { (tid + 0) >> 4, (tid + 256) >> 4, (tid + 512) >> 4, (tid + 768) >> 4 };
    const int kvC    = (tid & 15) * 4;

    #pragma unroll
    for (int it = 0; it < 8; it++) {
        int id = tid + it * 256;
        int r = id >> 4, c4 = (id & 15) * 4;
        *(float4*)&Qs[r * 68 + c4] = *(const float4*)&Qg[r * 64 + c4];
    }
    if (tid < 128) { row_m[tid] = -INFINITY; row_l[tid] = 0.0f; }

    float4 rk[4];
    #pragma unroll
    for (int it = 0; it < 4; it++) rk[it] = *(const float4*)&Kg[kvR[it] * 64 + kvC];

    float ofr[2][4][4] = {};

    for (int kt = 0; kt < 32; kt++) {
        __syncthreads();

        #pragma unroll
        for (int it = 0; it < 4; it++) *(float4*)&Ks[kvR[it] * 68 + kvC] = rk[it];
        const float* Vp = Vg + kt * 64 * 64;
        #pragma unroll
        for (int it = 0; it < 4; it++) cp16(&Vs[kvR[it] * 72 + kvC], &Vp[kvR[it] * 64 + kvC]);
        asm volatile("cp.async.commit_group;");
        if (kt + 1 < 32) {
            const float* Kp = Kg + (kt + 1) * 64 * 64;
            #pragma unroll
            for (int it = 0; it < 4; it++) rk[it] = *(const float4*)&Kp[kvR[it] * 64 + kvC];
        }
        __syncthreads();

        float sfr[2][4][4] = {};
        #pragma unroll
        for (int ks = 0; ks < 8; ks++) {
            const int kk = ks * 8;
            uint32_t af[2][4];
            #pragma unroll
            for (int f = 0; f < 2; f++) {
                int rbm = wm * 32 + f * 16 + g;
                af[f][0] = __float_as_uint(Qs[(rbm    ) * 68 + kk + t    ]);
                af[f][1] = __float_as_uint(Qs[(rbm + 8) * 68 + kk + t    ]);
                af[f][2] = __float_as_uint(Qs[(rbm    ) * 68 + kk + t + 4]);
                af[f][3] = __float_as_uint(Qs[(rbm + 8) * 68 + kk + t + 4]);
            }
            #pragma unroll
            for (int j = 0; j < 4; j++) {
                int nb = wn * 32 + j * 8 + g;
                uint32_t b0 = __float_as_uint(Ks[nb * 68 + kk + t    ]);
                uint32_t b1 = __float_as_uint(Ks[nb * 68 + kk + t + 4]);
                mma8(sfr[0][j], af[0][0], af[0][1], af[0][2], af[0][3], b0, b1);
                mma8(sfr[1][j], af[1][0], af[1][1], af[1][2], af[1][3], b0, b1);
            }
        }

        #pragma unroll
        for (int f = 0; f < 2; f++) {
            int rbm = wm * 32 + f * 16 + g;
            #pragma unroll
            for (int j = 0; j < 4; j++) {
                int col = wn * 32 + j * 8 + 2 * t;
                SP[(rbm    ) * 68 + col    ] = sfr[f][j][0];
                SP[(rbm    ) * 68 + col + 1] = sfr[f][j][1];
                SP[(rbm + 8) * 68 + col    ] = sfr[f][j][2];
                SP[(rbm + 8) * 68 + col + 1] = sfr[f][j][3];
            }
        }
        asm volatile("cp.async.wait_group 0;" ::: "memory");
        __syncthreads();

        {
            const int row = tid >> 1, part = tid & 1;
            float* Sr = SP + row * 68 + part * 32;
            float4 v[8];
            #pragma unroll
            for (int i = 0; i < 8; i++) v[i] = *(const float4*)&Sr[i * 4];
            float mloc = -INFINITY;
            #pragma unroll
            for (int i = 0; i < 8; i++)
                mloc = fmaxf(mloc, fmaxf(fmaxf(v[i].x, v[i].y), fmaxf(v[i].z, v[i].w)));
            mloc = fmaxf(mloc, __shfl_xor_sync(0xffffffffu, mloc, 1));
            float mold = row_m[row];
            float mnew = fmaxf(mold, mloc);
            float ssum = 0.0f;
            #pragma unroll
            for (int i = 0; i < 8; i++) {
                v[i].x = __expf(v[i].x - mnew); v[i].y = __expf(v[i].y - mnew);
                v[i].z = __expf(v[i].z - mnew); v[i].w = __expf(v[i].w - mnew);
                ssum += v[i].x + v[i].y + v[i].z + v[i].w;
                v[i].x = f2tff(v[i].x); v[i].y = f2tff(v[i].y);
                v[i].z = f2tff(v[i].z); v[i].w = f2tff(v[i].w);
                *(float4*)&Sr[i * 4] = v[i];
            }
            ssum += __shfl_xor_sync(0xffffffffu, ssum, 1);
            if (part == 0) {
                float sc = __expf(mold - mnew);
                row_scale[row] = sc;
                row_l[row] = row_l[row] * sc + ssum;
                row_m[row] = mnew;
            }
        }
        __syncthreads();

        #pragma unroll
        for (int f = 0; f < 2; f++) {
            int rbm = wm * 32 + f * 16 + g;
            float s1 = row_scale[rbm];
            float s2 = row_scale[rbm + 8];
            #pragma unroll
            for (int j = 0; j < 4; j++) {
                ofr[f][j][0] *= s1; ofr[f][j][1] *= s1;
                ofr[f][j][2] *= s2; ofr[f][j][3] *= s2;
            }
        }
        #pragma unroll
        for (int ks = 0; ks < 8; ks++) {
            const int kk = ks * 8;
            uint32_t af[2][4];
            #pragma unroll
            for (int f = 0; f < 2; f++) {
                int rbm = wm * 32 + f * 16 + g;
                af[f][0] = __float_as_uint(SP[(rbm    ) * 68 + kk + t    ]);
                af[f][1] = __float_as_uint(SP[(rbm + 8) * 68 + kk + t    ]);
                af[f][2] = __float_as_uint(SP[(rbm    ) * 68 + kk + t + 4]);
                af[f][3] = __float_as_uint(SP[(rbm + 8) * 68 + kk + t + 4]);
            }
            #pragma unroll
            for (int j = 0; j < 4; j++) {
                int nb = wn * 32 + j * 8 + g;
                uint32_t b0 = __float_as_uint(Vs[(kk + t    ) * 72 + nb]);
                uint32_t b1 = __float_as_uint(Vs[(kk + t + 4) * 72 + nb]);
                mma8(ofr[0][j], af[0][0], af[0][1], af[0][2], af[0][3], b0, b1);
                mma8(ofr[1][j], af[1][0], af[1][1], af[1][2], af[1][3], b0, b1);
            }
        }
    }

    __syncthreads();
    #pragma unroll
    for (int f = 0; f < 2; f++) {
        int rbm = wm * 32 + f * 16 + g;
        float l1 = 1.0f / row_l[rbm];
        float l2 = 1.0f / row_l[rbm + 8];
        #pragma unroll
        for (int j = 0; j < 4; j++) {
            int col = wn * 32 + j * 8 + 2 * t;
            SP[(rbm    ) * 68 + col    ] = ofr[f][j][0] * l1;
            SP[(rbm    ) * 68 + col + 1] = ofr[f][j][1] * l1;
            SP[(rbm + 8) * 68 + col    ] = ofr[f][j][2] * l2;
            SP[(rbm + 8) * 68 + col + 1] = ofr[f][j][3] * l2;
        }
    }
    __syncthreads();
    #pragma unroll
    for (int it = 0; it < 8; it++) {
        int id = tid + it * 256;
        int r = id >> 4, c4 = (id & 15) * 4;
        *(float4*)&g_AO[(q0 + r) * 1024 + h * 64 + c4] = *(const float4*)&SP[r * 68 + c4];
    }
}

// ---------------------------------------------------------------------------
// Kernel 3: output projection (tf32), double-buffered smem pipeline.
// ---------------------------------------------------------------------------
__global__ __launch_bounds__(256, 2) void oproj_kernel(
    const float* __restrict__ Wo, float* __restrict__ out)
{
    const int n0 = blockIdx.x * 64;
    const int m0 = blockIdx.y * 128;

    extern __shared__ float dyn[];
    float* Cs = dyn;                       // [128][68] epilogue overlap

    const int tid  = threadIdx.x;
    const int lane = tid & 31, warp = tid >> 5;
    const int wm = warp & 3, wn = warp >> 2;
    const int g = lane >> 2, t = lane & 3;

    const int arA[4] = { (tid + 0) >> 3, (tid + 256) >> 3, (tid + 512) >> 3, (tid + 768) >> 3 };
    const int acA    = (tid & 7) * 4;
    const int brB[2] = { tid >> 4, (tid + 256) >> 4 };
    const int bcB    = (tid & 15) * 4;

    float cfr[2][4][4] = {};
    float4 ra[4], rb[2];

    #pragma unroll
    for (int it = 0; it < 4; it++) ra[it] = *(const float4*)&g_AO[(m0 + arA[it]) * 1024 + acA];
    #pragma unroll
    for (int it = 0; it < 2; it++) rb[it] = *(const float4*)&Wo[brB[it] * 1024 + n0 + bcB];
    stageA(dyn, arA, acA, ra);
    stageB(dyn + 128 * 36, brB, bcB, rb);
    __syncthreads();

    #pragma unroll 2
    for (int k0 = 0; k0 < 1024; k0 += 32) {
        const int cur = (k0 >> 5) & 1;
        float* As  = dyn + (cur ? GSTAGE : 0);
        float* Bs  = As + 128 * 36;
        float* Asn = dyn + (cur ? 0 : GSTAGE);
        float* Bsn = Asn + 128 * 36;
        const bool has_next = (k0 + 32) < 1024;

        if (has_next) {
            const int kn = k0 + 32;
            #pragma unroll
            for (int it = 0; it < 4; it++) ra[it] = *(const float4*)&g_AO[(m0 + arA[it]) * 1024 + kn + acA];
            #pragma unroll
            for (int it = 0; it < 2; it++) rb[it] = *(const float4*)&Wo[(kn + brB[it]) * 1024 + n0 + bcB];
        }

        mma_phase(As, Bs, wm, wn, g, t, cfr);

        if (has_next) {
            stageA(Asn, arA, acA, ra);
            stageB(Bsn, brB, bcB, rb);
        }
        __syncthreads();
    }

    #pragma unroll
    for (int f = 0; f < 2; f++) {
        int rbm = wm * 32 + f * 16 + g;
        #pragma unroll
        for (int j = 0; j < 4; j++) {
            int col = wn * 32 + j * 8 + 2 * t;
            Cs[(rbm    ) * 68 + col    ] = cfr[f][j][0];
            Cs[(rbm    ) * 68 + col + 1] = cfr[f][j][1];
            Cs[(rbm + 8) * 68 + col    ] = cfr[f][j][2];
            Cs[(rbm + 8) * 68 + col + 1] = cfr[f][j][3];
        }
    }
    __syncthreads();
    #pragma unroll
    for (int it = 0; it < 8; it++) {
        int id = tid + it * 256;
        int r = id >> 4, c4 = (id & 15) * 4;
        *(float4*)&out[(m0 + r) * 1024 + n0 + c4] = *(const float4*)&Cs[r * 68 + c4];
    }
}

// ---------------------------------------------------------------------------
// Launch.
// ---------------------------------------------------------------------------
extern "C" void kernel_launch(void* const* d_in, const int* in_sizes, int n_in,
                              void* d_out, int out_size)
{
    const float* X  = (const float*)d_in[0];
    const float* cs = (const float*)d_in[1];
    const float* sn = (const float*)d_in[2];
    // d_in[3] = attention_mask (all ones) — unused
    const float* Wq = (const float*)d_in[4];
    const float* Wk = (const float*)d_in[5];
    const float* Wv = (const float*)d_in[6];
    const float* Wo = (const float*)d_in[7];
    float* out = (float*)d_out;

    const size_t smem_gemm = 2 * GSTAGE * sizeof(float);   // 54272 B
    cudaFuncSetAttribute(qkv_rope_kernel,
                         cudaFuncAttributeMaxDynamicSharedMemorySize, (int)smem_gemm);
    cudaFuncSetAttribute(oproj_kernel,
                         cudaFuncAttributeMaxDynamicSharedMemorySize, (int)smem_gemm);

    qkv_rope_kernel<<<dim3(24, 16), 256, smem_gemm>>>(X, Wq, Wk, Wv, cs, sn);

    // Qs[128][68] + Ks[64][68] + Vs[64][72] + SP[128][68]
    const size_t smem_flash = (128 * 68 + 64 * 68 + 64 * 72 + 128 * 68) * sizeof(float); // 105472 B
    cudaFuncSetAttribute(flash_kernel,
                         cudaFuncAttributeMaxDynamicSharedMemorySize, (int)smem_flash);
    flash_kernel<<<dim3(16, 16), 256, smem_flash>>>();

    oproj_kernel<<<dim3(16, 16), 256, smem_gemm>>>(Wo, out);
}

// round 8
// speedup vs baseline: 3.9147x; 1.1029x over previous
#include <cuda_runtime.h>
#include <math.h>
#include <stdint.h>

#define SEQ 2048
#define HID 1024
#define NH 16
#define NKV 4
#define HD 64
#define SCALING 0.125f

// GEMM double-buffer stage size (floats): As[128][36] + Bs[32][68]
#define GSTAGE (128 * 36 + 32 * 68)   // 6784

// Scratch (device globals; 16B-aligned: targets of float4 access)
__device__ __align__(16) float g_Q[NH * SEQ * HD];    // [h][m][d], RoPE'd, pre-scaled, tf32
__device__ __align__(16) float g_K[NKV * SEQ * HD];   // [kvh][m][d], RoPE'd, tf32
__device__ __align__(16) float g_V[NKV * SEQ * HD];   // [kvh][m][d], tf32
__device__ __align__(16) float g_AO[SEQ * HID];       // [m][h*64+d] fp32

// ---------------------------------------------------------------------------
// Helpers
// ---------------------------------------------------------------------------
__device__ __forceinline__ float f2tff(float x) {
    uint32_t r;
    asm("cvt.rna.tf32.f32 %0, %1;" : "=r"(r) : "f"(x));
    return __uint_as_float(r);
}

__device__ __forceinline__ void mma8(float c[4],
                                     uint32_t a0, uint32_t a1, uint32_t a2, uint32_t a3,
                                     uint32_t b0, uint32_t b1) {
    asm volatile(
        "mma.sync.aligned.m16n8k8.row.col.f32.tf32.tf32.f32 "
        "{%0,%1,%2,%3}, {%4,%5,%6,%7}, {%8,%9}, {%0,%1,%2,%3};"
        : "+f"(c[0]), "+f"(c[1]), "+f"(c[2]), "+f"(c[3])
        : "r"(a0), "r"(a1), "r"(a2), "r"(a3), "r"(b0), "r"(b1));
}

__device__ __forceinline__ void cp16(float* smem_dst, const float* gsrc) {
    uint32_t s = (uint32_t)__cvta_generic_to_shared(smem_dst);
    asm volatile("cp.async.ca.shared.global [%0], [%1], 16;" :: "r"(s), "l"(gsrc));
}

// Stage helpers for the projection GEMMs
__device__ __forceinline__ void stageA(float* As, const int* arA, int acA, const float4* ra) {
    #pragma unroll
    for (int it = 0; it < 4; it++) {
        float* a = &As[arA[it] * 36 + acA];
        a[0] = f2tff(ra[it].x); a[1] = f2tff(ra[it].y);
        a[2] = f2tff(ra[it].z); a[3] = f2tff(ra[it].w);
    }
}
__device__ __forceinline__ void stageB(float* Bs, const int* brB, int bcB, const float4* rb) {
    #pragma unroll
    for (int it = 0; it < 2; it++) {
        float* b = &Bs[brB[it] * 68 + bcB];
        b[0] = f2tff(rb[it].x); b[1] = f2tff(rb[it].y);
        b[2] = f2tff(rb[it].z); b[3] = f2tff(rb[it].w);
    }
}

__device__ __forceinline__ void mma_phase(const float* As, const float* Bs,
                                          int wm, int wn, int g, int t,
                                          float cfr[2][4][4]) {
    #pragma unroll
    for (int ks = 0; ks < 4; ks++) {
        const int kk = ks * 8;
        uint32_t af[2][4];
        #pragma unroll
        for (int f = 0; f < 2; f++) {
            int rbm = wm * 32 + f * 16 + g;
            af[f][0] = __float_as_uint(As[(rbm    ) * 36 + kk + t    ]);
            af[f][1] = __float_as_uint(As[(rbm + 8) * 36 + kk + t    ]);
            af[f][2] = __float_as_uint(As[(rbm    ) * 36 + kk + t + 4]);
            af[f][3] = __float_as_uint(As[(rbm + 8) * 36 + kk + t + 4]);
        }
        #pragma unroll
        for (int j = 0; j < 4; j++) {
            int nb = wn * 32 + j * 8 + g;
            uint32_t b0 = __float_as_uint(Bs[(kk + t    ) * 68 + nb]);
            uint32_t b1 = __float_as_uint(Bs[(kk + t + 4) * 68 + nb]);
            mma8(cfr[0][j], af[0][0], af[0][1], af[0][2], af[0][3], b0, b1);
            mma8(cfr[1][j], af[1][0], af[1][1], af[1][2], af[1][3], b0, b1);
        }
    }
}

// ---------------------------------------------------------------------------
// Kernel 1: fused QKV projection + RoPE (tf32), double-buffered smem pipeline.
// ---------------------------------------------------------------------------
__global__ __launch_bounds__(256, 2) void qkv_rope_kernel(
    const float* __restrict__ X,
    const float* __restrict__ Wq,
    const float* __restrict__ Wk,
    const float* __restrict__ Wv,
    const float* __restrict__ cs,
    const float* __restrict__ sn)
{
    const int n0g = blockIdx.x * 64;
    const int m0  = blockIdx.y * 128;

    const float* Bmat;
    int ldb, ncol0, kind;                  // 0=Q, 1=K, 2=V
    if (n0g < 1024)       { Bmat = Wq; ldb = 1024; ncol0 = n0g;        kind = 0; }
    else if (n0g < 1280)  { Bmat = Wk; ldb = 256;  ncol0 = n0g - 1024; kind = 1; }
    else                  { Bmat = Wv; ldb = 256;  ncol0 = n0g - 1280; kind = 2; }

    extern __shared__ float dyn[];
    float* Cs = dyn;                       // [128][68] epilogue overlap (stage 0)

    const int tid  = threadIdx.x;
    const int lane = tid & 31, warp = tid >> 5;
    const int wm = warp & 3, wn = warp >> 2;
    const int g = lane >> 2, t = lane & 3;

    const int arA[4] = { (tid + 0) >> 3, (tid + 256) >> 3, (tid + 512) >> 3, (tid + 768) >> 3 };
    const int acA    = (tid & 7) * 4;
    const int brB[2] = { tid >> 4, (tid + 256) >> 4 };
    const int bcB    = (tid & 15) * 4;

    float cfr[2][4][4] = {};
    float4 ra[4], rb[2];

    #pragma unroll
    for (int it = 0; it < 4; it++) ra[it] = *(const float4*)&X[(m0 + arA[it]) * 1024 + acA];
    #pragma unroll
    for (int it = 0; it < 2; it++) rb[it] = *(const float4*)&Bmat[brB[it] * ldb + ncol0 + bcB];
    stageA(dyn, arA, acA, ra);
    stageB(dyn + 128 * 36, brB, bcB, rb);
    __syncthreads();

    #pragma unroll 2
    for (int k0 = 0; k0 < 1024; k0 += 32) {
        const int cur = (k0 >> 5) & 1;
        float* As  = dyn + (cur ? GSTAGE : 0);
        float* Bs  = As + 128 * 36;
        float* Asn = dyn + (cur ? 0 : GSTAGE);
        float* Bsn = Asn + 128 * 36;
        const bool has_next = (k0 + 32) < 1024;

        if (has_next) {
            const int kn = k0 + 32;
            #pragma unroll
            for (int it = 0; it < 4; it++) ra[it] = *(const float4*)&X[(m0 + arA[it]) * 1024 + kn + acA];
            #pragma unroll
            for (int it = 0; it < 2; it++) rb[it] = *(const float4*)&Bmat[(kn + brB[it]) * ldb + ncol0 + bcB];
        }

        mma_phase(As, Bs, wm, wn, g, t, cfr);

        if (has_next) {
            stageA(Asn, arA, acA, ra);
            stageB(Bsn, brB, bcB, rb);
        }
        __syncthreads();
    }

    #pragma unroll
    for (int f = 0; f < 2; f++) {
        int rbm = wm * 32 + f * 16 + g;
        #pragma unroll
        for (int j = 0; j < 4; j++) {
            int col = wn * 32 + j * 8 + 2 * t;
            Cs[(rbm    ) * 68 + col    ] = cfr[f][j][0];
            Cs[(rbm    ) * 68 + col + 1] = cfr[f][j][1];
            Cs[(rbm + 8) * 68 + col    ] = cfr[f][j][2];
            Cs[(rbm + 8) * 68 + col + 1] = cfr[f][j][3];
        }
    }
    __syncthreads();

    const int head_local = (kind == 0) ? (n0g >> 6) : (ncol0 >> 6);
    const int r0e = (tid >> 4) * 8;
    const int c0e = (tid & 15) * 4;
    #pragma unroll
    for (int i = 0; i < 8; i++) {
        const int r = r0e + i;
        const int m = m0 + r;
        #pragma unroll
        for (int j = 0; j < 4; j++) {
            const int d = c0e + j;
            float val = Cs[r * 68 + d];
            float outv;
            if (kind == 2) {
                outv = val;
            } else {
                float partner = (d < 32) ? -Cs[r * 68 + d + 32] : Cs[r * 68 + d - 32];
                outv = val * cs[m * HD + d] + partner * sn[m * HD + d];
                if (kind == 0) outv *= SCALING;
            }
            outv = f2tff(outv);
            const int dst = head_local * SEQ * HD + m * HD + d;
            if (kind == 0)      g_Q[dst] = outv;
            else if (kind == 1) g_K[dst] = outv;
            else                g_V[dst] = outv;
        }
    }
}

// ---------------------------------------------------------------------------
// Kernel 2: flash attention (tf32) — warp-exclusive rows, register softmax,
// cp.async 2-stage KV pipeline, ONE block barrier per KV tile.
// Block = (128 queries, head). 8 warps, warp tile 16 rows x 64 cols.
// Smem: QSP[128][68] (Q, then P, then O staging) + K[2][64][68] + V[2][64][72].
// ---------------------------------------------------------------------------
__global__ __launch_bounds__(256, 2) void flash_kernel()
{
    const int q0  = blockIdx.x * 128;
    const int h   = blockIdx.y;
    const int kvh = h >> 2;

    extern __shared__ float smf[];
    float* QSP = smf;                              // [128][68]
    float* Kst = smf + 128 * 68;                   // [2][64][68]
    float* Vst = smf + 128 * 68 + 2 * 64 * 68;     // [2][64][72]

    const int tid  = threadIdx.x;
    const int lane = tid & 31, warp = tid >> 5;
    const int g = lane >> 2, t = lane & 3;
    const int rw = warp * 16;                      // this warp's row base

    const float* Qg = g_Q + h * SEQ * HD + q0 * HD;
    const float* Kg = g_K + kvh * SEQ * HD;
    const float* Vg = g_V + kvh * SEQ * HD;

    // KV staging coords: 4 chunks x 256 threads x float4 covers 64x64
    const int kvR[4] = { (tid + 0) >> 4, (tid + 256) >> 4, (tid + 512) >> 4, (tid + 768) >> 4 };
    const int kvC    = (tid & 15) * 4;

    // Load Q tile cooperatively, then hoist this warp's fragments to registers.
    #pragma unroll
    for (int it = 0; it < 8; it++) {
        int id = tid + it * 256;
        int r = id >> 4, c4 = (id & 15) * 4;
        *(float4*)&QSP[r * 68 + c4] = *(const float4*)&Qg[r * 64 + c4];
    }
    __syncthreads();
    uint32_t qfr[8][4];
    #pragma unroll
    for (int ks = 0; ks < 8; ks++) {
        const int kk = ks * 8;
        qfr[ks][0] = __float_as_uint(QSP[(rw + g    ) * 68 + kk + t    ]);
        qfr[ks][1] = __float_as_uint(QSP[(rw + g + 8) * 68 + kk + t    ]);
        qfr[ks][2] = __float_as_uint(QSP[(rw + g    ) * 68 + kk + t + 4]);
        qfr[ks][3] = __float_as_uint(QSP[(rw + g + 8) * 68 + kk + t + 4]);
    }
    // (each warp reads only its own rows; P later overwrites only its own rows)

    // Prologue: stage KV tile 0 into slot 0
    {
        const float* Kp = Kg;
        const float* Vp = Vg;
        #pragma unroll
        for (int it = 0; it < 4; it++) {
            cp16(&Kst[kvR[it] * 68 + kvC], &Kp[kvR[it] * 64 + kvC]);
            cp16(&Vst[kvR[it] * 72 + kvC], &Vp[kvR[it] * 64 + kvC]);
        }
        asm volatile("cp.async.commit_group;");
    }

    float m1 = -INFINITY, m2 = -INFINITY, l1 = 0.0f, l2 = 0.0f;
    float ofr[8][4] = {};

    for (int kt = 0; kt < 32; kt++) {
        asm volatile("cp.async.wait_group 0;" ::: "memory");
        __syncthreads();   // KV(kt) ready; all warps done with slot (kt-1)&1

        if (kt + 1 < 32) {
            const int sl = (kt + 1) & 1;
            const float* Kp = Kg + (kt + 1) * 64 * 64;
            const float* Vp = Vg + (kt + 1) * 64 * 64;
            float* Kn = Kst + sl * 64 * 68;
            float* Vn = Vst + sl * 64 * 72;
            #pragma unroll
            for (int it = 0; it < 4; it++) {
                cp16(&Kn[kvR[it] * 68 + kvC], &Kp[kvR[it] * 64 + kvC]);
                cp16(&Vn[kvR[it] * 72 + kvC], &Vp[kvR[it] * 64 + kvC]);
            }
            asm volatile("cp.async.commit_group;");
        }

        const float* Ks = Kst + (kt & 1) * 64 * 68;
        const float* Vs = Vst + (kt & 1) * 64 * 72;

        // S = Q @ K^T : 16 rows x 64 cols, 8 n-blocks x 8 k-steps
        float sfr[8][4] = {};
        #pragma unroll
        for (int ks = 0; ks < 8; ks++) {
            const int kk = ks * 8;
            #pragma unroll
            for (int j = 0; j < 8; j++) {
                int nb = j * 8 + g;
                uint32_t b0 = __float_as_uint(Ks[nb * 68 + kk + t    ]);
                uint32_t b1 = __float_as_uint(Ks[nb * 68 + kk + t + 4]);
                mma8(sfr[j], qfr[ks][0], qfr[ks][1], qfr[ks][2], qfr[ks][3], b0, b1);
            }
        }

        // Register online softmax (rows rw+g and rw+g+8; reduce over quad)
        float mloc1 = -INFINITY, mloc2 = -INFINITY;
        #pragma unroll
        for (int j = 0; j < 8; j++) {
            mloc1 = fmaxf(mloc1, fmaxf(sfr[j][0], sfr[j][1]));
            mloc2 = fmaxf(mloc2, fmaxf(sfr[j][2], sfr[j][3]));
        }
        mloc1 = fmaxf(mloc1, __shfl_xor_sync(0xffffffffu, mloc1, 1));
        mloc1 = fmaxf(mloc1, __shfl_xor_sync(0xffffffffu, mloc1, 2));
        mloc2 = fmaxf(mloc2, __shfl_xor_sync(0xffffffffu, mloc2, 1));
        mloc2 = fmaxf(mloc2, __shfl_xor_sync(0xffffffffu, mloc2, 2));
        float mnew1 = fmaxf(m1, mloc1);
        float mnew2 = fmaxf(m2, mloc2);
        float sc1 = __expf(m1 - mnew1);   // first iter: exp(-inf) = 0
        float sc2 = __expf(m2 - mnew2);
        float ss1 = 0.0f, ss2 = 0.0f;
        #pragma unroll
        for (int j = 0; j < 8; j++) {
            sfr[j][0] = __expf(sfr[j][0] - mnew1); ss1 += sfr[j][0];
            sfr[j][1] = __expf(sfr[j][1] - mnew1); ss1 += sfr[j][1];
            sfr[j][2] = __expf(sfr[j][2] - mnew2); ss2 += sfr[j][2];
            sfr[j][3] = __expf(sfr[j][3] - mnew2); ss2 += sfr[j][3];
        }
        ss1 += __shfl_xor_sync(0xffffffffu, ss1, 1);
        ss1 += __shfl_xor_sync(0xffffffffu, ss1, 2);
        ss2 += __shfl_xor_sync(0xffffffffu, ss2, 1);
        ss2 += __shfl_xor_sync(0xffffffffu, ss2, 2);
        l1 = l1 * sc1 + ss1;  m1 = mnew1;
        l2 = l2 * sc2 + ss2;  m2 = mnew2;

        #pragma unroll
        for (int j = 0; j < 8; j++) {
            ofr[j][0] *= sc1; ofr[j][1] *= sc1;
            ofr[j][2] *= sc2; ofr[j][3] *= sc2;
        }

        // P -> QSP (own rows only), tf32-rounded
        #pragma unroll
        for (int j = 0; j < 8; j++) {
            int col = j * 8 + 2 * t;
            QSP[(rw + g    ) * 68 + col    ] = f2tff(sfr[j][0]);
            QSP[(rw + g    ) * 68 + col + 1] = f2tff(sfr[j][1]);
            QSP[(rw + g + 8) * 68 + col    ] = f2tff(sfr[j][2]);
            QSP[(rw + g + 8) * 68 + col + 1] = f2tff(sfr[j][3]);
        }
        __syncwarp();

        // O += P @ V : k over kv (64), n over d (64)
        #pragma unroll
        for (int ks = 0; ks < 8; ks++) {
            const int kk = ks * 8;
            uint32_t a0 = __float_as_uint(QSP[(rw + g    ) * 68 + kk + t    ]);
            uint32_t a1 = __float_as_uint(QSP[(rw + g + 8) * 68 + kk + t    ]);
            uint32_t a2 = __float_as_uint(QSP[(rw + g    ) * 68 + kk + t + 4]);
            uint32_t a3 = __float_as_uint(QSP[(rw + g + 8) * 68 + kk + t + 4]);
            #pragma unroll
            for (int j = 0; j < 8; j++) {
                int nb = j * 8 + g;
                uint32_t b0 = __float_as_uint(Vs[(kk + t    ) * 72 + nb]);
                uint32_t b1 = __float_as_uint(Vs[(kk + t + 4) * 72 + nb]);
                mma8(ofr[j], a0, a1, a2, a3, b0, b1);
            }
        }
    }

    // Normalize into QSP (own rows), then coalesced block-wide store.
    float inv1 = 1.0f / l1;
    float inv2 = 1.0f / l2;
    #pragma unroll
    for (int j = 0; j < 8; j++) {
        int col = j * 8 + 2 * t;
        QSP[(rw + g    ) * 68 + col    ] = ofr[j][0] * inv1;
        QSP[(rw + g    ) * 68 + col + 1] = ofr[j][1] * inv1;
        QSP[(rw + g + 8) * 68 + col    ] = ofr[j][2] * inv2;
        QSP[(rw + g + 8) * 68 + col + 1] = ofr[j][3] * inv2;
    }
    __syncthreads();
    #pragma unroll
    for (int it = 0; it < 8; it++) {
        int id = tid + it * 256;
        int r = id >> 4, c4 = (id & 15) * 4;
        *(float4*)&g_AO[(q0 + r) * 1024 + h * 64 + c4] = *(const float4*)&QSP[r * 68 + c4];
    }
}

// ---------------------------------------------------------------------------
// Kernel 3: output projection (tf32), double-buffered smem pipeline.
// ---------------------------------------------------------------------------
__global__ __launch_bounds__(256, 2) void oproj_kernel(
    const float* __restrict__ Wo, float* __restrict__ out)
{
    const int n0 = blockIdx.x * 64;
    const int m0 = blockIdx.y * 128;

    extern __shared__ float dyn[];
    float* Cs = dyn;

    const int tid  = threadIdx.x;
    const int lane = tid & 31, warp = tid >> 5;
    const int wm = warp & 3, wn = warp >> 2;
    const int g = lane >> 2, t = lane & 3;

    const int arA[4] = { (tid + 0) >> 3, (tid + 256) >> 3, (tid + 512) >> 3, (tid + 768) >> 3 };
    const int acA    = (tid & 7) * 4;
    const int brB[2] = { tid >> 4, (tid + 256) >> 4 };
    const int bcB    = (tid & 15) * 4;

    float cfr[2][4][4] = {};
    float4 ra[4], rb[2];

    #pragma unroll
    for (int it = 0; it < 4; it++) ra[it] = *(const float4*)&g_AO[(m0 + arA[it]) * 1024 + acA];
    #pragma unroll
    for (int it = 0; it < 2; it++) rb[it] = *(const float4*)&Wo[brB[it] * 1024 + n0 + bcB];
    stageA(dyn, arA, acA, ra);
    stageB(dyn + 128 * 36, brB, bcB, rb);
    __syncthreads();

    #pragma unroll 2
    for (int k0 = 0; k0 < 1024; k0 += 32) {
        const int cur = (k0 >> 5) & 1;
        float* As  = dyn + (cur ? GSTAGE : 0);
        float* Bs  = As + 128 * 36;
        float* Asn = dyn + (cur ? 0 : GSTAGE);
        float* Bsn = Asn + 128 * 36;
        const bool has_next = (k0 + 32) < 1024;

        if (has_next) {
            const int kn = k0 + 32;
            #pragma unroll
            for (int it = 0; it < 4; it++) ra[it] = *(const float4*)&g_AO[(m0 + arA[it]) * 1024 + kn + acA];
            #pragma unroll
            for (int it = 0; it < 2; it++) rb[it] = *(const float4*)&Wo[(kn + brB[it]) * 1024 + n0 + bcB];
        }

        mma_phase(As, Bs, wm, wn, g, t, cfr);

        if (has_next) {
            stageA(Asn, arA, acA, ra);
            stageB(Bsn, brB, bcB, rb);
        }
        __syncthreads();
    }

    #pragma unroll
    for (int f = 0; f < 2; f++) {
        int rbm = wm * 32 + f * 16 + g;
        #pragma unroll
        for (int j = 0; j < 4; j++) {
            int col = wn * 32 + j * 8 + 2 * t;
            Cs[(rbm    ) * 68 + col    ] = cfr[f][j][0];
            Cs[(rbm    ) * 68 + col + 1] = cfr[f][j][1];
            Cs[(rbm + 8) * 68 + col    ] = cfr[f][j][2];
            Cs[(rbm + 8) * 68 + col + 1] = cfr[f][j][3];
        }
    }
    __syncthreads();
    #pragma unroll
    for (int it = 0; it < 8; it++) {
        int id = tid + it * 256;
        int r = id >> 4, c4 = (id & 15) * 4;
        *(float4*)&out[(m0 + r) * 1024 + n0 + c4] = *(const float4*)&Cs[r * 68 + c4];
    }
}

// ---------------------------------------------------------------------------
// Launch.
// ---------------------------------------------------------------------------
extern "C" void kernel_launch(void* const* d_in, const int* in_sizes, int n_in,
                              void* d_out, int out_size)
{
    const float* X  = (const float*)d_in[0];
    const float* cs = (const float*)d_in[1];
    const float* sn = (const float*)d_in[2];
    // d_in[3] = attention_mask (all ones) — unused
    const float* Wq = (const float*)d_in[4];
    const float* Wk = (const float*)d_in[5];
    const float* Wv = (const float*)d_in[6];
    const float* Wo = (const float*)d_in[7];
    float* out = (float*)d_out;

    const size_t smem_gemm = 2 * GSTAGE * sizeof(float);   // 54272 B
    cudaFuncSetAttribute(qkv_rope_kernel,
                         cudaFuncAttributeMaxDynamicSharedMemorySize, (int)smem_gemm);
    cudaFuncSetAttribute(oproj_kernel,
                         cudaFuncAttributeMaxDynamicSharedMemorySize, (int)smem_gemm);

    qkv_rope_kernel<<<dim3(24, 16), 256, smem_gemm>>>(X, Wq, Wk, Wv, cs, sn);

    // QSP[128][68] + K[2][64][68] + V[2][64][72]
    const size_t smem_flash = (128 * 68 + 2 * 64 * 68 + 2 * 64 * 72) * sizeof(float); // 106496 B
    cudaFuncSetAttribute(flash_kernel,
                         cudaFuncAttributeMaxDynamicSharedMemorySize, (int)smem_flash);
    flash_kernel<<<dim3(16, 16), 256, smem_flash>>>();

    oproj_kernel<<<dim3(16, 16), 256, smem_gemm>>>(Wo, out);
}

// round 9
// speedup vs baseline: 3.9781x; 1.0162x over previous
#include <cuda_runtime.h>
#include <math.h>
#include <stdint.h>

#define SEQ 2048
#define HID 1024
#define NH 16
#define NKV 4
#define HD 64
#define SCALING 0.125f

// GEMM double-buffer stage size (floats): As[128][36] + Bs[32][68]
#define GSTAGE (128 * 36 + 32 * 68)   // 6784 floats = 27136 B

// Scratch (device globals; 16B-aligned: targets of float4 / cp.async access)
__device__ __align__(16) float g_Q[NH * SEQ * HD];    // [h][m][d] RoPE'd, pre-scaled, tf32
__device__ __align__(16) float g_K[NKV * SEQ * HD];   // [kvh][m][d] RoPE'd, tf32
__device__ __align__(16) float g_V[NKV * SEQ * HD];   // [kvh][m][d] tf32
__device__ __align__(16) float g_AO[SEQ * HID];       // [m][h*64+d] tf32-rounded
// tf32-rounded copies of inputs (made each launch by cvt kernels)
__device__ __align__(16) float g_Xt[SEQ * HID];
__device__ __align__(16) float g_Wqt[HID * 1024];
__device__ __align__(16) float g_Wkt[HID * 256];
__device__ __align__(16) float g_Wvt[HID * 256];
__device__ __align__(16) float g_Wot[1024 * HID];

// ---------------------------------------------------------------------------
// Helpers
// ---------------------------------------------------------------------------
__device__ __forceinline__ float f2tff(float x) {
    uint32_t r;
    asm("cvt.rna.tf32.f32 %0, %1;" : "=r"(r) : "f"(x));
    return __uint_as_float(r);
}

__device__ __forceinline__ void mma8(float c[4],
                                     uint32_t a0, uint32_t a1, uint32_t a2, uint32_t a3,
                                     uint32_t b0, uint32_t b1) {
    asm volatile(
        "mma.sync.aligned.m16n8k8.row.col.f32.tf32.tf32.f32 "
        "{%0,%1,%2,%3}, {%4,%5,%6,%7}, {%8,%9}, {%0,%1,%2,%3};"
        : "+f"(c[0]), "+f"(c[1]), "+f"(c[2]), "+f"(c[3])
        : "r"(a0), "r"(a1), "r"(a2), "r"(a3), "r"(b0), "r"(b1));
}

__device__ __forceinline__ void cp16(float* smem_dst, const float* gsrc) {
    uint32_t s = (uint32_t)__cvta_generic_to_shared(smem_dst);
    asm volatile("cp.async.ca.shared.global [%0], [%1], 16;" :: "r"(s), "l"(gsrc));
}

// One 32-k-step MMA phase over the given stage buffers
__device__ __forceinline__ void mma_phase(const float* As, const float* Bs,
                                          int wm, int wn, int g, int t,
                                          float cfr[2][4][4]) {
    #pragma unroll
    for (int ks = 0; ks < 4; ks++) {
        const int kk = ks * 8;
        uint32_t af[2][4];
        #pragma unroll
        for (int f = 0; f < 2; f++) {
            int rbm = wm * 32 + f * 16 + g;
            af[f][0] = __float_as_uint(As[(rbm    ) * 36 + kk + t    ]);
            af[f][1] = __float_as_uint(As[(rbm + 8) * 36 + kk + t    ]);
            af[f][2] = __float_as_uint(As[(rbm    ) * 36 + kk + t + 4]);
            af[f][3] = __float_as_uint(As[(rbm + 8) * 36 + kk + t + 4]);
        }
        #pragma unroll
        for (int j = 0; j < 4; j++) {
            int nb = wn * 32 + j * 8 + g;
            uint32_t b0 = __float_as_uint(Bs[(kk + t    ) * 68 + nb]);
            uint32_t b1 = __float_as_uint(Bs[(kk + t + 4) * 68 + nb]);
            mma8(cfr[0][j], af[0][0], af[0][1], af[0][2], af[0][3], b0, b1);
            mma8(cfr[1][j], af[1][0], af[1][1], af[1][2], af[1][3], b0, b1);
        }
    }
}

// ---------------------------------------------------------------------------
// Kernel 0: tf32 rounding of an fp32 tensor (grid-stride, float4).
// ---------------------------------------------------------------------------
__global__ __launch_bounds__(256) void cvt_tf32_kernel(
    const float4* __restrict__ in, float4* __restrict__ out, int n4)
{
    int i = blockIdx.x * blockDim.x + threadIdx.x;
    int stride = gridDim.x * blockDim.x;
    for (; i < n4; i += stride) {
        float4 v = in[i];
        v.x = f2tff(v.x); v.y = f2tff(v.y); v.z = f2tff(v.z); v.w = f2tff(v.w);
        out[i] = v;
    }
}

// ---------------------------------------------------------------------------
// Kernel 1: fused QKV projection + RoPE (tf32), cp.async 2-stage pipeline,
// 3 blocks/SM. Block tile 128x64, BK=32, 8 warps (4m x 2n), warp tile 32x32.
// Operands pre-rounded to tf32 in g_Xt / g_W{q,k,v}t.
// ---------------------------------------------------------------------------
__global__ __launch_bounds__(256, 3) void qkv_rope_kernel(
    const float* __restrict__ cs,
    const float* __restrict__ sn)
{
    const int n0g = blockIdx.x * 64;
    const int m0  = blockIdx.y * 128;

    const float* Bmat;
    int ldb, ncol0, kind;                  // 0=Q, 1=K, 2=V
    if (n0g < 1024)       { Bmat = g_Wqt; ldb = 1024; ncol0 = n0g;        kind = 0; }
    else if (n0g < 1280)  { Bmat = g_Wkt; ldb = 256;  ncol0 = n0g - 1024; kind = 1; }
    else                  { Bmat = g_Wvt; ldb = 256;  ncol0 = n0g - 1280; kind = 2; }

    extern __shared__ float dyn[];
    float* Cs = dyn;                       // [128][68] epilogue overlap (stage 0)

    const int tid  = threadIdx.x;
    const int lane = tid & 31, warp = tid >> 5;
    const int wm = warp & 3, wn = warp >> 2;
    const int g = lane >> 2, t = lane & 3;

    const int arA[4] = { (tid + 0) >> 3, (tid + 256) >> 3, (tid + 512) >> 3, (tid + 768) >> 3 };
    const int acA    = (tid & 7) * 4;
    const int brB[2] = { tid >> 4, (tid + 256) >> 4 };
    const int bcB    = (tid & 15) * 4;

    float cfr[2][4][4] = {};

    // Prologue: stage 0 via cp.async
    {
        float* As = dyn;  float* Bs = dyn + 128 * 36;
        #pragma unroll
        for (int it = 0; it < 4; it++)
            cp16(&As[arA[it] * 36 + acA], &g_Xt[(m0 + arA[it]) * 1024 + acA]);
        #pragma unroll
        for (int it = 0; it < 2; it++)
            cp16(&Bs[brB[it] * 68 + bcB], &Bmat[brB[it] * ldb + ncol0 + bcB]);
        asm volatile("cp.async.commit_group;");
    }

    for (int k0 = 0; k0 < 1024; k0 += 32) {
        const int cur = (k0 >> 5) & 1;
        float* As  = dyn + (cur ? GSTAGE : 0);
        float* Bs  = As + 128 * 36;
        const bool has_next = (k0 + 32) < 1024;

        __syncthreads();   // all warps done with MMA(k-1) -> alt buffer free
        if (has_next) {
            const int kn = k0 + 32;
            float* Asn = dyn + (cur ? 0 : GSTAGE);
            float* Bsn = Asn + 128 * 36;
            #pragma unroll
            for (int it = 0; it < 4; it++)
                cp16(&Asn[arA[it] * 36 + acA], &g_Xt[(m0 + arA[it]) * 1024 + kn + acA]);
            #pragma unroll
            for (int it = 0; it < 2; it++)
                cp16(&Bsn[brB[it] * 68 + bcB], &Bmat[(kn + brB[it]) * ldb + ncol0 + bcB]);
            asm volatile("cp.async.commit_group;");
            asm volatile("cp.async.wait_group 1;" ::: "memory");
        } else {
            asm volatile("cp.async.wait_group 0;" ::: "memory");
        }
        __syncthreads();   // stage k visible to all warps

        mma_phase(As, Bs, wm, wn, g, t, cfr);
    }
    __syncthreads();       // before overwriting stage region with Cs

    // Fragments -> Cs for RoPE exchange
    #pragma unroll
    for (int f = 0; f < 2; f++) {
        int rbm = wm * 32 + f * 16 + g;
        #pragma unroll
        for (int j = 0; j < 4; j++) {
            int col = wn * 32 + j * 8 + 2 * t;
            Cs[(rbm    ) * 68 + col    ] = cfr[f][j][0];
            Cs[(rbm    ) * 68 + col + 1] = cfr[f][j][1];
            Cs[(rbm + 8) * 68 + col    ] = cfr[f][j][2];
            Cs[(rbm + 8) * 68 + col + 1] = cfr[f][j][3];
        }
    }
    __syncthreads();

    const int head_local = (kind == 0) ? (n0g >> 6) : (ncol0 >> 6);
    const int r0e = (tid >> 4) * 8;
    const int c0e = (tid & 15) * 4;
    #pragma unroll
    for (int i = 0; i < 8; i++) {
        const int r = r0e + i;
        const int m = m0 + r;
        #pragma unroll
        for (int j = 0; j < 4; j++) {
            const int d = c0e + j;
            float val = Cs[r * 68 + d];
            float outv;
            if (kind == 2) {
                outv = val;
            } else {
                float partner = (d < 32) ? -Cs[r * 68 + d + 32] : Cs[r * 68 + d - 32];
                outv = val * cs[m * HD + d] + partner * sn[m * HD + d];
                if (kind == 0) outv *= SCALING;
            }
            outv = f2tff(outv);
            const int dst = head_local * SEQ * HD + m * HD + d;
            if (kind == 0)      g_Q[dst] = outv;
            else if (kind == 1) g_K[dst] = outv;
            else                g_V[dst] = outv;
        }
    }
}

// ---------------------------------------------------------------------------
// Kernel 2: flash attention (tf32) — warp-exclusive rows, register softmax,
// cp.async 2-stage KV pipeline, one block barrier per KV tile.
// (unchanged from round 8 except output staged tf32-rounded for oproj)
// ---------------------------------------------------------------------------
__global__ __launch_bounds__(256, 2) void flash_kernel()
{
    const int q0  = blockIdx.x * 128;
    const int h   = blockIdx.y;
    const int kvh = h >> 2;

    extern __shared__ float smf[];
    float* QSP = smf;                              // [128][68]
    float* Kst = smf + 128 * 68;                   // [2][64][68]
    float* Vst = smf + 128 * 68 + 2 * 64 * 68;     // [2][64][72]

    const int tid  = threadIdx.x;
    const int lane = tid & 31, warp = tid >> 5;
    const int g = lane >> 2, t = lane & 3;
    const int rw = warp * 16;

    const float* Qg = g_Q + h * SEQ * HD + q0 * HD;
    const float* Kg = g_K + kvh * SEQ * HD;
    const float* Vg = g_V + kvh * SEQ * HD;

    const int kvR[4] = { (tid + 0) >> 4, (tid + 256) >> 4, (tid + 512) >> 4, (tid + 768) >> 4 };
    const int kvC    = (tid & 15) * 4;

    #pragma unroll
    for (int it = 0; it < 8; it++) {
        int id = tid + it * 256;
        int r = id >> 4, c4 = (id & 15) * 4;
        *(float4*)&QSP[r * 68 + c4] = *(const float4*)&Qg[r * 64 + c4];
    }
    __syncthreads();
    uint32_t qfr[8][4];
    #pragma unroll
    for (int ks = 0; ks < 8; ks++) {
        const int kk = ks * 8;
        qfr[ks][0] = __float_as_uint(QSP[(rw + g    ) * 68 + kk + t    ]);
        qfr[ks][1] = __float_as_uint(QSP[(rw + g + 8) * 68 + kk + t    ]);
        qfr[ks][2] = __float_as_uint(QSP[(rw + g    ) * 68 + kk + t + 4]);
        qfr[ks][3] = __float_as_uint(QSP[(rw + g + 8) * 68 + kk + t + 4]);
    }

    {
        #pragma unroll
        for (int it = 0; it < 4; it++) {
            cp16(&Kst[kvR[it] * 68 + kvC], &Kg[kvR[it] * 64 + kvC]);
            cp16(&Vst[kvR[it] * 72 + kvC], &Vg[kvR[it] * 64 + kvC]);
        }
        asm volatile("cp.async.commit_group;");
    }

    float m1 = -INFINITY, m2 = -INFINITY, l1 = 0.0f, l2 = 0.0f;
    float ofr[8][4] = {};

    for (int kt = 0; kt < 32; kt++) {
        asm volatile("cp.async.wait_group 0;" ::: "memory");
        __syncthreads();

        if (kt + 1 < 32) {
            const int sl = (kt + 1) & 1;
            const float* Kp = Kg + (kt + 1) * 64 * 64;
            const float* Vp = Vg + (kt + 1) * 64 * 64;
            float* Kn = Kst + sl * 64 * 68;
            float* Vn = Vst + sl * 64 * 72;
            #pragma unroll
            for (int it = 0; it < 4; it++) {
                cp16(&Kn[kvR[it] * 68 + kvC], &Kp[kvR[it] * 64 + kvC]);
                cp16(&Vn[kvR[it] * 72 + kvC], &Vp[kvR[it] * 64 + kvC]);
            }
            asm volatile("cp.async.commit_group;");
        }

        const float* Ks = Kst + (kt & 1) * 64 * 68;
        const float* Vs = Vst + (kt & 1) * 64 * 72;

        float sfr[8][4] = {};
        #pragma unroll
        for (int ks = 0; ks < 8; ks++) {
            const int kk = ks * 8;
            #pragma unroll
            for (int j = 0; j < 8; j++) {
                int nb = j * 8 + g;
                uint32_t b0 = __float_as_uint(Ks[nb * 68 + kk + t    ]);
                uint32_t b1 = __float_as_uint(Ks[nb * 68 + kk + t + 4]);
                mma8(sfr[j], qfr[ks][0], qfr[ks][1], qfr[ks][2], qfr[ks][3], b0, b1);
            }
        }

        float mloc1 = -INFINITY, mloc2 = -INFINITY;
        #pragma unroll
        for (int j = 0; j < 8; j++) {
            mloc1 = fmaxf(mloc1, fmaxf(sfr[j][0], sfr[j][1]));
            mloc2 = fmaxf(mloc2, fmaxf(sfr[j][2], sfr[j][3]));
        }
        mloc1 = fmaxf(mloc1, __shfl_xor_sync(0xffffffffu, mloc1, 1));
        mloc1 = fmaxf(mloc1, __shfl_xor_sync(0xffffffffu, mloc1, 2));
        mloc2 = fmaxf(mloc2, __shfl_xor_sync(0xffffffffu, mloc2, 1));
        mloc2 = fmaxf(mloc2, __shfl_xor_sync(0xffffffffu, mloc2, 2));
        float mnew1 = fmaxf(m1, mloc1);
        float mnew2 = fmaxf(m2, mloc2);
        float sc1 = __expf(m1 - mnew1);
        float sc2 = __expf(m2 - mnew2);
        float ss1 = 0.0f, ss2 = 0.0f;
        #pragma unroll
        for (int j = 0; j < 8; j++) {
            sfr[j][0] = __expf(sfr[j][0] - mnew1); ss1 += sfr[j][0];
            sfr[j][1] = __expf(sfr[j][1] - mnew1); ss1 += sfr[j][1];
            sfr[j][2] = __expf(sfr[j][2] - mnew2); ss2 += sfr[j][2];
            sfr[j][3] = __expf(sfr[j][3] - mnew2); ss2 += sfr[j][3];
        }
        ss1 += __shfl_xor_sync(0xffffffffu, ss1, 1);
        ss1 += __shfl_xor_sync(0xffffffffu, ss1, 2);
        ss2 += __shfl_xor_sync(0xffffffffu, ss2, 1);
        ss2 += __shfl_xor_sync(0xffffffffu, ss2, 2);
        l1 = l1 * sc1 + ss1;  m1 = mnew1;
        l2 = l2 * sc2 + ss2;  m2 = mnew2;

        #pragma unroll
        for (int j = 0; j < 8; j++) {
            ofr[j][0] *= sc1; ofr[j][1] *= sc1;
            ofr[j][2] *= sc2; ofr[j][3] *= sc2;
        }

        #pragma unroll
        for (int j = 0; j < 8; j++) {
            int col = j * 8 + 2 * t;
            QSP[(rw + g    ) * 68 + col    ] = f2tff(sfr[j][0]);
            QSP[(rw + g    ) * 68 + col + 1] = f2tff(sfr[j][1]);
            QSP[(rw + g + 8) * 68 + col    ] = f2tff(sfr[j][2]);
            QSP[(rw + g + 8) * 68 + col + 1] = f2tff(sfr[j][3]);
        }
        __syncwarp();

        #pragma unroll
        for (int ks = 0; ks < 8; ks++) {
            const int kk = ks * 8;
            uint32_t a0 = __float_as_uint(QSP[(rw + g    ) * 68 + kk + t    ]);
            uint32_t a1 = __float_as_uint(QSP[(rw + g + 8) * 68 + kk + t    ]);
            uint32_t a2 = __float_as_uint(QSP[(rw + g    ) * 68 + kk + t + 4]);
            uint32_t a3 = __float_as_uint(QSP[(rw + g + 8) * 68 + kk + t + 4]);
            #pragma unroll
            for (int j = 0; j < 8; j++) {
                int nb = j * 8 + g;
                uint32_t b0 = __float_as_uint(Vs[(kk + t    ) * 72 + nb]);
                uint32_t b1 = __float_as_uint(Vs[(kk + t + 4) * 72 + nb]);
                mma8(ofr[j], a0, a1, a2, a3, b0, b1);
            }
        }
    }

    // Normalize + tf32-round into QSP, then coalesced store (AO feeds tf32 GEMM).
    float inv1 = 1.0f / l1;
    float inv2 = 1.0f / l2;
    #pragma unroll
    for (int j = 0; j < 8; j++) {
        int col = j * 8 + 2 * t;
        QSP[(rw + g    ) * 68 + col    ] = f2tff(ofr[j][0] * inv1);
        QSP[(rw + g    ) * 68 + col + 1] = f2tff(ofr[j][1] * inv1);
        QSP[(rw + g + 8) * 68 + col    ] = f2tff(ofr[j][2] * inv2);
        QSP[(rw + g + 8) * 68 + col + 1] = f2tff(ofr[j][3] * inv2);
    }
    __syncthreads();
    #pragma unroll
    for (int it = 0; it < 8; it++) {
        int id = tid + it * 256;
        int r = id >> 4, c4 = (id & 15) * 4;
        *(float4*)&g_AO[(q0 + r) * 1024 + h * 64 + c4] = *(const float4*)&QSP[r * 68 + c4];
    }
}

// ---------------------------------------------------------------------------
// Kernel 3: output projection (tf32), cp.async 2-stage pipeline, 3 blocks/SM.
// Reads g_AO (tf32-rounded by flash) and g_Wot.
// ---------------------------------------------------------------------------
__global__ __launch_bounds__(256, 3) void oproj_kernel(float* __restrict__ out)
{
    const int n0 = blockIdx.x * 64;
    const int m0 = blockIdx.y * 128;

    extern __shared__ float dyn[];
    float* Cs = dyn;

    const int tid  = threadIdx.x;
    const int lane = tid & 31, warp = tid >> 5;
    const int wm = warp & 3, wn = warp >> 2;
    const int g = lane >> 2, t = lane & 3;

    const int arA[4] = { (tid + 0) >> 3, (tid + 256) >> 3, (tid + 512) >> 3, (tid + 768) >> 3 };
    const int acA    = (tid & 7) * 4;
    const int brB[2] = { tid >> 4, (tid + 256) >> 4 };
    const int bcB    = (tid & 15) * 4;

    float cfr[2][4][4] = {};

    {
        float* As = dyn;  float* Bs = dyn + 128 * 36;
        #pragma unroll
        for (int it = 0; it < 4; it++)
            cp16(&As[arA[it] * 36 + acA], &g_AO[(m0 + arA[it]) * 1024 + acA]);
        #pragma unroll
        for (int it = 0; it < 2; it++)
            cp16(&Bs[brB[it] * 68 + bcB], &g_Wot[brB[it] * 1024 + n0 + bcB]);
        asm volatile("cp.async.commit_group;");
    }

    for (int k0 = 0; k0 < 1024; k0 += 32) {
        const int cur = (k0 >> 5) & 1;
        float* As  = dyn + (cur ? GSTAGE : 0);
        float* Bs  = As + 128 * 36;
        const bool has_next = (k0 + 32) < 1024;

        __syncthreads();
        if (has_next) {
            const int kn = k0 + 32;
            float* Asn = dyn + (cur ? 0 : GSTAGE);
            float* Bsn = Asn + 128 * 36;
            #pragma unroll
            for (int it = 0; it < 4; it++)
                cp16(&Asn[arA[it] * 36 + acA], &g_AO[(m0 + arA[it]) * 1024 + kn + acA]);
            #pragma unroll
            for (int it = 0; it < 2; it++)
                cp16(&Bsn[brB[it] * 68 + bcB], &g_Wot[(kn + brB[it]) * 1024 + n0 + bcB]);
            asm volatile("cp.async.commit_group;");
            asm volatile("cp.async.wait_group 1;" ::: "memory");
        } else {
            asm volatile("cp.async.wait_group 0;" ::: "memory");
        }
        __syncthreads();

        mma_phase(As, Bs, wm, wn, g, t, cfr);
    }
    __syncthreads();

    #pragma unroll
    for (int f = 0; f < 2; f++) {
        int rbm = wm * 32 + f * 16 + g;
        #pragma unroll
        for (int j = 0; j < 4; j++) {
            int col = wn * 32 + j * 8 + 2 * t;
            Cs[(rbm    ) * 68 + col    ] = cfr[f][j][0];
            Cs[(rbm    ) * 68 + col + 1] = cfr[f][j][1];
            Cs[(rbm + 8) * 68 + col    ] = cfr[f][j][2];
            Cs[(rbm + 8) * 68 + col + 1] = cfr[f][j][3];
        }
    }
    __syncthreads();
    #pragma unroll
    for (int it = 0; it < 8; it++) {
        int id = tid + it * 256;
        int r = id >> 4, c4 = (id & 15) * 4;
        *(float4*)&out[(m0 + r) * 1024 + n0 + c4] = *(const float4*)&Cs[r * 68 + c4];
    }
}

// ---------------------------------------------------------------------------
// Launch.
// ---------------------------------------------------------------------------
extern "C" void kernel_launch(void* const* d_in, const int* in_sizes, int n_in,
                              void* d_out, int out_size)
{
    const float* X  = (const float*)d_in[0];
    const float* cs = (const float*)d_in[1];
    const float* sn = (const float*)d_in[2];
    // d_in[3] = attention_mask (all ones) — unused
    const float* Wq = (const float*)d_in[4];
    const float* Wk = (const float*)d_in[5];
    const float* Wv = (const float*)d_in[6];
    const float* Wo = (const float*)d_in[7];
    float* out = (float*)d_out;

    // Resolve device-global addresses (host side).
    float *pXt, *pWqt, *pWkt, *pWvt, *pWot;
    cudaGetSymbolAddress((void**)&pXt,  g_Xt);
    cudaGetSymbolAddress((void**)&pWqt, g_Wqt);
    cudaGetSymbolAddress((void**)&pWkt, g_Wkt);
    cudaGetSymbolAddress((void**)&pWvt, g_Wvt);
    cudaGetSymbolAddress((void**)&pWot, g_Wot);

    // tf32 pre-rounding of inputs
    cvt_tf32_kernel<<<512, 256>>>((const float4*)X,  (float4*)pXt,  SEQ * HID / 4);
    cvt_tf32_kernel<<<512, 256>>>((const float4*)Wq, (float4*)pWqt, HID * 1024 / 4);
    cvt_tf32_kernel<<<256, 256>>>((const float4*)Wk, (float4*)pWkt, HID * 256 / 4);
    cvt_tf32_kernel<<<256, 256>>>((const float4*)Wv, (float4*)pWvt, HID * 256 / 4);
    cvt_tf32_kernel<<<512, 256>>>((const float4*)Wo, (float4*)pWot, 1024 * HID / 4);

    const size_t smem_gemm = 2 * GSTAGE * sizeof(float);   // 54272 B
    cudaFuncSetAttribute(qkv_rope_kernel,
                         cudaFuncAttributeMaxDynamicSharedMemorySize, (int)smem_gemm);
    cudaFuncSetAttribute(oproj_kernel,
                         cudaFuncAttributeMaxDynamicSharedMemorySize, (int)smem_gemm);

    qkv_rope_kernel<<<dim3(24, 16), 256, smem_gemm>>>(cs, sn);

    // QSP[128][68] + K[2][64][68] + V[2][64][72]
    const size_t smem_flash = (128 * 68 + 2 * 64 * 68 + 2 * 64 * 72) * sizeof(float); // 106496 B
    cudaFuncSetAttribute(flash_kernel,
                         cudaFuncAttributeMaxDynamicSharedMemorySize, (int)smem_flash);
    flash_kernel<<<dim3(16, 16), 256, smem_flash>>>();

    oproj_kernel<<<dim3(16, 16), 256, smem_gemm>>>(out);
}

// round 10
// speedup vs baseline: 4.0748x; 1.0243x over previous
#include <cuda_runtime.h>
#include <math.h>
#include <stdint.h>

#define SEQ 2048
#define HID 1024
#define NH 16
#define NKV 4
#define HD 64
#define SCALING 0.125f

// GEMM double-buffer stage size (floats): As[128][36] + Bs[32][68]
#define GSTAGE (128 * 36 + 32 * 68)   // 6784 floats

// Scratch (device globals; 16B-aligned: targets of float4 / cp.async access)
__device__ __align__(16) float g_Q[NH * SEQ * HD];
__device__ __align__(16) float g_K[NKV * SEQ * HD];
__device__ __align__(16) float g_V[NKV * SEQ * HD];
__device__ __align__(16) float g_AO[SEQ * HID];
// tf32-rounded copies of inputs
__device__ __align__(16) float g_Xt[SEQ * HID];
__device__ __align__(16) float g_Wqt[HID * 1024];
__device__ __align__(16) float g_Wkt[HID * 256];
__device__ __align__(16) float g_Wvt[HID * 256];
__device__ __align__(16) float g_Wot[1024 * HID];

// ---------------------------------------------------------------------------
// Helpers
// ---------------------------------------------------------------------------
__device__ __forceinline__ float f2tff(float x) {
    uint32_t r;
    asm("cvt.rna.tf32.f32 %0, %1;" : "=r"(r) : "f"(x));
    return __uint_as_float(r);
}

__device__ __forceinline__ void mma8(float c[4],
                                     uint32_t a0, uint32_t a1, uint32_t a2, uint32_t a3,
                                     uint32_t b0, uint32_t b1) {
    asm volatile(
        "mma.sync.aligned.m16n8k8.row.col.f32.tf32.tf32.f32 "
        "{%0,%1,%2,%3}, {%4,%5,%6,%7}, {%8,%9}, {%0,%1,%2,%3};"
        : "+f"(c[0]), "+f"(c[1]), "+f"(c[2]), "+f"(c[3])
        : "r"(a0), "r"(a1), "r"(a2), "r"(a3), "r"(b0), "r"(b1));
}

__device__ __forceinline__ void cp16(float* smem_dst, const float* gsrc) {
    uint32_t s = (uint32_t)__cvta_generic_to_shared(smem_dst);
    asm volatile("cp.async.ca.shared.global [%0], [%1], 16;" :: "r"(s), "l"(gsrc));
}

__device__ __forceinline__ void mma_phase(const float* As, const float* Bs,
                                          int wm, int wn, int g, int t,
                                          float cfr[2][4][4]) {
    #pragma unroll
    for (int ks = 0; ks < 4; ks++) {
        const int kk = ks * 8;
        uint32_t af[2][4];
        #pragma unroll
        for (int f = 0; f < 2; f++) {
            int rbm = wm * 32 + f * 16 + g;
            af[f][0] = __float_as_uint(As[(rbm    ) * 36 + kk + t    ]);
            af[f][1] = __float_as_uint(As[(rbm + 8) * 36 + kk + t    ]);
            af[f][2] = __float_as_uint(As[(rbm    ) * 36 + kk + t + 4]);
            af[f][3] = __float_as_uint(As[(rbm + 8) * 36 + kk + t + 4]);
        }
        #pragma unroll
        for (int j = 0; j < 4; j++) {
            int nb = wn * 32 + j * 8 + g;
            uint32_t b0 = __float_as_uint(Bs[(kk + t    ) * 68 + nb]);
            uint32_t b1 = __float_as_uint(Bs[(kk + t + 4) * 68 + nb]);
            mma8(cfr[0][j], af[0][0], af[0][1], af[0][2], af[0][3], b0, b1);
            mma8(cfr[1][j], af[1][0], af[1][1], af[1][2], af[1][3], b0, b1);
        }
    }
}

// ---------------------------------------------------------------------------
// Kernel 0: merged tf32 rounding of ALL input tensors (one launch).
// Segment boundaries in float4 units (compile-time).
// ---------------------------------------------------------------------------
#define N4_X   (SEQ * HID / 4)                  // 524288
#define N4_WQ  (HID * 1024 / 4)                 // 262144
#define N4_WK  (HID * 256 / 4)                  // 65536
#define N4_WV  (HID * 256 / 4)                  // 65536
#define N4_WO  (1024 * HID / 4)                 // 262144
#define B0 N4_X
#define B1 (B0 + N4_WQ)
#define B2 (B1 + N4_WK)
#define B3 (B2 + N4_WV)
#define B4 (B3 + N4_WO)                          // 1179648 total

__global__ __launch_bounds__(256) void cvt_all_kernel(
    const float4* __restrict__ X,  const float4* __restrict__ Wq,
    const float4* __restrict__ Wk, const float4* __restrict__ Wv,
    const float4* __restrict__ Wo)
{
    int i = blockIdx.x * blockDim.x + threadIdx.x;
    const int stride = gridDim.x * blockDim.x;
    for (; i < B4; i += stride) {
        const float4* src; float4* dst; int off;
        if (i < B0)      { src = X;  dst = (float4*)g_Xt;  off = i; }
        else if (i < B1) { src = Wq; dst = (float4*)g_Wqt; off = i - B0; }
        else if (i < B2) { src = Wk; dst = (float4*)g_Wkt; off = i - B1; }
        else if (i < B3) { src = Wv; dst = (float4*)g_Wvt; off = i - B2; }
        else             { src = Wo; dst = (float4*)g_Wot; off = i - B3; }
        float4 v = src[off];
        v.x = f2tff(v.x); v.y = f2tff(v.y); v.z = f2tff(v.z); v.w = f2tff(v.w);
        dst[off] = v;
    }
}

// ---------------------------------------------------------------------------
// Kernel 1: fused QKV projection + RoPE (tf32), cp.async 2-stage, 3 blocks/SM.
// ---------------------------------------------------------------------------
__global__ __launch_bounds__(256, 3) void qkv_rope_kernel(
    const float* __restrict__ cs,
    const float* __restrict__ sn)
{
    const int n0g = blockIdx.x * 64;
    const int m0  = blockIdx.y * 128;

    const float* Bmat;
    int ldb, ncol0, kind;                  // 0=Q, 1=K, 2=V
    if (n0g < 1024)       { Bmat = g_Wqt; ldb = 1024; ncol0 = n0g;        kind = 0; }
    else if (n0g < 1280)  { Bmat = g_Wkt; ldb = 256;  ncol0 = n0g - 1024; kind = 1; }
    else                  { Bmat = g_Wvt; ldb = 256;  ncol0 = n0g - 1280; kind = 2; }

    extern __shared__ float dyn[];
    float* Cs = dyn;

    const int tid  = threadIdx.x;
    const int lane = tid & 31, warp = tid >> 5;
    const int wm = warp & 3, wn = warp >> 2;
    const int g = lane >> 2, t = lane & 3;

    const int arA[4] = { (tid + 0) >> 3, (tid + 256) >> 3, (tid + 512) >> 3, (tid + 768) >> 3 };
    const int acA    = (tid & 7) * 4;
    const int brB[2] = { tid >> 4, (tid + 256) >> 4 };
    const int bcB    = (tid & 15) * 4;

    float cfr[2][4][4] = {};

    {
        float* As = dyn;  float* Bs = dyn + 128 * 36;
        #pragma unroll
        for (int it = 0; it < 4; it++)
            cp16(&As[arA[it] * 36 + acA], &g_Xt[(m0 + arA[it]) * 1024 + acA]);
        #pragma unroll
        for (int it = 0; it < 2; it++)
            cp16(&Bs[brB[it] * 68 + bcB], &Bmat[brB[it] * ldb + ncol0 + bcB]);
        asm volatile("cp.async.commit_group;");
    }

    #pragma unroll 2
    for (int k0 = 0; k0 < 1024; k0 += 32) {
        const int cur = (k0 >> 5) & 1;
        float* As  = dyn + (cur ? GSTAGE : 0);
        float* Bs  = As + 128 * 36;
        const bool has_next = (k0 + 32) < 1024;

        __syncthreads();
        if (has_next) {
            const int kn = k0 + 32;
            float* Asn = dyn + (cur ? 0 : GSTAGE);
            float* Bsn = Asn + 128 * 36;
            #pragma unroll
            for (int it = 0; it < 4; it++)
                cp16(&Asn[arA[it] * 36 + acA], &g_Xt[(m0 + arA[it]) * 1024 + kn + acA]);
            #pragma unroll
            for (int it = 0; it < 2; it++)
                cp16(&Bsn[brB[it] * 68 + bcB], &Bmat[(kn + brB[it]) * ldb + ncol0 + bcB]);
            asm volatile("cp.async.commit_group;");
            asm volatile("cp.async.wait_group 1;" ::: "memory");
        } else {
            asm volatile("cp.async.wait_group 0;" ::: "memory");
        }
        __syncthreads();

        mma_phase(As, Bs, wm, wn, g, t, cfr);
    }
    __syncthreads();

    #pragma unroll
    for (int f = 0; f < 2; f++) {
        int rbm = wm * 32 + f * 16 + g;
        #pragma unroll
        for (int j = 0; j < 4; j++) {
            int col = wn * 32 + j * 8 + 2 * t;
            Cs[(rbm    ) * 68 + col    ] = cfr[f][j][0];
            Cs[(rbm    ) * 68 + col + 1] = cfr[f][j][1];
            Cs[(rbm + 8) * 68 + col    ] = cfr[f][j][2];
            Cs[(rbm + 8) * 68 + col + 1] = cfr[f][j][3];
        }
    }
    __syncthreads();

    const int head_local = (kind == 0) ? (n0g >> 6) : (ncol0 >> 6);
    const int r0e = (tid >> 4) * 8;
    const int c0e = (tid & 15) * 4;
    #pragma unroll
    for (int i = 0; i < 8; i++) {
        const int r = r0e + i;
        const int m = m0 + r;
        #pragma unroll
        for (int j = 0; j < 4; j++) {
            const int d = c0e + j;
            float val = Cs[r * 68 + d];
            float outv;
            if (kind == 2) {
                outv = val;
            } else {
                float partner = (d < 32) ? -Cs[r * 68 + d + 32] : Cs[r * 68 + d - 32];
                outv = val * cs[m * HD + d] + partner * sn[m * HD + d];
                if (kind == 0) outv *= SCALING;
            }
            outv = f2tff(outv);
            const int dst = head_local * SEQ * HD + m * HD + d;
            if (kind == 0)      g_Q[dst] = outv;
            else if (kind == 1) g_K[dst] = outv;
            else                g_V[dst] = outv;
        }
    }
}

// ---------------------------------------------------------------------------
// Flash per-KV-tile body: compile-time stage pointers (manual unroll-2 host).
// ---------------------------------------------------------------------------
__device__ __forceinline__ void flash_tile(
    const float* Ks, const float* Vs,          // current stage (smem)
    float* Kn, float* Vn, bool prefetch,       // next stage (smem) + gmem srcs
    const float* Kgn, const float* Vgn,
    const int* kvR, int kvC,
    const uint32_t (*qfr)[4], float (*ofr)[4],
    float& m1, float& m2, float& l1, float& l2,
    float* QSP, int rw, int g, int t)
{
    asm volatile("cp.async.wait_group 0;" ::: "memory");
    __syncthreads();   // tile data ready; all warps done with the other stage

    if (prefetch) {
        #pragma unroll
        for (int it = 0; it < 4; it++) {
            cp16(&Kn[kvR[it] * 68 + kvC], &Kgn[kvR[it] * 64 + kvC]);
            cp16(&Vn[kvR[it] * 72 + kvC], &Vgn[kvR[it] * 64 + kvC]);
        }
        asm volatile("cp.async.commit_group;");
    }

    // S = Q @ K^T
    float sfr[8][4] = {};
    #pragma unroll
    for (int ks = 0; ks < 8; ks++) {
        const int kk = ks * 8;
        #pragma unroll
        for (int j = 0; j < 8; j++) {
            int nb = j * 8 + g;
            uint32_t b0 = __float_as_uint(Ks[nb * 68 + kk + t    ]);
            uint32_t b1 = __float_as_uint(Ks[nb * 68 + kk + t + 4]);
            mma8(sfr[j], qfr[ks][0], qfr[ks][1], qfr[ks][2], qfr[ks][3], b0, b1);
        }
    }

    // Register online softmax (rows rw+g, rw+g+8; quad reduction)
    float mloc1 = -INFINITY, mloc2 = -INFINITY;
    #pragma unroll
    for (int j = 0; j < 8; j++) {
        mloc1 = fmaxf(mloc1, fmaxf(sfr[j][0], sfr[j][1]));
        mloc2 = fmaxf(mloc2, fmaxf(sfr[j][2], sfr[j][3]));
    }
    mloc1 = fmaxf(mloc1, __shfl_xor_sync(0xffffffffu, mloc1, 1));
    mloc1 = fmaxf(mloc1, __shfl_xor_sync(0xffffffffu, mloc1, 2));
    mloc2 = fmaxf(mloc2, __shfl_xor_sync(0xffffffffu, mloc2, 1));
    mloc2 = fmaxf(mloc2, __shfl_xor_sync(0xffffffffu, mloc2, 2));
    float mnew1 = fmaxf(m1, mloc1);
    float mnew2 = fmaxf(m2, mloc2);
    float sc1 = __expf(m1 - mnew1);   // first tile: exp(-inf)=0
    float sc2 = __expf(m2 - mnew2);
    float ss1 = 0.0f, ss2 = 0.0f;
    #pragma unroll
    for (int j = 0; j < 8; j++) {
        sfr[j][0] = __expf(sfr[j][0] - mnew1); ss1 += sfr[j][0];
        sfr[j][1] = __expf(sfr[j][1] - mnew1); ss1 += sfr[j][1];
        sfr[j][2] = __expf(sfr[j][2] - mnew2); ss2 += sfr[j][2];
        sfr[j][3] = __expf(sfr[j][3] - mnew2); ss2 += sfr[j][3];
    }
    ss1 += __shfl_xor_sync(0xffffffffu, ss1, 1);
    ss1 += __shfl_xor_sync(0xffffffffu, ss1, 2);
    ss2 += __shfl_xor_sync(0xffffffffu, ss2, 1);
    ss2 += __shfl_xor_sync(0xffffffffu, ss2, 2);
    l1 = l1 * sc1 + ss1;  m1 = mnew1;
    l2 = l2 * sc2 + ss2;  m2 = mnew2;

    #pragma unroll
    for (int j = 0; j < 8; j++) {
        ofr[j][0] *= sc1; ofr[j][1] *= sc1;
        ofr[j][2] *= sc2; ofr[j][3] *= sc2;
    }

    // P -> QSP (own rows), tf32-rounded
    #pragma unroll
    for (int j = 0; j < 8; j++) {
        int col = j * 8 + 2 * t;
        QSP[(rw + g    ) * 68 + col    ] = f2tff(sfr[j][0]);
        QSP[(rw + g    ) * 68 + col + 1] = f2tff(sfr[j][1]);
        QSP[(rw + g + 8) * 68 + col    ] = f2tff(sfr[j][2]);
        QSP[(rw + g + 8) * 68 + col + 1] = f2tff(sfr[j][3]);
    }
    __syncwarp();

    // O += P @ V
    #pragma unroll
    for (int ks = 0; ks < 8; ks++) {
        const int kk = ks * 8;
        uint32_t a0 = __float_as_uint(QSP[(rw + g    ) * 68 + kk + t    ]);
        uint32_t a1 = __float_as_uint(QSP[(rw + g + 8) * 68 + kk + t    ]);
        uint32_t a2 = __float_as_uint(QSP[(rw + g    ) * 68 + kk + t + 4]);
        uint32_t a3 = __float_as_uint(QSP[(rw + g + 8) * 68 + kk + t + 4]);
        #pragma unroll
        for (int j = 0; j < 8; j++) {
            int nb = j * 8 + g;
            uint32_t b0 = __float_as_uint(Vs[(kk + t    ) * 72 + nb]);
            uint32_t b1 = __float_as_uint(Vs[(kk + t + 4) * 72 + nb]);
            mma8(ofr[j], a0, a1, a2, a3, b0, b1);
        }
    }
}

// ---------------------------------------------------------------------------
// Kernel 2: flash attention (tf32) — warp-exclusive rows, register softmax,
// cp.async 2-stage KV pipeline, manual unroll-2 (static stage pointers).
// ---------------------------------------------------------------------------
__global__ __launch_bounds__(256, 2) void flash_kernel()
{
    const int q0  = blockIdx.x * 128;
    const int h   = blockIdx.y;
    const int kvh = h >> 2;

    extern __shared__ float smf[];
    float* QSP = smf;                              // [128][68]
    float* K0  = smf + 128 * 68;                   // [64][68]
    float* K1  = K0 + 64 * 68;                     // [64][68]
    float* V0  = K1 + 64 * 68;                     // [64][72]
    float* V1  = V0 + 64 * 72;                     // [64][72]

    const int tid  = threadIdx.x;
    const int lane = tid & 31, warp = tid >> 5;
    const int g = lane >> 2, t = lane & 3;
    const int rw = warp * 16;

    const float* Qg = g_Q + h * SEQ * HD + q0 * HD;
    const float* Kg = g_K + kvh * SEQ * HD;
    const float* Vg = g_V + kvh * SEQ * HD;

    const int kvR[4] = { (tid + 0) >> 4, (tid + 256) >> 4, (tid + 512) >> 4, (tid + 768) >> 4 };
    const int kvC    = (tid & 15) * 4;

    #pragma unroll
    for (int it = 0; it < 8; it++) {
        int id = tid + it * 256;
        int r = id >> 4, c4 = (id & 15) * 4;
        *(float4*)&QSP[r * 68 + c4] = *(const float4*)&Qg[r * 64 + c4];
    }
    __syncthreads();
    uint32_t qfr[8][4];
    #pragma unroll
    for (int ks = 0; ks < 8; ks++) {
        const int kk = ks * 8;
        qfr[ks][0] = __float_as_uint(QSP[(rw + g    ) * 68 + kk + t    ]);
        qfr[ks][1] = __float_as_uint(QSP[(rw + g + 8) * 68 + kk + t    ]);
        qfr[ks][2] = __float_as_uint(QSP[(rw + g    ) * 68 + kk + t + 4]);
        qfr[ks][3] = __float_as_uint(QSP[(rw + g + 8) * 68 + kk + t + 4]);
    }

    // Prologue: stage tile 0 into slot 0
    #pragma unroll
    for (int it = 0; it < 4; it++) {
        cp16(&K0[kvR[it] * 68 + kvC], &Kg[kvR[it] * 64 + kvC]);
        cp16(&V0[kvR[it] * 72 + kvC], &Vg[kvR[it] * 64 + kvC]);
    }
    asm volatile("cp.async.commit_group;");

    float m1 = -INFINITY, m2 = -INFINITY, l1 = 0.0f, l2 = 0.0f;
    float ofr[8][4] = {};

    for (int ktp = 0; ktp < 16; ktp++) {
        const int kt0 = 2 * ktp;
        // even tile (slot 0), prefetch odd tile into slot 1
        flash_tile(K0, V0, K1, V1, true,
                   Kg + (kt0 + 1) * 64 * 64, Vg + (kt0 + 1) * 64 * 64,
                   kvR, kvC, qfr, ofr, m1, m2, l1, l2, QSP, rw, g, t);
        // odd tile (slot 1), prefetch next even tile into slot 0
        const bool more = (kt0 + 2) < 32;
        const float* Kgn = Kg + (more ? (kt0 + 2) * 64 * 64 : 0);
        const float* Vgn = Vg + (more ? (kt0 + 2) * 64 * 64 : 0);
        flash_tile(K1, V1, K0, V0, more,
                   Kgn, Vgn, kvR, kvC, qfr, ofr, m1, m2, l1, l2, QSP, rw, g, t);
    }

    // Normalize + tf32-round into QSP, then coalesced store.
    float inv1 = 1.0f / l1;
    float inv2 = 1.0f / l2;
    #pragma unroll
    for (int j = 0; j < 8; j++) {
        int col = j * 8 + 2 * t;
        QSP[(rw + g    ) * 68 + col    ] = f2tff(ofr[j][0] * inv1);
        QSP[(rw + g    ) * 68 + col + 1] = f2tff(ofr[j][1] * inv1);
        QSP[(rw + g + 8) * 68 + col    ] = f2tff(ofr[j][2] * inv2);
        QSP[(rw + g + 8) * 68 + col + 1] = f2tff(ofr[j][3] * inv2);
    }
    __syncthreads();
    #pragma unroll
    for (int it = 0; it < 8; it++) {
        int id = tid + it * 256;
        int r = id >> 4, c4 = (id & 15) * 4;
        *(float4*)&g_AO[(q0 + r) * 1024 + h * 64 + c4] = *(const float4*)&QSP[r * 68 + c4];
    }
}

// ---------------------------------------------------------------------------
// Kernel 3: output projection (tf32), cp.async 2-stage, 3 blocks/SM.
// ---------------------------------------------------------------------------
__global__ __launch_bounds__(256, 3) void oproj_kernel(float* __restrict__ out)
{
    const int n0 = blockIdx.x * 64;
    const int m0 = blockIdx.y * 128;

    extern __shared__ float dyn[];
    float* Cs = dyn;

    const int tid  = threadIdx.x;
    const int lane = tid & 31, warp = tid >> 5;
    const int wm = warp & 3, wn = warp >> 2;
    const int g = lane >> 2, t = lane & 3;

    const int arA[4] = { (tid + 0) >> 3, (tid + 256) >> 3, (tid + 512) >> 3, (tid + 768) >> 3 };
    const int acA    = (tid & 7) * 4;
    const int brB[2] = { tid >> 4, (tid + 256) >> 4 };
    const int bcB    = (tid & 15) * 4;

    float cfr[2][4][4] = {};

    {
        float* As = dyn;  float* Bs = dyn + 128 * 36;
        #pragma unroll
        for (int it = 0; it < 4; it++)
            cp16(&As[arA[it] * 36 + acA], &g_AO[(m0 + arA[it]) * 1024 + acA]);
        #pragma unroll
        for (int it = 0; it < 2; it++)
            cp16(&Bs[brB[it] * 68 + bcB], &g_Wot[brB[it] * 1024 + n0 + bcB]);
        asm volatile("cp.async.commit_group;");
    }

    #pragma unroll 2
    for (int k0 = 0; k0 < 1024; k0 += 32) {
        const int cur = (k0 >> 5) & 1;
        float* As  = dyn + (cur ? GSTAGE : 0);
        float* Bs  = As + 128 * 36;
        const bool has_next = (k0 + 32) < 1024;

        __syncthreads();
        if (has_next) {
            const int kn = k0 + 32;
            float* Asn = dyn + (cur ? 0 : GSTAGE);
            float* Bsn = Asn + 128 * 36;
            #pragma unroll
            for (int it = 0; it < 4; it++)
                cp16(&Asn[arA[it] * 36 + acA], &g_AO[(m0 + arA[it]) * 1024 + kn + acA]);
            #pragma unroll
            for (int it = 0; it < 2; it++)
                cp16(&Bsn[brB[it] * 68 + bcB], &g_Wot[(kn + brB[it]) * 1024 + n0 + bcB]);
            asm volatile("cp.async.commit_group;");
            asm volatile("cp.async.wait_group 1;" ::: "memory");
        } else {
            asm volatile("cp.async.wait_group 0;" ::: "memory");
        }
        __syncthreads();

        mma_phase(As, Bs, wm, wn, g, t, cfr);
    }
    __syncthreads();

    #pragma unroll
    for (int f = 0; f < 2; f++) {
        int rbm = wm * 32 + f * 16 + g;
        #pragma unroll
        for (int j = 0; j < 4; j++) {
            int col = wn * 32 + j * 8 + 2 * t;
            Cs[(rbm    ) * 68 + col    ] = cfr[f][j][0];
            Cs[(rbm    ) * 68 + col + 1] = cfr[f][j][1];
            Cs[(rbm + 8) * 68 + col    ] = cfr[f][j][2];
            Cs[(rbm + 8) * 68 + col + 1] = cfr[f][j][3];
        }
    }
    __syncthreads();
    #pragma unroll
    for (int it = 0; it < 8; it++) {
        int id = tid + it * 256;
        int r = id >> 4, c4 = (id & 15) * 4;
        *(float4*)&out[(m0 + r) * 1024 + n0 + c4] = *(const float4*)&Cs[r * 68 + c4];
    }
}

// ---------------------------------------------------------------------------
// Launch.
// ---------------------------------------------------------------------------
extern "C" void kernel_launch(void* const* d_in, const int* in_sizes, int n_in,
                              void* d_out, int out_size)
{
    const float* X  = (const float*)d_in[0];
    const float* cs = (const float*)d_in[1];
    const float* sn = (const float*)d_in[2];
    // d_in[3] = attention_mask (all ones) — unused
    const float* Wq = (const float*)d_in[4];
    const float* Wk = (const float*)d_in[5];
    const float* Wv = (const float*)d_in[6];
    const float* Wo = (const float*)d_in[7];
    float* out = (float*)d_out;

    // Single merged tf32 pre-rounding pass
    cvt_all_kernel<<<1152, 256>>>((const float4*)X, (const float4*)Wq,
                                  (const float4*)Wk, (const float4*)Wv,
                                  (const float4*)Wo);

    const size_t smem_gemm = 2 * GSTAGE * sizeof(float);   // 54272 B
    cudaFuncSetAttribute(qkv_rope_kernel,
                         cudaFuncAttributeMaxDynamicSharedMemorySize, (int)smem_gemm);
    cudaFuncSetAttribute(oproj_kernel,
                         cudaFuncAttributeMaxDynamicSharedMemorySize, (int)smem_gemm);

    qkv_rope_kernel<<<dim3(24, 16), 256, smem_gemm>>>(cs, sn);

    // QSP[128][68] + K[2][64][68] + V[2][64][72]
    const size_t smem_flash = (128 * 68 + 2 * 64 * 68 + 2 * 64 * 72) * sizeof(float); // 106496 B
    cudaFuncSetAttribute(flash_kernel,
                         cudaFuncAttributeMaxDynamicSharedMemorySize, (int)smem_flash);
    flash_kernel<<<dim3(16, 16), 256, smem_flash>>>();

    oproj_kernel<<<dim3(16, 16), 256, smem_gemm>>>(out);
}

// round 11
// speedup vs baseline: 4.1525x; 1.0191x over previous
#include <cuda_runtime.h>
#include <math.h>
#include <stdint.h>

#define SEQ 2048
#define HID 1024
#define NH 16
#define NKV 4
#define HD 64
#define SCALING 0.125f
#define LOG2E 1.4426950408889634f

// GEMM double-buffer stage size (floats): As[128][36] + Bs[32][68]
#define GSTAGE (128 * 36 + 32 * 68)   // 6784 floats

// Scratch (device globals; 16B-aligned)
__device__ __align__(16) float g_Q[NH * SEQ * HD];   // RoPE'd, scaled by 0.125*log2e, tf32
__device__ __align__(16) float g_K[NKV * SEQ * HD];
__device__ __align__(16) float g_V[NKV * SEQ * HD];
__device__ __align__(16) float g_AO[SEQ * HID];
__device__ __align__(16) float g_Xt[SEQ * HID];
__device__ __align__(16) float g_Wqt[HID * 1024];
__device__ __align__(16) float g_Wkt[HID * 256];
__device__ __align__(16) float g_Wvt[HID * 256];
__device__ __align__(16) float g_Wot[1024 * HID];

// ---------------------------------------------------------------------------
// Helpers
// ---------------------------------------------------------------------------
__device__ __forceinline__ float f2tff(float x) {
    uint32_t r;
    asm("cvt.rna.tf32.f32 %0, %1;" : "=r"(r) : "f"(x));
    return __uint_as_float(r);
}

__device__ __forceinline__ float ex2(float x) {
    float r;
    asm("ex2.approx.f32 %0, %1;" : "=f"(r) : "f"(x));
    return r;
}

__device__ __forceinline__ void mma8(float c[4],
                                     uint32_t a0, uint32_t a1, uint32_t a2, uint32_t a3,
                                     uint32_t b0, uint32_t b1) {
    asm volatile(
        "mma.sync.aligned.m16n8k8.row.col.f32.tf32.tf32.f32 "
        "{%0,%1,%2,%3}, {%4,%5,%6,%7}, {%8,%9}, {%0,%1,%2,%3};"
        : "+f"(c[0]), "+f"(c[1]), "+f"(c[2]), "+f"(c[3])
        : "r"(a0), "r"(a1), "r"(a2), "r"(a3), "r"(b0), "r"(b1));
}

__device__ __forceinline__ void cp16(float* smem_dst, const float* gsrc) {
    uint32_t s = (uint32_t)__cvta_generic_to_shared(smem_dst);
    asm volatile("cp.async.ca.shared.global [%0], [%1], 16;" :: "r"(s), "l"(gsrc));
}

__device__ __forceinline__ void mma_phase(const float* As, const float* Bs,
                                          int wm, int wn, int g, int t,
                                          float cfr[2][4][4]) {
    #pragma unroll
    for (int ks = 0; ks < 4; ks++) {
        const int kk = ks * 8;
        uint32_t af[2][4];
        #pragma unroll
        for (int f = 0; f < 2; f++) {
            int rbm = wm * 32 + f * 16 + g;
            af[f][0] = __float_as_uint(As[(rbm    ) * 36 + kk + t    ]);
            af[f][1] = __float_as_uint(As[(rbm + 8) * 36 + kk + t    ]);
            af[f][2] = __float_as_uint(As[(rbm    ) * 36 + kk + t + 4]);
            af[f][3] = __float_as_uint(As[(rbm + 8) * 36 + kk + t + 4]);
        }
        #pragma unroll
        for (int j = 0; j < 4; j++) {
            int nb = wn * 32 + j * 8 + g;
            uint32_t b0 = __float_as_uint(Bs[(kk + t    ) * 68 + nb]);
            uint32_t b1 = __float_as_uint(Bs[(kk + t + 4) * 68 + nb]);
            mma8(cfr[0][j], af[0][0], af[0][1], af[0][2], af[0][3], b0, b1);
            mma8(cfr[1][j], af[1][0], af[1][1], af[1][2], af[1][3], b0, b1);
        }
    }
}

// ---------------------------------------------------------------------------
// Kernel 0: merged tf32 rounding of ALL inputs. Exact cover: 1 float4/thread.
// ---------------------------------------------------------------------------
#define N4_X   (SEQ * HID / 4)
#define N4_WQ  (HID * 1024 / 4)
#define N4_WK  (HID * 256 / 4)
#define N4_WV  (HID * 256 / 4)
#define N4_WO  (1024 * HID / 4)
#define B0 N4_X
#define B1 (B0 + N4_WQ)
#define B2 (B1 + N4_WK)
#define B3 (B2 + N4_WV)
#define B4 (B3 + N4_WO)                  // 1179648 = 4608 * 256

__global__ __launch_bounds__(256) void cvt_all_kernel(
    const float4* __restrict__ X,  const float4* __restrict__ Wq,
    const float4* __restrict__ Wk, const float4* __restrict__ Wv,
    const float4* __restrict__ Wo)
{
    const int i = blockIdx.x * 256 + threadIdx.x;
    const float4* src; float4* dst; int off;
    if (i < B0)      { src = X;  dst = (float4*)g_Xt;  off = i; }
    else if (i < B1) { src = Wq; dst = (float4*)g_Wqt; off = i - B0; }
    else if (i < B2) { src = Wk; dst = (float4*)g_Wkt; off = i - B1; }
    else if (i < B3) { src = Wv; dst = (float4*)g_Wvt; off = i - B2; }
    else             { src = Wo; dst = (float4*)g_Wot; off = i - B3; }
    float4 v = src[off];
    v.x = f2tff(v.x); v.y = f2tff(v.y); v.z = f2tff(v.z); v.w = f2tff(v.w);
    dst[off] = v;
}

// ---------------------------------------------------------------------------
// Kernel 1: fused QKV projection + RoPE (tf32), cp.async 2-stage, 3 blocks/SM.
// Q pre-scaled by 0.125 * log2(e) (flash softmax runs in exp2 domain).
// ---------------------------------------------------------------------------
__global__ __launch_bounds__(256, 3) void qkv_rope_kernel(
    const float* __restrict__ cs,
    const float* __restrict__ sn)
{
    const int n0g = blockIdx.x * 64;
    const int m0  = blockIdx.y * 128;

    const float* Bmat;
    int ldb, ncol0, kind;                  // 0=Q, 1=K, 2=V
    if (n0g < 1024)       { Bmat = g_Wqt; ldb = 1024; ncol0 = n0g;        kind = 0; }
    else if (n0g < 1280)  { Bmat = g_Wkt; ldb = 256;  ncol0 = n0g - 1024; kind = 1; }
    else                  { Bmat = g_Wvt; ldb = 256;  ncol0 = n0g - 1280; kind = 2; }

    extern __shared__ float dyn[];
    float* Cs = dyn;

    const int tid  = threadIdx.x;
    const int lane = tid & 31, warp = tid >> 5;
    const int wm = warp & 3, wn = warp >> 2;
    const int g = lane >> 2, t = lane & 3;

    const int arA[4] = { (tid + 0) >> 3, (tid + 256) >> 3, (tid + 512) >> 3, (tid + 768) >> 3 };
    const int acA    = (tid & 7) * 4;
    const int brB[2] = { tid >> 4, (tid + 256) >> 4 };
    const int bcB    = (tid & 15) * 4;

    float cfr[2][4][4] = {};

    {
        float* As = dyn;  float* Bs = dyn + 128 * 36;
        #pragma unroll
        for (int it = 0; it < 4; it++)
            cp16(&As[arA[it] * 36 + acA], &g_Xt[(m0 + arA[it]) * 1024 + acA]);
        #pragma unroll
        for (int it = 0; it < 2; it++)
            cp16(&Bs[brB[it] * 68 + bcB], &Bmat[brB[it] * ldb + ncol0 + bcB]);
        asm volatile("cp.async.commit_group;");
    }

    #pragma unroll 2
    for (int k0 = 0; k0 < 1024; k0 += 32) {
        const int cur = (k0 >> 5) & 1;
        float* As  = dyn + (cur ? GSTAGE : 0);
        float* Bs  = As + 128 * 36;
        const bool has_next = (k0 + 32) < 1024;

        __syncthreads();
        if (has_next) {
            const int kn = k0 + 32;
            float* Asn = dyn + (cur ? 0 : GSTAGE);
            float* Bsn = Asn + 128 * 36;
            #pragma unroll
            for (int it = 0; it < 4; it++)
                cp16(&Asn[arA[it] * 36 + acA], &g_Xt[(m0 + arA[it]) * 1024 + kn + acA]);
            #pragma unroll
            for (int it = 0; it < 2; it++)
                cp16(&Bsn[brB[it] * 68 + bcB], &Bmat[(kn + brB[it]) * ldb + ncol0 + bcB]);
            asm volatile("cp.async.commit_group;");
            asm volatile("cp.async.wait_group 1;" ::: "memory");
        } else {
            asm volatile("cp.async.wait_group 0;" ::: "memory");
        }
        __syncthreads();

        mma_phase(As, Bs, wm, wn, g, t, cfr);
    }
    __syncthreads();

    #pragma unroll
    for (int f = 0; f < 2; f++) {
        int rbm = wm * 32 + f * 16 + g;
        #pragma unroll
        for (int j = 0; j < 4; j++) {
            int col = wn * 32 + j * 8 + 2 * t;
            Cs[(rbm    ) * 68 + col    ] = cfr[f][j][0];
            Cs[(rbm    ) * 68 + col + 1] = cfr[f][j][1];
            Cs[(rbm + 8) * 68 + col    ] = cfr[f][j][2];
            Cs[(rbm + 8) * 68 + col + 1] = cfr[f][j][3];
        }
    }
    __syncthreads();

    // Vectorized epilogue: 8 rows x one float4 column-chunk per thread.
    const int head_local = (kind == 0) ? (n0g >> 6) : (ncol0 >> 6);
    const int r0e = (tid >> 4) * 8;
    const int c0e = (tid & 15) * 4;            // multiple of 4; all 4 cols same half
    const bool lowhalf = (c0e < 32);
    float* dstbase = (kind == 0) ? g_Q : (kind == 1) ? g_K : g_V;
    const float qscale = SCALING * LOG2E;

    #pragma unroll
    for (int i = 0; i < 8; i++) {
        const int r = r0e + i;
        const int m = m0 + r;
        float4 val = *(const float4*)&Cs[r * 68 + c0e];
        float4 outv;
        if (kind == 2) {
            outv = val;
        } else {
            float4 par = lowhalf ? *(const float4*)&Cs[r * 68 + c0e + 32]
                                 : *(const float4*)&Cs[r * 68 + c0e - 32];
            float psgn = lowhalf ? -1.0f : 1.0f;
            float4 c4 = *(const float4*)&cs[m * HD + c0e];
            float4 s4 = *(const float4*)&sn[m * HD + c0e];
            outv.x = val.x * c4.x + psgn * par.x * s4.x;
            outv.y = val.y * c4.y + psgn * par.y * s4.y;
            outv.z = val.z * c4.z + psgn * par.z * s4.z;
            outv.w = val.w * c4.w + psgn * par.w * s4.w;
            if (kind == 0) {
                outv.x *= qscale; outv.y *= qscale;
                outv.z *= qscale; outv.w *= qscale;
            }
        }
        outv.x = f2tff(outv.x); outv.y = f2tff(outv.y);
        outv.z = f2tff(outv.z); outv.w = f2tff(outv.w);
        *(float4*)&dstbase[head_local * SEQ * HD + m * HD + c0e] = outv;
    }
}

// ---------------------------------------------------------------------------
// Flash per-KV-tile body (exp2-domain softmax; Q pre-scaled by log2e).
// ---------------------------------------------------------------------------
__device__ __forceinline__ void flash_tile(
    const float* Ks, const float* Vs,
    float* Kn, float* Vn, bool prefetch,
    const float* Kgn, const float* Vgn,
    const int* kvR, int kvC,
    const uint32_t (*qfr)[4], float (*ofr)[4],
    float& m1, float& m2, float& l1, float& l2,
    float* QSP, int rw, int g, int t)
{
    asm volatile("cp.async.wait_group 0;" ::: "memory");
    __syncthreads();

    if (prefetch) {
        #pragma unroll
        for (int it = 0; it < 4; it++) {
            cp16(&Kn[kvR[it] * 68 + kvC], &Kgn[kvR[it] * 64 + kvC]);
            cp16(&Vn[kvR[it] * 72 + kvC], &Vgn[kvR[it] * 64 + kvC]);
        }
        asm volatile("cp.async.commit_group;");
    }

    // S = Q @ K^T (S already in log2 domain: Q scaled by 0.125*log2e)
    float sfr[8][4] = {};
    #pragma unroll
    for (int ks = 0; ks < 8; ks++) {
        const int kk = ks * 8;
        #pragma unroll
        for (int j = 0; j < 8; j++) {
            int nb = j * 8 + g;
            uint32_t b0 = __float_as_uint(Ks[nb * 68 + kk + t    ]);
            uint32_t b1 = __float_as_uint(Ks[nb * 68 + kk + t + 4]);
            mma8(sfr[j], qfr[ks][0], qfr[ks][1], qfr[ks][2], qfr[ks][3], b0, b1);
        }
    }

    // Register online softmax, exp2 domain
    float mloc1 = -INFINITY, mloc2 = -INFINITY;
    #pragma unroll
    for (int j = 0; j < 8; j++) {
        mloc1 = fmaxf(mloc1, fmaxf(sfr[j][0], sfr[j][1]));
        mloc2 = fmaxf(mloc2, fmaxf(sfr[j][2], sfr[j][3]));
    }
    mloc1 = fmaxf(mloc1, __shfl_xor_sync(0xffffffffu, mloc1, 1));
    mloc1 = fmaxf(mloc1, __shfl_xor_sync(0xffffffffu, mloc1, 2));
    mloc2 = fmaxf(mloc2, __shfl_xor_sync(0xffffffffu, mloc2, 1));
    mloc2 = fmaxf(mloc2, __shfl_xor_sync(0xffffffffu, mloc2, 2));
    float mnew1 = fmaxf(m1, mloc1);
    float mnew2 = fmaxf(m2, mloc2);
    float sc1 = ex2(m1 - mnew1);   // first tile: ex2(-inf)=0
    float sc2 = ex2(m2 - mnew2);
    float ss1 = 0.0f, ss2 = 0.0f;
    #pragma unroll
    for (int j = 0; j < 8; j++) {
        sfr[j][0] = ex2(sfr[j][0] - mnew1); ss1 += sfr[j][0];
        sfr[j][1] = ex2(sfr[j][1] - mnew1); ss1 += sfr[j][1];
        sfr[j][2] = ex2(sfr[j][2] - mnew2); ss2 += sfr[j][2];
        sfr[j][3] = ex2(sfr[j][3] - mnew2); ss2 += sfr[j][3];
    }
    ss1 += __shfl_xor_sync(0xffffffffu, ss1, 1);
    ss1 += __shfl_xor_sync(0xffffffffu, ss1, 2);
    ss2 += __shfl_xor_sync(0xffffffffu, ss2, 1);
    ss2 += __shfl_xor_sync(0xffffffffu, ss2, 2);
    l1 = l1 * sc1 + ss1;  m1 = mnew1;
    l2 = l2 * sc2 + ss2;  m2 = mnew2;

    #pragma unroll
    for (int j = 0; j < 8; j++) {
        ofr[j][0] *= sc1; ofr[j][1] *= sc1;
        ofr[j][2] *= sc2; ofr[j][3] *= sc2;
    }

    // P -> QSP (own rows), tf32-rounded
    #pragma unroll
    for (int j = 0; j < 8; j++) {
        int col = j * 8 + 2 * t;
        QSP[(rw + g    ) * 68 + col    ] = f2tff(sfr[j][0]);
        QSP[(rw + g    ) * 68 + col + 1] = f2tff(sfr[j][1]);
        QSP[(rw + g + 8) * 68 + col    ] = f2tff(sfr[j][2]);
        QSP[(rw + g + 8) * 68 + col + 1] = f2tff(sfr[j][3]);
    }
    __syncwarp();

    // O += P @ V
    #pragma unroll
    for (int ks = 0; ks < 8; ks++) {
        const int kk = ks * 8;
        uint32_t a0 = __float_as_uint(QSP[(rw + g    ) * 68 + kk + t    ]);
        uint32_t a1 = __float_as_uint(QSP[(rw + g + 8) * 68 + kk + t    ]);
        uint32_t a2 = __float_as_uint(QSP[(rw + g    ) * 68 + kk + t + 4]);
        uint32_t a3 = __float_as_uint(QSP[(rw + g + 8) * 68 + kk + t + 4]);
        #pragma unroll
        for (int j = 0; j < 8; j++) {
            int nb = j * 8 + g;
            uint32_t b0 = __float_as_uint(Vs[(kk + t    ) * 72 + nb]);
            uint32_t b1 = __float_as_uint(Vs[(kk + t + 4) * 72 + nb]);
            mma8(ofr[j], a0, a1, a2, a3, b0, b1);
        }
    }
}

// ---------------------------------------------------------------------------
// Kernel 2: flash attention (tf32), warp-exclusive rows, register softmax,
// cp.async 2-stage, manual unroll-2 static stage pointers.
// ---------------------------------------------------------------------------
__global__ __launch_bounds__(256, 2) void flash_kernel()
{
    const int q0  = blockIdx.x * 128;
    const int h   = blockIdx.y;
    const int kvh = h >> 2;

    extern __shared__ float smf[];
    float* QSP = smf;                              // [128][68]
    float* K0  = smf + 128 * 68;
    float* K1  = K0 + 64 * 68;
    float* V0  = K1 + 64 * 68;
    float* V1  = V0 + 64 * 72;

    const int tid  = threadIdx.x;
    const int lane = tid & 31, warp = tid >> 5;
    const int g = lane >> 2, t = lane & 3;
    const int rw = warp * 16;

    const float* Qg = g_Q + h * SEQ * HD + q0 * HD;
    const float* Kg = g_K + kvh * SEQ * HD;
    const float* Vg = g_V + kvh * SEQ * HD;

    const int kvR[4] = { (tid + 0) >> 4, (tid + 256) >> 4, (tid + 512) >> 4, (tid + 768) >> 4 };
    const int kvC    = (tid & 15) * 4;

    #pragma unroll
    for (int it = 0; it < 8; it++) {
        int id = tid + it * 256;
        int r = id >> 4, c4 = (id & 15) * 4;
        *(float4*)&QSP[r * 68 + c4] = *(const float4*)&Qg[r * 64 + c4];
    }
    __syncthreads();
    uint32_t qfr[8][4];
    #pragma unroll
    for (int ks = 0; ks < 8; ks++) {
        const int kk = ks * 8;
        qfr[ks][0] = __float_as_uint(QSP[(rw + g    ) * 68 + kk + t    ]);
        qfr[ks][1] = __float_as_uint(QSP[(rw + g + 8) * 68 + kk + t    ]);
        qfr[ks][2] = __float_as_uint(QSP[(rw + g    ) * 68 + kk + t + 4]);
        qfr[ks][3] = __float_as_uint(QSP[(rw + g + 8) * 68 + kk + t + 4]);
    }

    #pragma unroll
    for (int it = 0; it < 4; it++) {
        cp16(&K0[kvR[it] * 68 + kvC], &Kg[kvR[it] * 64 + kvC]);
        cp16(&V0[kvR[it] * 72 + kvC], &Vg[kvR[it] * 64 + kvC]);
    }
    asm volatile("cp.async.commit_group;");

    float m1 = -INFINITY, m2 = -INFINITY, l1 = 0.0f, l2 = 0.0f;
    float ofr[8][4] = {};

    for (int ktp = 0; ktp < 16; ktp++) {
        const int kt0 = 2 * ktp;
        flash_tile(K0, V0, K1, V1, true,
                   Kg + (kt0 + 1) * 64 * 64, Vg + (kt0 + 1) * 64 * 64,
                   kvR, kvC, qfr, ofr, m1, m2, l1, l2, QSP, rw, g, t);
        const bool more = (kt0 + 2) < 32;
        const float* Kgn = Kg + (more ? (kt0 + 2) * 64 * 64 : 0);
        const float* Vgn = Vg + (more ? (kt0 + 2) * 64 * 64 : 0);
        flash_tile(K1, V1, K0, V0, more,
                   Kgn, Vgn, kvR, kvC, qfr, ofr, m1, m2, l1, l2, QSP, rw, g, t);
    }

    float inv1 = 1.0f / l1;
    float inv2 = 1.0f / l2;
    #pragma unroll
    for (int j = 0; j < 8; j++) {
        int col = j * 8 + 2 * t;
        QSP[(rw + g    ) * 68 + col    ] = f2tff(ofr[j][0] * inv1);
        QSP[(rw + g    ) * 68 + col + 1] = f2tff(ofr[j][1] * inv1);
        QSP[(rw + g + 8) * 68 + col    ] = f2tff(ofr[j][2] * inv2);
        QSP[(rw + g + 8) * 68 + col + 1] = f2tff(ofr[j][3] * inv2);
    }
    __syncthreads();
    #pragma unroll
    for (int it = 0; it < 8; it++) {
        int id = tid + it * 256;
        int r = id >> 4, c4 = (id & 15) * 4;
        *(float4*)&g_AO[(q0 + r) * 1024 + h * 64 + c4] = *(const float4*)&QSP[r * 68 + c4];
    }
}

// ---------------------------------------------------------------------------
// Kernel 3: output projection (tf32), cp.async 2-stage, 3 blocks/SM.
// ---------------------------------------------------------------------------
__global__ __launch_bounds__(256, 3) void oproj_kernel(float* __restrict__ out)
{
    const int n0 = blockIdx.x * 64;
    const int m0 = blockIdx.y * 128;

    extern __shared__ float dyn[];
    float* Cs = dyn;

    const int tid  = threadIdx.x;
    const int lane = tid & 31, warp = tid >> 5;
    const int wm = warp & 3, wn = warp >> 2;
    const int g = lane >> 2, t = lane & 3;

    const int arA[4] = { (tid + 0) >> 3, (tid + 256) >> 3, (tid + 512) >> 3, (tid + 768) >> 3 };
    const int acA    = (tid & 7) * 4;
    const int brB[2] = { tid >> 4, (tid + 256) >> 4 };
    const int bcB    = (tid & 15) * 4;

    float cfr[2][4][4] = {};

    {
        float* As = dyn;  float* Bs = dyn + 128 * 36;
        #pragma unroll
        for (int it = 0; it < 4; it++)
            cp16(&As[arA[it] * 36 + acA], &g_AO[(m0 + arA[it]) * 1024 + acA]);
        #pragma unroll
        for (int it = 0; it < 2; it++)
            cp16(&Bs[brB[it] * 68 + bcB], &g_Wot[brB[it] * 1024 + n0 + bcB]);
        asm volatile("cp.async.commit_group;");
    }

    #pragma unroll 2
    for (int k0 = 0; k0 < 1024; k0 += 32) {
        const int cur = (k0 >> 5) & 1;
        float* As  = dyn + (cur ? GSTAGE : 0);
        float* Bs  = As + 128 * 36;
        const bool has_next = (k0 + 32) < 1024;

        __syncthreads();
        if (has_next) {
            const int kn = k0 + 32;
            float* Asn = dyn + (cur ? 0 : GSTAGE);
            float* Bsn = Asn + 128 * 36;
            #pragma unroll
            for (int it = 0; it < 4; it++)
                cp16(&Asn[arA[it] * 36 + acA], &g_AO[(m0 + arA[it]) * 1024 + kn + acA]);
            #pragma unroll
            for (int it = 0; it < 2; it++)
                cp16(&Bsn[brB[it] * 68 + bcB], &g_Wot[(kn + brB[it]) * 1024 + n0 + bcB]);
            asm volatile("cp.async.commit_group;");
            asm volatile("cp.async.wait_group 1;" ::: "memory");
        } else {
            asm volatile("cp.async.wait_group 0;" ::: "memory");
        }
        __syncthreads();

        mma_phase(As, Bs, wm, wn, g, t, cfr);
    }
    __syncthreads();

    #pragma unroll
    for (int f = 0; f < 2; f++) {
        int rbm = wm * 32 + f * 16 + g;
        #pragma unroll
        for (int j = 0; j < 4; j++) {
            int col = wn * 32 + j * 8 + 2 * t;
            Cs[(rbm    ) * 68 + col    ] = cfr[f][j][0];
            Cs[(rbm    ) * 68 + col + 1] = cfr[f][j][1];
            Cs[(rbm + 8) * 68 + col    ] = cfr[f][j][2];
            Cs[(rbm + 8) * 68 + col + 1] = cfr[f][j][3];
        }
    }
    __syncthreads();
    #pragma unroll
    for (int it = 0; it < 8; it++) {
        int id = tid + it * 256;
        int r = id >> 4, c4 = (id & 15) * 4;
        *(float4*)&out[(m0 + r) * 1024 + n0 + c4] = *(const float4*)&Cs[r * 68 + c4];
    }
}

// ---------------------------------------------------------------------------
// Launch.
// ---------------------------------------------------------------------------
extern "C" void kernel_launch(void* const* d_in, const int* in_sizes, int n_in,
                              void* d_out, int out_size)
{
    const float* X  = (const float*)d_in[0];
    const float* cs = (const float*)d_in[1];
    const float* sn = (const float*)d_in[2];
    // d_in[3] = attention_mask (all ones) — unused
    const float* Wq = (const float*)d_in[4];
    const float* Wk = (const float*)d_in[5];
    const float* Wv = (const float*)d_in[6];
    const float* Wo = (const float*)d_in[7];
    float* out = (float*)d_out;

    cvt_all_kernel<<<4608, 256>>>((const float4*)X, (const float4*)Wq,
                                  (const float4*)Wk, (const float4*)Wv,
                                  (const float4*)Wo);

    const size_t smem_gemm = 2 * GSTAGE * sizeof(float);   // 54272 B
    cudaFuncSetAttribute(qkv_rope_kernel,
                         cudaFuncAttributeMaxDynamicSharedMemorySize, (int)smem_gemm);
    cudaFuncSetAttribute(oproj_kernel,
                         cudaFuncAttributeMaxDynamicSharedMemorySize, (int)smem_gemm);

    qkv_rope_kernel<<<dim3(24, 16), 256, smem_gemm>>>(cs, sn);

    const size_t smem_flash = (128 * 68 + 2 * 64 * 68 + 2 * 64 * 72) * sizeof(float); // 106496 B
    cudaFuncSetAttribute(flash_kernel,
                         cudaFuncAttributeMaxDynamicSharedMemorySize, (int)smem_flash);
    flash_kernel<<<dim3(16, 16), 256, smem_flash>>>();

    oproj_kernel<<<dim3(16, 16), 256, smem_gemm>>>(out);
}

// round 14
// speedup vs baseline: 7.0631x; 1.7009x over previous
#include <cuda_runtime.h>
#include <cuda_fp16.h>
#include <math.h>
#include <stdint.h>

#define SEQ 2048
#define HID 1024
#define NH 16
#define NKV 4
#define HD 64
#define SCALING 0.125f
#define LOG2E 1.4426950408889634f

// ---------------------------------------------------------------------------
// Device globals (16B-aligned)
// ---------------------------------------------------------------------------
__device__ __align__(16) __half g_Qh[NH * SEQ * HD];    // [h][m][d], RoPE'd, *0.125*log2e
__device__ __align__(16) __half g_Kh[NKV * SEQ * HD];   // [kvh][m][d], RoPE'd
__device__ __align__(16) __half g_Vt[NKV * HD * SEQ];   // [kvh][d][m]  (TRANSPOSED)
__device__ __align__(16) __half g_AOh[SEQ * HID];       // [m][h*64+d]
__device__ __align__(16) __half g_Xh[SEQ * HID];        // [m][k]
__device__ __align__(16) __half g_WqT[1024 * HID];      // [n][k]
__device__ __align__(16) __half g_WkT[256 * HID];       // [n][k]
__device__ __align__(16) __half g_WvT[256 * HID];       // [n][k]
__device__ __align__(16) __half g_WoT[HID * 1024];      // [n][k]

// ---------------------------------------------------------------------------
// Helpers
// ---------------------------------------------------------------------------
__device__ __forceinline__ float ex2(float x) {
    float r;
    asm("ex2.approx.f32 %0, %1;" : "=f"(r) : "f"(x));
    return r;
}

__device__ __forceinline__ uint32_t pack_h2(float lo, float hi) {
    __half2 h = __floats2half2_rn(lo, hi);
    return *reinterpret_cast<uint32_t*>(&h);
}

// m16n8k16 fp16 MMA, f32 accumulate.
__device__ __forceinline__ void mma16(float c[4],
                                      uint32_t a0, uint32_t a1, uint32_t a2, uint32_t a3,
                                      uint32_t b0, uint32_t b1) {
    asm volatile(
        "mma.sync.aligned.m16n8k16.row.col.f32.f16.f16.f32 "
        "{%0,%1,%2,%3}, {%4,%5,%6,%7}, {%8,%9}, {%0,%1,%2,%3};"
        : "+f"(c[0]), "+f"(c[1]), "+f"(c[2]), "+f"(c[3])
        : "r"(a0), "r"(a1), "r"(a2), "r"(a3), "r"(b0), "r"(b1));
}

__device__ __forceinline__ void cp16h(__half* smem_dst, const __half* gsrc) {
    uint32_t s = (uint32_t)__cvta_generic_to_shared(smem_dst);
    asm volatile("cp.async.ca.shared.global [%0], [%1], 16;" :: "r"(s), "l"(gsrc));
}

__device__ __forceinline__ uint32_t ldh2(const __half* p) {
    return *reinterpret_cast<const uint32_t*>(p);
}

// ---------------------------------------------------------------------------
// Kernel 0a: X fp32 -> fp16 (8 elems/thread).
// ---------------------------------------------------------------------------
__global__ __launch_bounds__(256) void cvt_x_kernel(const float4* __restrict__ X)
{
    const int i = blockIdx.x * 256 + threadIdx.x;   // 0 .. 2048*1024/8-1
    float4 v0 = X[2 * i], v1 = X[2 * i + 1];
    uint4 o;
    o.x = pack_h2(v0.x, v0.y);
    o.y = pack_h2(v0.z, v0.w);
    o.z = pack_h2(v1.x, v1.y);
    o.w = pack_h2(v1.z, v1.w);
    *reinterpret_cast<uint4*>(&g_Xh[8 * i]) = o;
}

// ---------------------------------------------------------------------------
// Kernel 0b: weight transpose + fp16 convert: WT[n][k] = half(W[k][n]).
// ---------------------------------------------------------------------------
__global__ __launch_bounds__(256) void wt_kernel(
    const float* __restrict__ Wq, const float* __restrict__ Wk,
    const float* __restrict__ Wv, const float* __restrict__ Wo)
{
    __shared__ float tile[32][33];
    const int id = blockIdx.x;
    const float* src; __half* dst; int ncols, local;
    if (id < 1024)      { src = Wq; dst = g_WqT; ncols = 1024; local = id; }
    else if (id < 1280) { src = Wk; dst = g_WkT; ncols = 256;  local = id - 1024; }
    else if (id < 1536) { src = Wv; dst = g_WvT; ncols = 256;  local = id - 1280; }
    else                { src = Wo; dst = g_WoT; ncols = 1024; local = id - 1536; }
    const int ntiles = ncols / 32;
    const int kb = (local / ntiles) * 32;
    const int nb = (local % ntiles) * 32;
    const int tx = threadIdx.x & 31;
    const int ty = threadIdx.x >> 5;          // 0..7
    #pragma unroll
    for (int j = 0; j < 4; j++)
        tile[ty + j * 8][tx] = src[(kb + ty + j * 8) * ncols + nb + tx];
    __syncthreads();
    #pragma unroll
    for (int j = 0; j < 4; j++)
        dst[(nb + ty + j * 8) * 1024 + kb + tx] = __float2half_rn(tile[tx][ty + j * 8]);
}

// ---------------------------------------------------------------------------
// Kernel 1: fused QKV projection + RoPE (fp16 m16n8k16), cp.async 2-stage.
// Block tile 128x64, BK=32, 8 warps (4m x 2n), warp tile 32x32.
// ---------------------------------------------------------------------------
#define QSTAGE_H (128 * 40 + 64 * 40)   // 7680 halves = 15360 B

__global__ __launch_bounds__(256, 3) void qkv_rope_kernel(
    const float* __restrict__ cs,
    const float* __restrict__ sn)
{
    const int n0g = blockIdx.x * 64;
    const int m0  = blockIdx.y * 128;

    const __half* Wt;
    int ncol0, kind;                       // 0=Q, 1=K, 2=V
    if (n0g < 1024)       { Wt = g_WqT; ncol0 = n0g;        kind = 0; }
    else if (n0g < 1280)  { Wt = g_WkT; ncol0 = n0g - 1024; kind = 1; }
    else                  { Wt = g_WvT; ncol0 = n0g - 1280; kind = 2; }

    extern __shared__ float dynf[];
    __half* dynh = (__half*)dynf;
    float* Cs = dynf;                      // [128][68] f32 epilogue staging

    const int tid  = threadIdx.x;
    const int lane = tid & 31, warp = tid >> 5;
    const int wm = warp & 3, wn = warp >> 2;
    const int g = lane >> 2, t = lane & 3;

    // staging coords: A 512 chunks (2/thread), B 256 chunks (1/thread)
    const int aR[2] = { tid >> 2, (tid + 256) >> 2 };
    const int aC    = (tid & 3) * 8;
    const int bR    = tid >> 2;
    const int bC    = (tid & 3) * 8;

    float cfr[2][4][4] = {};

    {
        __half* As = dynh;  __half* Bs = dynh + 128 * 40;
        #pragma unroll
        for (int it = 0; it < 2; it++)
            cp16h(&As[aR[it] * 40 + aC], &g_Xh[(m0 + aR[it]) * 1024 + aC]);
        cp16h(&Bs[bR * 40 + bC], &Wt[(ncol0 + bR) * 1024 + bC]);
        asm volatile("cp.async.commit_group;");
    }

    #pragma unroll 2
    for (int k0 = 0; k0 < 1024; k0 += 32) {
        const int cur = (k0 >> 5) & 1;
        __half* As = dynh + (cur ? QSTAGE_H : 0);
        __half* Bs = As + 128 * 40;
        const bool has_next = (k0 + 32) < 1024;

        __syncthreads();
        if (has_next) {
            const int kn = k0 + 32;
            __half* Asn = dynh + (cur ? 0 : QSTAGE_H);
            __half* Bsn = Asn + 128 * 40;
            #pragma unroll
            for (int it = 0; it < 2; it++)
                cp16h(&Asn[aR[it] * 40 + aC], &g_Xh[(m0 + aR[it]) * 1024 + kn + aC]);
            cp16h(&Bsn[bR * 40 + bC], &Wt[(ncol0 + bR) * 1024 + kn + bC]);
            asm volatile("cp.async.commit_group;");
            asm volatile("cp.async.wait_group 1;" ::: "memory");
        } else {
            asm volatile("cp.async.wait_group 0;" ::: "memory");
        }
        __syncthreads();

        #pragma unroll
        for (int ks = 0; ks < 2; ks++) {
            const int kk = ks * 16;
            uint32_t af[2][4];
            #pragma unroll
            for (int f = 0; f < 2; f++) {
                int rbm = wm * 32 + f * 16 + g;
                af[f][0] = ldh2(&As[(rbm    ) * 40 + kk + 2 * t    ]);
                af[f][1] = ldh2(&As[(rbm + 8) * 40 + kk + 2 * t    ]);
                af[f][2] = ldh2(&As[(rbm    ) * 40 + kk + 2 * t + 8]);
                af[f][3] = ldh2(&As[(rbm + 8) * 40 + kk + 2 * t + 8]);
            }
            #pragma unroll
            for (int j = 0; j < 4; j++) {
                int nb = wn * 32 + j * 8 + g;
                uint32_t b0 = ldh2(&Bs[nb * 40 + kk + 2 * t    ]);
                uint32_t b1 = ldh2(&Bs[nb * 40 + kk + 2 * t + 8]);
                mma16(cfr[0][j], af[0][0], af[0][1], af[0][2], af[0][3], b0, b1);
                mma16(cfr[1][j], af[1][0], af[1][1], af[1][2], af[1][3], b0, b1);
            }
        }
    }
    __syncthreads();

    // fragments -> Cs (f32) for RoPE partner exchange
    #pragma unroll
    for (int f = 0; f < 2; f++) {
        int rbm = wm * 32 + f * 16 + g;
        #pragma unroll
        for (int j = 0; j < 4; j++) {
            int col = wn * 32 + j * 8 + 2 * t;
            Cs[(rbm    ) * 68 + col    ] = cfr[f][j][0];
            Cs[(rbm    ) * 68 + col + 1] = cfr[f][j][1];
            Cs[(rbm + 8) * 68 + col    ] = cfr[f][j][2];
            Cs[(rbm + 8) * 68 + col + 1] = cfr[f][j][3];
        }
    }
    __syncthreads();

    const int head_local = (kind == 0) ? (n0g >> 6) : (ncol0 >> 6);
    const int r0e = (tid >> 4) * 8;
    const int c0e = (tid & 15) * 4;
    const bool lowhalf = (c0e < 32);
    const float qscale = SCALING * LOG2E;

    #pragma unroll
    for (int i = 0; i < 8; i++) {
        const int r = r0e + i;
        const int m = m0 + r;
        float4 val = *(const float4*)&Cs[r * 68 + c0e];
        float4 outv;
        if (kind == 2) {
            outv = val;
        } else {
            float4 par = lowhalf ? *(const float4*)&Cs[r * 68 + c0e + 32]
                                 : *(const float4*)&Cs[r * 68 + c0e - 32];
            float psgn = lowhalf ? -1.0f : 1.0f;
            float4 c4 = *(const float4*)&cs[m * HD + c0e];
            float4 s4 = *(const float4*)&sn[m * HD + c0e];
            outv.x = val.x * c4.x + psgn * par.x * s4.x;
            outv.y = val.y * c4.y + psgn * par.y * s4.y;
            outv.z = val.z * c4.z + psgn * par.z * s4.z;
            outv.w = val.w * c4.w + psgn * par.w * s4.w;
            if (kind == 0) {
                outv.x *= qscale; outv.y *= qscale;
                outv.z *= qscale; outv.w *= qscale;
            }
        }
        if (kind == 2) {
            // V stored transposed: g_Vt[kvh][d][m]
            __half* vb = g_Vt + head_local * HD * SEQ;
            vb[(c0e + 0) * SEQ + m] = __float2half_rn(outv.x);
            vb[(c0e + 1) * SEQ + m] = __float2half_rn(outv.y);
            vb[(c0e + 2) * SEQ + m] = __float2half_rn(outv.z);
            vb[(c0e + 3) * SEQ + m] = __float2half_rn(outv.w);
        } else {
            uint2 o;
            o.x = pack_h2(outv.x, outv.y);
            o.y = pack_h2(outv.z, outv.w);
            __half* dstb = (kind == 0) ? g_Qh : g_Kh;
            *reinterpret_cast<uint2*>(&dstb[head_local * SEQ * HD + m * HD + c0e]) = o;
        }
    }
}

// ---------------------------------------------------------------------------
// Flash per-KV-tile body (fp16 MMAs, f32 softmax in exp2 domain).
// KV tiles are 64 rows x 64 halves = 512 x 16B chunks -> 2 chunks/thread.
// ---------------------------------------------------------------------------
__device__ __forceinline__ void flash_tile(
    const __half* Ks, const __half* Vs,
    __half* Kn, __half* Vn, bool prefetch,
    const __half* Kgn, const __half* Vgn,
    const int* kvR, const int* kvC,
    const uint32_t (*qfr)[4], float (*ofr)[4],
    float& m1, float& m2, float& l1, float& l2,
    __half* QSP, int rw, int g, int t)
{
    asm volatile("cp.async.wait_group 0;" ::: "memory");
    __syncthreads();

    if (prefetch) {
        #pragma unroll
        for (int it = 0; it < 2; it++) {
            cp16h(&Kn[kvR[it] * 72 + kvC[it]], &Kgn[kvR[it] * 64 + kvC[it]]);
            cp16h(&Vn[kvR[it] * 72 + kvC[it]], &Vgn[kvR[it] * SEQ + kvC[it]]);
        }
        asm volatile("cp.async.commit_group;");
    }

    // S = Q @ K^T : k = d (64) -> 4 k16 steps; n = kv (64) -> 8 j-blocks
    float sfr[8][4] = {};
    #pragma unroll
    for (int ks = 0; ks < 4; ks++) {
        const int kk = ks * 16;
        #pragma unroll
        for (int j = 0; j < 8; j++) {
            int nb = j * 8 + g;
            uint32_t b0 = ldh2(&Ks[nb * 72 + kk + 2 * t    ]);
            uint32_t b1 = ldh2(&Ks[nb * 72 + kk + 2 * t + 8]);
            mma16(sfr[j], qfr[ks][0], qfr[ks][1], qfr[ks][2], qfr[ks][3], b0, b1);
        }
    }

    // register online softmax (rows rw+g, rw+g+8), exp2 domain
    float mloc1 = -INFINITY, mloc2 = -INFINITY;
    #pragma unroll
    for (int j = 0; j < 8; j++) {
        mloc1 = fmaxf(mloc1, fmaxf(sfr[j][0], sfr[j][1]));
        mloc2 = fmaxf(mloc2, fmaxf(sfr[j][2], sfr[j][3]));
    }
    mloc1 = fmaxf(mloc1, __shfl_xor_sync(0xffffffffu, mloc1, 1));
    mloc1 = fmaxf(mloc1, __shfl_xor_sync(0xffffffffu, mloc1, 2));
    mloc2 = fmaxf(mloc2, __shfl_xor_sync(0xffffffffu, mloc2, 1));
    mloc2 = fmaxf(mloc2, __shfl_xor_sync(0xffffffffu, mloc2, 2));
    float mnew1 = fmaxf(m1, mloc1);
    float mnew2 = fmaxf(m2, mloc2);
    float sc1 = ex2(m1 - mnew1);   // first tile: ex2(-inf)=0
    float sc2 = ex2(m2 - mnew2);
    float ss1 = 0.0f, ss2 = 0.0f;
    #pragma unroll
    for (int j = 0; j < 8; j++) {
        sfr[j][0] = ex2(sfr[j][0] - mnew1); ss1 += sfr[j][0];
        sfr[j][1] = ex2(sfr[j][1] - mnew1); ss1 += sfr[j][1];
        sfr[j][2] = ex2(sfr[j][2] - mnew2); ss2 += sfr[j][2];
        sfr[j][3] = ex2(sfr[j][3] - mnew2); ss2 += sfr[j][3];
    }
    ss1 += __shfl_xor_sync(0xffffffffu, ss1, 1);
    ss1 += __shfl_xor_sync(0xffffffffu, ss1, 2);
    ss2 += __shfl_xor_sync(0xffffffffu, ss2, 1);
    ss2 += __shfl_xor_sync(0xffffffffu, ss2, 2);
    l1 = l1 * sc1 + ss1;  m1 = mnew1;
    l2 = l2 * sc2 + ss2;  m2 = mnew2;

    #pragma unroll
    for (int j = 0; j < 8; j++) {
        ofr[j][0] *= sc1; ofr[j][1] *= sc1;
        ofr[j][2] *= sc2; ofr[j][3] *= sc2;
    }

    // P -> QSP as packed half2 (own rows only)
    #pragma unroll
    for (int j = 0; j < 8; j++) {
        int col = j * 8 + 2 * t;
        *reinterpret_cast<uint32_t*>(&QSP[(rw + g    ) * 72 + col]) = pack_h2(sfr[j][0], sfr[j][1]);
        *reinterpret_cast<uint32_t*>(&QSP[(rw + g + 8) * 72 + col]) = pack_h2(sfr[j][2], sfr[j][3]);
    }
    __syncwarp();

    // O += P @ V^T : k = kv (64) -> 4 k16 steps; n = d (64) -> 8 j-blocks
    #pragma unroll
    for (int ks = 0; ks < 4; ks++) {
        const int kk = ks * 16;
        uint32_t a0 = ldh2(&QSP[(rw + g    ) * 72 + kk + 2 * t    ]);
        uint32_t a1 = ldh2(&QSP[(rw + g + 8) * 72 + kk + 2 * t    ]);
        uint32_t a2 = ldh2(&QSP[(rw + g    ) * 72 + kk + 2 * t + 8]);
        uint32_t a3 = ldh2(&QSP[(rw + g + 8) * 72 + kk + 2 * t + 8]);
        #pragma unroll
        for (int j = 0; j < 8; j++) {
            int nb = j * 8 + g;
            uint32_t b0 = ldh2(&Vs[nb * 72 + kk + 2 * t    ]);
            uint32_t b1 = ldh2(&Vs[nb * 72 + kk + 2 * t + 8]);
            mma16(ofr[j], a0, a1, a2, a3, b0, b1);
        }
    }
}

// ---------------------------------------------------------------------------
// Kernel 2: flash attention (fp16 MMA), warp-exclusive rows, register softmax,
// cp.async 2-stage KV pipeline, manual unroll-2.
// ---------------------------------------------------------------------------
__global__ __launch_bounds__(256, 2) void flash_kernel()
{
    const int q0  = blockIdx.x * 128;
    const int h   = blockIdx.y;
    const int kvh = h >> 2;

    extern __shared__ __half smh[];
    __half* QSP = smh;                    // [128][72]
    __half* K0  = smh + 128 * 72;         // [64][72]
    __half* K1  = K0 + 64 * 72;
    __half* V0  = K1 + 64 * 72;
    __half* V1  = V0 + 64 * 72;

    const int tid  = threadIdx.x;
    const int lane = tid & 31, warp = tid >> 5;
    const int g = lane >> 2, t = lane & 3;
    const int rw = warp * 16;

    const __half* Qg = g_Qh + h * SEQ * HD + q0 * HD;
    const __half* Kg = g_Kh + kvh * SEQ * HD;
    const __half* Vg = g_Vt + kvh * HD * SEQ;   // [d][m]

    // KV staging: 512 chunks of 8 halves -> 2 per thread
    const int kvR[2] = { tid >> 3, (tid + 256) >> 3 };
    const int kvC[2] = { (tid & 7) * 8, ((tid + 256) & 7) * 8 };

    // Q tile -> QSP (uint4 = 8 halves), then fragments to registers
    #pragma unroll
    for (int it = 0; it < 4; it++) {
        int id = tid + it * 256;
        int r = id >> 3, c8 = (id & 7) * 8;
        *(uint4*)&QSP[r * 72 + c8] = *(const uint4*)&Qg[r * 64 + c8];
    }
    __syncthreads();
    uint32_t qfr[4][4];
    #pragma unroll
    for (int ks = 0; ks < 4; ks++) {
        const int kk = ks * 16;
        qfr[ks][0] = ldh2(&QSP[(rw + g    ) * 72 + kk + 2 * t    ]);
        qfr[ks][1] = ldh2(&QSP[(rw + g + 8) * 72 + kk + 2 * t    ]);
        qfr[ks][2] = ldh2(&QSP[(rw + g    ) * 72 + kk + 2 * t + 8]);
        qfr[ks][3] = ldh2(&QSP[(rw + g + 8) * 72 + kk + 2 * t + 8]);
    }

    // prologue: stage KV tile 0 into slot 0
    #pragma unroll
    for (int it = 0; it < 2; it++) {
        cp16h(&K0[kvR[it] * 72 + kvC[it]], &Kg[kvR[it] * 64 + kvC[it]]);
        cp16h(&V0[kvR[it] * 72 + kvC[it]], &Vg[kvR[it] * SEQ + kvC[it]]);
    }
    asm volatile("cp.async.commit_group;");

    float m1 = -INFINITY, m2 = -INFINITY, l1 = 0.0f, l2 = 0.0f;
    float ofr[8][4] = {};

    for (int ktp = 0; ktp < 16; ktp++) {
        const int kt0 = 2 * ktp;
        flash_tile(K0, V0, K1, V1, true,
                   Kg + (kt0 + 1) * 64 * 64, Vg + (kt0 + 1) * 64,
                   kvR, kvC, qfr, ofr, m1, m2, l1, l2, QSP, rw, g, t);
        const bool more = (kt0 + 2) < 32;
        const __half* Kgn = Kg + (more ? (kt0 + 2) * 64 * 64 : 0);
        const __half* Vgn = Vg + (more ? (kt0 + 2) * 64 : 0);
        flash_tile(K1, V1, K0, V0, more,
                   Kgn, Vgn, kvR, kvC, qfr, ofr, m1, m2, l1, l2, QSP, rw, g, t);
    }

    // normalize -> half2 into QSP -> coalesced store to g_AOh
    float inv1 = 1.0f / l1;
    float inv2 = 1.0f / l2;
    __syncthreads();
    #pragma unroll
    for (int j = 0; j < 8; j++) {
        int col = j * 8 + 2 * t;
        *reinterpret_cast<uint32_t*>(&QSP[(rw + g    ) * 72 + col]) =
            pack_h2(ofr[j][0] * inv1, ofr[j][1] * inv1);
        *reinterpret_cast<uint32_t*>(&QSP[(rw + g + 8) * 72 + col]) =
            pack_h2(ofr[j][2] * inv2, ofr[j][3] * inv2);
    }
    __syncthreads();
    #pragma unroll
    for (int it = 0; it < 4; it++) {
        int id = tid + it * 256;
        int r = id >> 3, c8 = (id & 7) * 8;
        *(uint4*)&g_AOh[(q0 + r) * 1024 + h * 64 + c8] = *(const uint4*)&QSP[r * 72 + c8];
    }
}

// ---------------------------------------------------------------------------
// Kernel 3: output projection (fp16 m16n8k16), cp.async 2-stage, out f32.
// ---------------------------------------------------------------------------
__global__ __launch_bounds__(256, 3) void oproj_kernel(float* __restrict__ out)
{
    const int n0 = blockIdx.x * 64;
    const int m0 = blockIdx.y * 128;

    extern __shared__ float dynf[];
    __half* dynh = (__half*)dynf;
    float* Cs = dynf;                      // [128][68] f32 epilogue staging

    const int tid  = threadIdx.x;
    const int lane = tid & 31, warp = tid >> 5;
    const int wm = warp & 3, wn = warp >> 2;
    const int g = lane >> 2, t = lane & 3;

    const int aR[2] = { tid >> 2, (tid + 256) >> 2 };
    const int aC    = (tid & 3) * 8;
    const int bR    = tid >> 2;
    const int bC    = (tid & 3) * 8;

    float cfr[2][4][4] = {};

    {
        __half* As = dynh;  __half* Bs = dynh + 128 * 40;
        #pragma unroll
        for (int it = 0; it < 2; it++)
            cp16h(&As[aR[it] * 40 + aC], &g_AOh[(m0 + aR[it]) * 1024 + aC]);
        cp16h(&Bs[bR * 40 + bC], &g_WoT[(n0 + bR) * 1024 + bC]);
        asm volatile("cp.async.commit_group;");
    }

    #pragma unroll 2
    for (int k0 = 0; k0 < 1024; k0 += 32) {
        const int cur = (k0 >> 5) & 1;
        __half* As = dynh + (cur ? QSTAGE_H : 0);
        __half* Bs = As + 128 * 40;
        const bool has_next = (k0 + 32) < 1024;

        __syncthreads();
        if (has_next) {
            const int kn = k0 + 32;
            __half* Asn = dynh + (cur ? 0 : QSTAGE_H);
            __half* Bsn = Asn + 128 * 40;
            #pragma unroll
            for (int it = 0; it < 2; it++)
                cp16h(&Asn[aR[it] * 40 + aC], &g_AOh[(m0 + aR[it]) * 1024 + kn + aC]);
            cp16h(&Bsn[bR * 40 + bC], &g_WoT[(n0 + bR) * 1024 + kn + bC]);
            asm volatile("cp.async.commit_group;");
            asm volatile("cp.async.wait_group 1;" ::: "memory");
        } else {
            asm volatile("cp.async.wait_group 0;" ::: "memory");
        }
        __syncthreads();

        #pragma unroll
        for (int ks = 0; ks < 2; ks++) {
            const int kk = ks * 16;
            uint32_t af[2][4];
            #pragma unroll
            for (int f = 0; f < 2; f++) {
                int rbm = wm * 32 + f * 16 + g;
                af[f][0] = ldh2(&As[(rbm    ) * 40 + kk + 2 * t    ]);
                af[f][1] = ldh2(&As[(rbm + 8) * 40 + kk + 2 * t    ]);
                af[f][2] = ldh2(&As[(rbm    ) * 40 + kk + 2 * t + 8]);
                af[f][3] = ldh2(&As[(rbm + 8) * 40 + kk + 2 * t + 8]);
            }
            #pragma unroll
            for (int j = 0; j < 4; j++) {
                int nb = wn * 32 + j * 8 + g;
                uint32_t b0 = ldh2(&Bs[nb * 40 + kk + 2 * t    ]);
                uint32_t b1 = ldh2(&Bs[nb * 40 + kk + 2 * t + 8]);
                mma16(cfr[0][j], af[0][0], af[0][1], af[0][2], af[0][3], b0, b1);
                mma16(cfr[1][j], af[1][0], af[1][1], af[1][2], af[1][3], b0, b1);
            }
        }
    }
    __syncthreads();

    #pragma unroll
    for (int f = 0; f < 2; f++) {
        int rbm = wm * 32 + f * 16 + g;
        #pragma unroll
        for (int j = 0; j < 4; j++) {
            int col = wn * 32 + j * 8 + 2 * t;
            Cs[(rbm    ) * 68 + col    ] = cfr[f][j][0];
            Cs[(rbm    ) * 68 + col + 1] = cfr[f][j][1];
            Cs[(rbm + 8) * 68 + col    ] = cfr[f][j][2];
            Cs[(rbm + 8) * 68 + col + 1] = cfr[f][j][3];
        }
    }
    __syncthreads();
    #pragma unroll
    for (int it = 0; it < 8; it++) {
        int id = tid + it * 256;
        int r = id >> 4, c4 = (id & 15) * 4;
        *(float4*)&out[(m0 + r) * 1024 + n0 + c4] = *(const float4*)&Cs[r * 68 + c4];
    }
}

// ---------------------------------------------------------------------------
// Launch.
// ---------------------------------------------------------------------------
extern "C" void kernel_launch(void* const* d_in, const int* in_sizes, int n_in,
                              void* d_out, int out_size)
{
    const float* X  = (const float*)d_in[0];
    const float* cs = (const float*)d_in[1];
    const float* sn = (const float*)d_in[2];
    // d_in[3] = attention_mask (all ones) — unused
    const float* Wq = (const float*)d_in[4];
    const float* Wk = (const float*)d_in[5];
    const float* Wv = (const float*)d_in[6];
    const float* Wo = (const float*)d_in[7];
    float* out = (float*)d_out;

    cvt_x_kernel<<<1024, 256>>>((const float4*)X);
    wt_kernel<<<2560, 256>>>(Wq, Wk, Wv, Wo);

    const size_t smem_gemm = 128 * 68 * sizeof(float);   // 34816 (> 2 stages 30720)
    cudaFuncSetAttribute(qkv_rope_kernel,
                         cudaFuncAttributeMaxDynamicSharedMemorySize, (int)smem_gemm);
    cudaFuncSetAttribute(oproj_kernel,
                         cudaFuncAttributeMaxDynamicSharedMemorySize, (int)smem_gemm);

    qkv_rope_kernel<<<dim3(24, 16), 256, smem_gemm>>>(cs, sn);

    // flash smem: QSP[128][72] + 2xK[64][72] + 2xV[64][72] halves = 55296 B
    const size_t smem_flash = (128 * 72 + 4 * 64 * 72) * sizeof(__half);
    cudaFuncSetAttribute(flash_kernel,
                         cudaFuncAttributeMaxDynamicSharedMemorySize, (int)smem_flash);
    flash_kernel<<<dim3(16, 16), 256, smem_flash>>>();

    oproj_kernel<<<dim3(16, 16), 256, smem_gemm>>>(out);
}

// round 15
// speedup vs baseline: 7.6475x; 1.0827x over previous
#include <cuda_runtime.h>
#include <cuda_fp16.h>
#include <math.h>
#include <stdint.h>

#define SEQ 2048
#define HID 1024
#define NH 16
#define NKV 4
#define HD 64
#define SCALING 0.125f
#define LOG2E 1.4426950408889634f

// ---------------------------------------------------------------------------
// Device globals (16B-aligned)
// ---------------------------------------------------------------------------
__device__ __align__(16) __half g_Qh[NH * SEQ * HD];    // [h][m][d], RoPE'd, *0.125*log2e
__device__ __align__(16) __half g_Kh[NKV * SEQ * HD];   // [kvh][m][d], RoPE'd
__device__ __align__(16) __half g_Vt[NKV * HD * SEQ];   // [kvh][d][m]  (TRANSPOSED)
__device__ __align__(16) __half g_AOh[SEQ * HID];       // [m][h*64+d]
__device__ __align__(16) __half g_Xh[SEQ * HID];        // [m][k]
__device__ __align__(16) __half g_WqT[1024 * HID];      // [n][k]
__device__ __align__(16) __half g_WkT[256 * HID];       // [n][k]
__device__ __align__(16) __half g_WvT[256 * HID];       // [n][k]
__device__ __align__(16) __half g_WoT[HID * 1024];      // [n][k]

// ---------------------------------------------------------------------------
// Helpers
// ---------------------------------------------------------------------------
__device__ __forceinline__ float ex2(float x) {
    float r;
    asm("ex2.approx.f32 %0, %1;" : "=f"(r) : "f"(x));
    return r;
}

__device__ __forceinline__ uint32_t pack_h2(float lo, float hi) {
    __half2 h = __floats2half2_rn(lo, hi);
    return *reinterpret_cast<uint32_t*>(&h);
}

__device__ __forceinline__ void mma16(float c[4],
                                      uint32_t a0, uint32_t a1, uint32_t a2, uint32_t a3,
                                      uint32_t b0, uint32_t b1) {
    asm volatile(
        "mma.sync.aligned.m16n8k16.row.col.f32.f16.f16.f32 "
        "{%0,%1,%2,%3}, {%4,%5,%6,%7}, {%8,%9}, {%0,%1,%2,%3};"
        : "+f"(c[0]), "+f"(c[1]), "+f"(c[2]), "+f"(c[3])
        : "r"(a0), "r"(a1), "r"(a2), "r"(a3), "r"(b0), "r"(b1));
}

__device__ __forceinline__ void cp16h(__half* smem_dst, const __half* gsrc) {
    uint32_t s = (uint32_t)__cvta_generic_to_shared(smem_dst);
    asm volatile("cp.async.ca.shared.global [%0], [%1], 16;" :: "r"(s), "l"(gsrc));
}

__device__ __forceinline__ uint32_t ldh2(const __half* p) {
    return *reinterpret_cast<const uint32_t*>(p);
}

// ldmatrix.x4: 4 8x8 b16 matrices; address lanes 8i..8i+7 feed matrix i.
__device__ __forceinline__ void ldsm4(uint32_t& r0, uint32_t& r1,
                                      uint32_t& r2, uint32_t& r3, const __half* p) {
    uint32_t a = (uint32_t)__cvta_generic_to_shared(p);
    asm volatile("ldmatrix.sync.aligned.m8n8.x4.shared.b16 {%0,%1,%2,%3}, [%4];"
                 : "=r"(r0), "=r"(r1), "=r"(r2), "=r"(r3) : "r"(a));
}

// ---------------------------------------------------------------------------
// Kernel 0: merged prep — X fp32->fp16 copy (blocks 0..1023) +
// weight transpose+convert (blocks 1024..3583).
// ---------------------------------------------------------------------------
__global__ __launch_bounds__(256) void prep_kernel(
    const float* __restrict__ Xf,
    const float* __restrict__ Wq, const float* __restrict__ Wk,
    const float* __restrict__ Wv, const float* __restrict__ Wo)
{
    __shared__ float tile[32][33];
    const int id = blockIdx.x;
    if (id < 1024) {
        const float4* X = (const float4*)Xf;
        const int i = id * 256 + threadIdx.x;
        float4 v0 = X[2 * i], v1 = X[2 * i + 1];
        uint4 o;
        o.x = pack_h2(v0.x, v0.y);
        o.y = pack_h2(v0.z, v0.w);
        o.z = pack_h2(v1.x, v1.y);
        o.w = pack_h2(v1.z, v1.w);
        *reinterpret_cast<uint4*>(&g_Xh[8 * i]) = o;
        return;
    }
    const int wid = id - 1024;                 // 0..2559
    const float* src; __half* dst; int ncols, local;
    if (wid < 1024)      { src = Wq; dst = g_WqT; ncols = 1024; local = wid; }
    else if (wid < 1280) { src = Wk; dst = g_WkT; ncols = 256;  local = wid - 1024; }
    else if (wid < 1536) { src = Wv; dst = g_WvT; ncols = 256;  local = wid - 1280; }
    else                 { src = Wo; dst = g_WoT; ncols = 1024; local = wid - 1536; }
    const int ntiles = ncols / 32;
    const int kb = (local / ntiles) * 32;
    const int nb = (local % ntiles) * 32;
    const int tx = threadIdx.x & 31;
    const int ty = threadIdx.x >> 5;
    #pragma unroll
    for (int j = 0; j < 4; j++)
        tile[ty + j * 8][tx] = src[(kb + ty + j * 8) * ncols + nb + tx];
    __syncthreads();
    #pragma unroll
    for (int j = 0; j < 4; j++)
        dst[(nb + ty + j * 8) * 1024 + kb + tx] = __float2half_rn(tile[tx][ty + j * 8]);
}

// ---------------------------------------------------------------------------
// Kernel 1: fused QKV projection + RoPE (fp16 m16n8k16 + ldmatrix).
// Block tile 128x64, BK=32, 8 warps (4m x 2n), warp tile 32x32.
// ---------------------------------------------------------------------------
#define QSTAGE_H (128 * 40 + 64 * 40)   // 7680 halves = 15360 B

__global__ __launch_bounds__(256, 3) void qkv_rope_kernel(
    const float* __restrict__ cs,
    const float* __restrict__ sn)
{
    const int n0g = blockIdx.x * 64;
    const int m0  = blockIdx.y * 128;

    const __half* Wt;
    int ncol0, kind;                       // 0=Q, 1=K, 2=V
    if (n0g < 1024)       { Wt = g_WqT; ncol0 = n0g;        kind = 0; }
    else if (n0g < 1280)  { Wt = g_WkT; ncol0 = n0g - 1024; kind = 1; }
    else                  { Wt = g_WvT; ncol0 = n0g - 1280; kind = 2; }

    extern __shared__ float dynf[];
    __half* dynh = (__half*)dynf;
    float* Cs = dynf;                      // [128][68] f32 epilogue staging

    const int tid  = threadIdx.x;
    const int lane = tid & 31, warp = tid >> 5;
    const int wm = warp & 3, wn = warp >> 2;
    const int g = lane >> 2, t = lane & 3;

    // ldmatrix address components
    const int rbase = lane & 7;
    const int arowoff = ((lane >> 3) & 1) * 8;   // A: matrix1/3 -> +8 rows
    const int akoff   = ((lane >> 4) & 1) * 8;   // A: matrix2/3 -> +8 k
    const int khalf   = ((lane >> 3) & 1) * 8;   // B: matrix1/3 -> +8 k
    const int jsel    = (lane >> 4) & 1;         // B: matrix2/3 -> next j

    const int aR[2] = { tid >> 2, (tid + 256) >> 2 };
    const int aC    = (tid & 3) * 8;
    const int bR    = tid >> 2;
    const int bC    = (tid & 3) * 8;

    float cfr[2][4][4] = {};

    {
        __half* As = dynh;  __half* Bs = dynh + 128 * 40;
        #pragma unroll
        for (int it = 0; it < 2; it++)
            cp16h(&As[aR[it] * 40 + aC], &g_Xh[(m0 + aR[it]) * 1024 + aC]);
        cp16h(&Bs[bR * 40 + bC], &Wt[(ncol0 + bR) * 1024 + bC]);
        asm volatile("cp.async.commit_group;");
    }

    #pragma unroll 2
    for (int k0 = 0; k0 < 1024; k0 += 32) {
        const int cur = (k0 >> 5) & 1;
        __half* As = dynh + (cur ? QSTAGE_H : 0);
        __half* Bs = As + 128 * 40;
        const bool has_next = (k0 + 32) < 1024;

        __syncthreads();
        if (has_next) {
            const int kn = k0 + 32;
            __half* Asn = dynh + (cur ? 0 : QSTAGE_H);
            __half* Bsn = Asn + 128 * 40;
            #pragma unroll
            for (int it = 0; it < 2; it++)
                cp16h(&Asn[aR[it] * 40 + aC], &g_Xh[(m0 + aR[it]) * 1024 + kn + aC]);
            cp16h(&Bsn[bR * 40 + bC], &Wt[(ncol0 + bR) * 1024 + kn + bC]);
            asm volatile("cp.async.commit_group;");
            asm volatile("cp.async.wait_group 1;" ::: "memory");
        } else {
            asm volatile("cp.async.wait_group 0;" ::: "memory");
        }
        __syncthreads();

        #pragma unroll
        for (int ks = 0; ks < 2; ks++) {
            const int kk = ks * 16;
            uint32_t af[2][4];
            #pragma unroll
            for (int f = 0; f < 2; f++)
                ldsm4(af[f][0], af[f][1], af[f][2], af[f][3],
                      &As[(wm * 32 + f * 16 + arowoff + rbase) * 40 + kk + akoff]);
            #pragma unroll
            for (int jp = 0; jp < 2; jp++) {
                uint32_t b00, b01, b10, b11;
                ldsm4(b00, b01, b10, b11,
                      &Bs[(wn * 32 + (jp * 2 + jsel) * 8 + rbase) * 40 + kk + khalf]);
                mma16(cfr[0][2 * jp    ], af[0][0], af[0][1], af[0][2], af[0][3], b00, b01);
                mma16(cfr[0][2 * jp + 1], af[0][0], af[0][1], af[0][2], af[0][3], b10, b11);
                mma16(cfr[1][2 * jp    ], af[1][0], af[1][1], af[1][2], af[1][3], b00, b01);
                mma16(cfr[1][2 * jp + 1], af[1][0], af[1][1], af[1][2], af[1][3], b10, b11);
            }
        }
    }
    __syncthreads();

    // fragments -> Cs (f32) for RoPE partner exchange
    #pragma unroll
    for (int f = 0; f < 2; f++) {
        int rbm = wm * 32 + f * 16 + g;
        #pragma unroll
        for (int j = 0; j < 4; j++) {
            int col = wn * 32 + j * 8 + 2 * t;
            Cs[(rbm    ) * 68 + col    ] = cfr[f][j][0];
            Cs[(rbm    ) * 68 + col + 1] = cfr[f][j][1];
            Cs[(rbm + 8) * 68 + col    ] = cfr[f][j][2];
            Cs[(rbm + 8) * 68 + col + 1] = cfr[f][j][3];
        }
    }
    __syncthreads();

    const int head_local = (kind == 0) ? (n0g >> 6) : (ncol0 >> 6);
    const int r0e = (tid >> 4) * 8;
    const int c0e = (tid & 15) * 4;
    const bool lowhalf = (c0e < 32);
    const float qscale = SCALING * LOG2E;

    #pragma unroll
    for (int i = 0; i < 8; i++) {
        const int r = r0e + i;
        const int m = m0 + r;
        float4 val = *(const float4*)&Cs[r * 68 + c0e];
        float4 outv;
        if (kind == 2) {
            outv = val;
        } else {
            float4 par = lowhalf ? *(const float4*)&Cs[r * 68 + c0e + 32]
                                 : *(const float4*)&Cs[r * 68 + c0e - 32];
            float psgn = lowhalf ? -1.0f : 1.0f;
            float4 c4 = *(const float4*)&cs[m * HD + c0e];
            float4 s4 = *(const float4*)&sn[m * HD + c0e];
            outv.x = val.x * c4.x + psgn * par.x * s4.x;
            outv.y = val.y * c4.y + psgn * par.y * s4.y;
            outv.z = val.z * c4.z + psgn * par.z * s4.z;
            outv.w = val.w * c4.w + psgn * par.w * s4.w;
            if (kind == 0) {
                outv.x *= qscale; outv.y *= qscale;
                outv.z *= qscale; outv.w *= qscale;
            }
        }
        if (kind == 2) {
            __half* vb = g_Vt + head_local * HD * SEQ;
            vb[(c0e + 0) * SEQ + m] = __float2half_rn(outv.x);
            vb[(c0e + 1) * SEQ + m] = __float2half_rn(outv.y);
            vb[(c0e + 2) * SEQ + m] = __float2half_rn(outv.z);
            vb[(c0e + 3) * SEQ + m] = __float2half_rn(outv.w);
        } else {
            uint2 o;
            o.x = pack_h2(outv.x, outv.y);
            o.y = pack_h2(outv.z, outv.w);
            __half* dstb = (kind == 0) ? g_Qh : g_Kh;
            *reinterpret_cast<uint2*>(&dstb[head_local * SEQ * HD + m * HD + c0e]) = o;
        }
    }
}

// ---------------------------------------------------------------------------
// Flash per-KV-tile body (fp16 MMA + ldmatrix, f32 softmax in exp2 domain).
// ---------------------------------------------------------------------------
__device__ __forceinline__ void flash_tile(
    const __half* Ks, const __half* Vs,
    __half* Kn, __half* Vn, bool prefetch,
    const __half* Kgn, const __half* Vgn,
    const int* kvR, const int* kvC,
    const uint32_t (*qfr)[4], float (*ofr)[4],
    float& m1, float& m2, float& l1, float& l2,
    __half* QSP, int rw, int g, int t,
    int rbase, int arowoff, int akoff, int khalf, int jsel)
{
    asm volatile("cp.async.wait_group 0;" ::: "memory");
    __syncthreads();

    if (prefetch) {
        #pragma unroll
        for (int it = 0; it < 2; it++) {
            cp16h(&Kn[kvR[it] * 72 + kvC[it]], &Kgn[kvR[it] * 64 + kvC[it]]);
            cp16h(&Vn[kvR[it] * 72 + kvC[it]], &Vgn[kvR[it] * SEQ + kvC[it]]);
        }
        asm volatile("cp.async.commit_group;");
    }

    // S = Q @ K^T : k = d (64) -> 4 k16 steps; B frags via ldmatrix (2 j/op)
    float sfr[8][4] = {};
    #pragma unroll
    for (int ks = 0; ks < 4; ks++) {
        const int kk = ks * 16;
        #pragma unroll
        for (int jp = 0; jp < 4; jp++) {
            uint32_t b00, b01, b10, b11;
            ldsm4(b00, b01, b10, b11,
                  &Ks[((jp * 2 + jsel) * 8 + rbase) * 72 + kk + khalf]);
            mma16(sfr[2 * jp    ], qfr[ks][0], qfr[ks][1], qfr[ks][2], qfr[ks][3], b00, b01);
            mma16(sfr[2 * jp + 1], qfr[ks][0], qfr[ks][1], qfr[ks][2], qfr[ks][3], b10, b11);
        }
    }

    // register online softmax (rows rw+g, rw+g+8), exp2 domain
    float mloc1 = -INFINITY, mloc2 = -INFINITY;
    #pragma unroll
    for (int j = 0; j < 8; j++) {
        mloc1 = fmaxf(mloc1, fmaxf(sfr[j][0], sfr[j][1]));
        mloc2 = fmaxf(mloc2, fmaxf(sfr[j][2], sfr[j][3]));
    }
    mloc1 = fmaxf(mloc1, __shfl_xor_sync(0xffffffffu, mloc1, 1));
    mloc1 = fmaxf(mloc1, __shfl_xor_sync(0xffffffffu, mloc1, 2));
    mloc2 = fmaxf(mloc2, __shfl_xor_sync(0xffffffffu, mloc2, 1));
    mloc2 = fmaxf(mloc2, __shfl_xor_sync(0xffffffffu, mloc2, 2));
    float mnew1 = fmaxf(m1, mloc1);
    float mnew2 = fmaxf(m2, mloc2);
    float sc1 = ex2(m1 - mnew1);   // first tile: ex2(-inf)=0
    float sc2 = ex2(m2 - mnew2);
    float ss1 = 0.0f, ss2 = 0.0f;
    #pragma unroll
    for (int j = 0; j < 8; j++) {
        sfr[j][0] = ex2(sfr[j][0] - mnew1); ss1 += sfr[j][0];
        sfr[j][1] = ex2(sfr[j][1] - mnew1); ss1 += sfr[j][1];
        sfr[j][2] = ex2(sfr[j][2] - mnew2); ss2 += sfr[j][2];
        sfr[j][3] = ex2(sfr[j][3] - mnew2); ss2 += sfr[j][3];
    }
    ss1 += __shfl_xor_sync(0xffffffffu, ss1, 1);
    ss1 += __shfl_xor_sync(0xffffffffu, ss1, 2);
    ss2 += __shfl_xor_sync(0xffffffffu, ss2, 1);
    ss2 += __shfl_xor_sync(0xffffffffu, ss2, 2);
    l1 = l1 * sc1 + ss1;  m1 = mnew1;
    l2 = l2 * sc2 + ss2;  m2 = mnew2;

    #pragma unroll
    for (int j = 0; j < 8; j++) {
        ofr[j][0] *= sc1; ofr[j][1] *= sc1;
        ofr[j][2] *= sc2; ofr[j][3] *= sc2;
    }

    // P -> QSP as packed half2 (own rows only)
    #pragma unroll
    for (int j = 0; j < 8; j++) {
        int col = j * 8 + 2 * t;
        *reinterpret_cast<uint32_t*>(&QSP[(rw + g    ) * 72 + col]) = pack_h2(sfr[j][0], sfr[j][1]);
        *reinterpret_cast<uint32_t*>(&QSP[(rw + g + 8) * 72 + col]) = pack_h2(sfr[j][2], sfr[j][3]);
    }
    __syncwarp();

    // O += P @ V^T : A frags (P) + B frags (V) via ldmatrix
    #pragma unroll
    for (int ks = 0; ks < 4; ks++) {
        const int kk = ks * 16;
        uint32_t a0, a1, a2, a3;
        ldsm4(a0, a1, a2, a3, &QSP[(rw + arowoff + rbase) * 72 + kk + akoff]);
        #pragma unroll
        for (int jp = 0; jp < 4; jp++) {
            uint32_t b00, b01, b10, b11;
            ldsm4(b00, b01, b10, b11,
                  &Vs[((jp * 2 + jsel) * 8 + rbase) * 72 + kk + khalf]);
            mma16(ofr[2 * jp    ], a0, a1, a2, a3, b00, b01);
            mma16(ofr[2 * jp + 1], a0, a1, a2, a3, b10, b11);
        }
    }
}

// ---------------------------------------------------------------------------
// Kernel 2: flash attention (fp16 MMA + ldmatrix), warp-exclusive rows,
// register softmax, cp.async 2-stage KV pipeline, manual unroll-2.
// ---------------------------------------------------------------------------
__global__ __launch_bounds__(256, 2) void flash_kernel()
{
    const int q0  = blockIdx.x * 128;
    const int h   = blockIdx.y;
    const int kvh = h >> 2;

    extern __shared__ __half smh[];
    __half* QSP = smh;                    // [128][72]
    __half* K0  = smh + 128 * 72;
    __half* K1  = K0 + 64 * 72;
    __half* V0  = K1 + 64 * 72;
    __half* V1  = V0 + 64 * 72;

    const int tid  = threadIdx.x;
    const int lane = tid & 31, warp = tid >> 5;
    const int g = lane >> 2, t = lane & 3;
    const int rw = warp * 16;

    const int rbase = lane & 7;
    const int arowoff = ((lane >> 3) & 1) * 8;
    const int akoff   = ((lane >> 4) & 1) * 8;
    const int khalf   = ((lane >> 3) & 1) * 8;
    const int jsel    = (lane >> 4) & 1;

    const __half* Qg = g_Qh + h * SEQ * HD + q0 * HD;
    const __half* Kg = g_Kh + kvh * SEQ * HD;
    const __half* Vg = g_Vt + kvh * HD * SEQ;   // [d][m]

    // KV staging: 512 chunks of 8 halves -> 2 per thread
    const int kvR[2] = { tid >> 3, (tid + 256) >> 3 };
    const int kvC[2] = { (tid & 7) * 8, ((tid + 256) & 7) * 8 };

    #pragma unroll
    for (int it = 0; it < 4; it++) {
        int id = tid + it * 256;
        int r = id >> 3, c8 = (id & 7) * 8;
        *(uint4*)&QSP[r * 72 + c8] = *(const uint4*)&Qg[r * 64 + c8];
    }
    __syncthreads();
    uint32_t qfr[4][4];
    #pragma unroll
    for (int ks = 0; ks < 4; ks++) {
        const int kk = ks * 16;
        ldsm4(qfr[ks][0], qfr[ks][1], qfr[ks][2], qfr[ks][3],
              &QSP[(rw + arowoff + rbase) * 72 + kk + akoff]);
    }

    #pragma unroll
    for (int it = 0; it < 2; it++) {
        cp16h(&K0[kvR[it] * 72 + kvC[it]], &Kg[kvR[it] * 64 + kvC[it]]);
        cp16h(&V0[kvR[it] * 72 + kvC[it]], &Vg[kvR[it] * SEQ + kvC[it]]);
    }
    asm volatile("cp.async.commit_group;");

    float m1 = -INFINITY, m2 = -INFINITY, l1 = 0.0f, l2 = 0.0f;
    float ofr[8][4] = {};

    for (int ktp = 0; ktp < 16; ktp++) {
        const int kt0 = 2 * ktp;
        flash_tile(K0, V0, K1, V1, true,
                   Kg + (kt0 + 1) * 64 * 64, Vg + (kt0 + 1) * 64,
                   kvR, kvC, qfr, ofr, m1, m2, l1, l2, QSP, rw, g, t,
                   rbase, arowoff, akoff, khalf, jsel);
        const bool more = (kt0 + 2) < 32;
        const __half* Kgn = Kg + (more ? (kt0 + 2) * 64 * 64 : 0);
        const __half* Vgn = Vg + (more ? (kt0 + 2) * 64 : 0);
        flash_tile(K1, V1, K0, V0, more,
                   Kgn, Vgn, kvR, kvC, qfr, ofr, m1, m2, l1, l2, QSP, rw, g, t,
                   rbase, arowoff, akoff, khalf, jsel);
    }

    float inv1 = 1.0f / l1;
    float inv2 = 1.0f / l2;
    __syncthreads();
    #pragma unroll
    for (int j = 0; j < 8; j++) {
        int col = j * 8 + 2 * t;
        *reinterpret_cast<uint32_t*>(&QSP[(rw + g    ) * 72 + col]) =
            pack_h2(ofr[j][0] * inv1, ofr[j][1] * inv1);
        *reinterpret_cast<uint32_t*>(&QSP[(rw + g + 8) * 72 + col]) =
            pack_h2(ofr[j][2] * inv2, ofr[j][3] * inv2);
    }
    __syncthreads();
    #pragma unroll
    for (int it = 0; it < 4; it++) {
        int id = tid + it * 256;
        int r = id >> 3, c8 = (id & 7) * 8;
        *(uint4*)&g_AOh[(q0 + r) * 1024 + h * 64 + c8] = *(const uint4*)&QSP[r * 72 + c8];
    }
}

// ---------------------------------------------------------------------------
// Kernel 3: output projection (fp16 m16n8k16 + ldmatrix), cp.async 2-stage.
// ---------------------------------------------------------------------------
__global__ __launch_bounds__(256, 3) void oproj_kernel(float* __restrict__ out)
{
    const int n0 = blockIdx.x * 64;
    const int m0 = blockIdx.y * 128;

    extern __shared__ float dynf[];
    __half* dynh = (__half*)dynf;
    float* Cs = dynf;

    const int tid  = threadIdx.x;
    const int lane = tid & 31, warp = tid >> 5;
    const int wm = warp & 3, wn = warp >> 2;
    const int g = lane >> 2, t = lane & 3;

    const int rbase = lane & 7;
    const int arowoff = ((lane >> 3) & 1) * 8;
    const int akoff   = ((lane >> 4) & 1) * 8;
    const int khalf   = ((lane >> 3) & 1) * 8;
    const int jsel    = (lane >> 4) & 1;

    const int aR[2] = { tid >> 2, (tid + 256) >> 2 };
    const int aC    = (tid & 3) * 8;
    const int bR    = tid >> 2;
    const int bC    = (tid & 3) * 8;

    float cfr[2][4][4] = {};

    {
        __half* As = dynh;  __half* Bs = dynh + 128 * 40;
        #pragma unroll
        for (int it = 0; it < 2; it++)
            cp16h(&As[aR[it] * 40 + aC], &g_AOh[(m0 + aR[it]) * 1024 + aC]);
        cp16h(&Bs[bR * 40 + bC], &g_WoT[(n0 + bR) * 1024 + bC]);
        asm volatile("cp.async.commit_group;");
    }

    #pragma unroll 2
    for (int k0 = 0; k0 < 1024; k0 += 32) {
        const int cur = (k0 >> 5) & 1;
        __half* As = dynh + (cur ? QSTAGE_H : 0);
        __half* Bs = As + 128 * 40;
        const bool has_next = (k0 + 32) < 1024;

        __syncthreads();
        if (has_next) {
            const int kn = k0 + 32;
            __half* Asn = dynh + (cur ? 0 : QSTAGE_H);
            __half* Bsn = Asn + 128 * 40;
            #pragma unroll
            for (int it = 0; it < 2; it++)
                cp16h(&Asn[aR[it] * 40 + aC], &g_AOh[(m0 + aR[it]) * 1024 + kn + aC]);
            cp16h(&Bsn[bR * 40 + bC], &g_WoT[(n0 + bR) * 1024 + kn + bC]);
            asm volatile("cp.async.commit_group;");
            asm volatile("cp.async.wait_group 1;" ::: "memory");
        } else {
            asm volatile("cp.async.wait_group 0;" ::: "memory");
        }
        __syncthreads();

        #pragma unroll
        for (int ks = 0; ks < 2; ks++) {
            const int kk = ks * 16;
            uint32_t af[2][4];
            #pragma unroll
            for (int f = 0; f < 2; f++)
                ldsm4(af[f][0], af[f][1], af[f][2], af[f][3],
                      &As[(wm * 32 + f * 16 + arowoff + rbase) * 40 + kk + akoff]);
            #pragma unroll
            for (int jp = 0; jp < 2; jp++) {
                uint32_t b00, b01, b10, b11;
                ldsm4(b00, b01, b10, b11,
                      &Bs[(wn * 32 + (jp * 2 + jsel) * 8 + rbase) * 40 + kk + khalf]);
                mma16(cfr[0][2 * jp    ], af[0][0], af[0][1], af[0][2], af[0][3], b00, b01);
                mma16(cfr[0][2 * jp + 1], af[0][0], af[0][1], af[0][2], af[0][3], b10, b11);
                mma16(cfr[1][2 * jp    ], af[1][0], af[1][1], af[1][2], af[1][3], b00, b01);
                mma16(cfr[1][2 * jp + 1], af[1][0], af[1][1], af[1][2], af[1][3], b10, b11);
            }
        }
    }
    __syncthreads();

    #pragma unroll
    for (int f = 0; f < 2; f++) {
        int rbm = wm * 32 + f * 16 + g;
        #pragma unroll
        for (int j = 0; j < 4; j++) {
            int col = wn * 32 + j * 8 + 2 * t;
            Cs[(rbm    ) * 68 + col    ] = cfr[f][j][0];
            Cs[(rbm    ) * 68 + col + 1] = cfr[f][j][1];
            Cs[(rbm + 8) * 68 + col    ] = cfr[f][j][2];
            Cs[(rbm + 8) * 68 + col + 1] = cfr[f][j][3];
        }
    }
    __syncthreads();
    #pragma unroll
    for (int it = 0; it < 8; it++) {
        int id = tid + it * 256;
        int r = id >> 4, c4 = (id & 15) * 4;
        *(float4*)&out[(m0 + r) * 1024 + n0 + c4] = *(const float4*)&Cs[r * 68 + c4];
    }
}

// ---------------------------------------------------------------------------
// Launch.
// ---------------------------------------------------------------------------
extern "C" void kernel_launch(void* const* d_in, const int* in_sizes, int n_in,
                              void* d_out, int out_size)
{
    const float* X  = (const float*)d_in[0];
    const float* cs = (const float*)d_in[1];
    const float* sn = (const float*)d_in[2];
    // d_in[3] = attention_mask (all ones) — unused
    const float* Wq = (const float*)d_in[4];
    const float* Wk = (const float*)d_in[5];
    const float* Wv = (const float*)d_in[6];
    const float* Wo = (const float*)d_in[7];
    float* out = (float*)d_out;

    prep_kernel<<<3584, 256>>>(X, Wq, Wk, Wv, Wo);

    const size_t smem_gemm = 128 * 68 * sizeof(float);   // 34816 (> 2 stages 30720)
    cudaFuncSetAttribute(qkv_rope_kernel,
                         cudaFuncAttributeMaxDynamicSharedMemorySize, (int)smem_gemm);
    cudaFuncSetAttribute(oproj_kernel,
                         cudaFuncAttributeMaxDynamicSharedMemorySize, (int)smem_gemm);

    qkv_rope_kernel<<<dim3(24, 16), 256, smem_gemm>>>(cs, sn);

    const size_t smem_flash = (128 * 72 + 4 * 64 * 72) * sizeof(__half);  // 55296 B
    cudaFuncSetAttribute(flash_kernel,
                         cudaFuncAttributeMaxDynamicSharedMemorySize, (int)smem_flash);
    flash_kernel<<<dim3(16, 16), 256, smem_flash>>>();

    oproj_kernel<<<dim3(16, 16), 256, smem_gemm>>>(out);
}

// round 16
// speedup vs baseline: 8.2453x; 1.0782x over previous
#include <cuda_runtime.h>
#include <cuda_fp16.h>
#include <math.h>
#include <stdint.h>

#define SEQ 2048
#define HID 1024
#define NH 16
#define NKV 4
#define HD 64
#define SCALING 0.125f
#define LOG2E 1.4426950408889634f

// ---------------------------------------------------------------------------
// Device globals (16B-aligned)
// ---------------------------------------------------------------------------
__device__ __align__(16) __half g_Qh[NH * SEQ * HD];    // [h][m][d], RoPE'd, *0.125*log2e
__device__ __align__(16) __half g_Kh[NKV * SEQ * HD];   // [kvh][m][d], RoPE'd
__device__ __align__(16) __half g_Vt[NKV * HD * SEQ];   // [kvh][d][m]  (TRANSPOSED)
__device__ __align__(16) __half g_AOh[SEQ * HID];       // [m][h*64+d]
__device__ __align__(16) __half g_Xh[SEQ * HID];        // [m][k]
__device__ __align__(16) __half g_WqT[1024 * HID];      // [n][k]
__device__ __align__(16) __half g_WkT[256 * HID];       // [n][k]
__device__ __align__(16) __half g_WvT[256 * HID];       // [n][k]
__device__ __align__(16) __half g_WoT[HID * 1024];      // [n][k]

// ---------------------------------------------------------------------------
// Helpers
// ---------------------------------------------------------------------------
__device__ __forceinline__ float ex2(float x) {
    float r;
    asm("ex2.approx.f32 %0, %1;" : "=f"(r) : "f"(x));
    return r;
}

__device__ __forceinline__ uint32_t pack_h2(float lo, float hi) {
    __half2 h = __floats2half2_rn(lo, hi);
    return *reinterpret_cast<uint32_t*>(&h);
}

__device__ __forceinline__ void mma16(float c[4],
                                      uint32_t a0, uint32_t a1, uint32_t a2, uint32_t a3,
                                      uint32_t b0, uint32_t b1) {
    asm volatile(
        "mma.sync.aligned.m16n8k16.row.col.f32.f16.f16.f32 "
        "{%0,%1,%2,%3}, {%4,%5,%6,%7}, {%8,%9}, {%0,%1,%2,%3};"
        : "+f"(c[0]), "+f"(c[1]), "+f"(c[2]), "+f"(c[3])
        : "r"(a0), "r"(a1), "r"(a2), "r"(a3), "r"(b0), "r"(b1));
}

__device__ __forceinline__ void cp16h(__half* smem_dst, const __half* gsrc) {
    uint32_t s = (uint32_t)__cvta_generic_to_shared(smem_dst);
    asm volatile("cp.async.ca.shared.global [%0], [%1], 16;" :: "r"(s), "l"(gsrc));
}

// ldmatrix.x4: 4 8x8 b16 matrices; address lanes 8i..8i+7 feed matrix i.
__device__ __forceinline__ void ldsm4(uint32_t& r0, uint32_t& r1,
                                      uint32_t& r2, uint32_t& r3, const __half* p) {
    uint32_t a = (uint32_t)__cvta_generic_to_shared(p);
    asm volatile("ldmatrix.sync.aligned.m8n8.x4.shared.b16 {%0,%1,%2,%3}, [%4];"
                 : "=r"(r0), "=r"(r1), "=r"(r2), "=r"(r3) : "r"(a));
}

// ---------------------------------------------------------------------------
// Kernel 0: merged prep — X fp32->fp16 copy (blocks 0..1023) +
// weight transpose+convert (blocks 1024..3583).
// ---------------------------------------------------------------------------
__global__ __launch_bounds__(256) void prep_kernel(
    const float* __restrict__ Xf,
    const float* __restrict__ Wq, const float* __restrict__ Wk,
    const float* __restrict__ Wv, const float* __restrict__ Wo)
{
    __shared__ float tile[32][33];
    const int id = blockIdx.x;
    if (id < 1024) {
        const float4* X = (const float4*)Xf;
        const int i = id * 256 + threadIdx.x;
        float4 v0 = X[2 * i], v1 = X[2 * i + 1];
        uint4 o;
        o.x = pack_h2(v0.x, v0.y);
        o.y = pack_h2(v0.z, v0.w);
        o.z = pack_h2(v1.x, v1.y);
        o.w = pack_h2(v1.z, v1.w);
        *reinterpret_cast<uint4*>(&g_Xh[8 * i]) = o;
        return;
    }
    const int wid = id - 1024;                 // 0..2559
    const float* src; __half* dst; int ncols, local;
    if (wid < 1024)      { src = Wq; dst = g_WqT; ncols = 1024; local = wid; }
    else if (wid < 1280) { src = Wk; dst = g_WkT; ncols = 256;  local = wid - 1024; }
    else if (wid < 1536) { src = Wv; dst = g_WvT; ncols = 256;  local = wid - 1280; }
    else                 { src = Wo; dst = g_WoT; ncols = 1024; local = wid - 1536; }
    const int ntiles = ncols / 32;
    const int kb = (local / ntiles) * 32;
    const int nb = (local % ntiles) * 32;
    const int tx = threadIdx.x & 31;
    const int ty = threadIdx.x >> 5;
    #pragma unroll
    for (int j = 0; j < 4; j++)
        tile[ty + j * 8][tx] = src[(kb + ty + j * 8) * ncols + nb + tx];
    __syncthreads();
    #pragma unroll
    for (int j = 0; j < 4; j++)
        dst[(nb + ty + j * 8) * 1024 + kb + tx] = __float2half_rn(tile[tx][ty + j * 8]);
}

// ---------------------------------------------------------------------------
// Kernel 1: fused QKV projection + RoPE (fp16 m16n8k16 + ldmatrix).
// Block tile 128x64, BK=32, 8 warps (4m x 2n), warp tile 32x32.
// ONE barrier per k-iter: wait -> sync -> prefetch(k+1) -> MMA(k).
// ---------------------------------------------------------------------------
#define QSTAGE_H (128 * 40 + 64 * 40)   // 7680 halves = 15360 B

__global__ __launch_bounds__(256, 3) void qkv_rope_kernel(
    const float* __restrict__ cs,
    const float* __restrict__ sn)
{
    const int n0g = blockIdx.x * 64;
    const int m0  = blockIdx.y * 128;

    const __half* Wt;
    int ncol0, kind;                       // 0=Q, 1=K, 2=V
    if (n0g < 1024)       { Wt = g_WqT; ncol0 = n0g;        kind = 0; }
    else if (n0g < 1280)  { Wt = g_WkT; ncol0 = n0g - 1024; kind = 1; }
    else                  { Wt = g_WvT; ncol0 = n0g - 1280; kind = 2; }

    extern __shared__ float dynf[];
    __half* dynh = (__half*)dynf;
    float* Cs = dynf;                      // [128][68] f32 epilogue staging

    const int tid  = threadIdx.x;
    const int lane = tid & 31, warp = tid >> 5;
    const int wm = warp & 3, wn = warp >> 2;
    const int g = lane >> 2, t = lane & 3;

    const int rbase = lane & 7;
    const int arowoff = ((lane >> 3) & 1) * 8;
    const int akoff   = ((lane >> 4) & 1) * 8;
    const int khalf   = ((lane >> 3) & 1) * 8;
    const int jsel    = (lane >> 4) & 1;

    const int aR[2] = { tid >> 2, (tid + 256) >> 2 };
    const int aC    = (tid & 3) * 8;
    const int bR    = tid >> 2;
    const int bC    = (tid & 3) * 8;

    float cfr[2][4][4] = {};

    {
        __half* As = dynh;  __half* Bs = dynh + 128 * 40;
        #pragma unroll
        for (int it = 0; it < 2; it++)
            cp16h(&As[aR[it] * 40 + aC], &g_Xh[(m0 + aR[it]) * 1024 + aC]);
        cp16h(&Bs[bR * 40 + bC], &Wt[(ncol0 + bR) * 1024 + bC]);
        asm volatile("cp.async.commit_group;");
    }

    #pragma unroll 2
    for (int k0 = 0; k0 < 1024; k0 += 32) {
        const int cur = (k0 >> 5) & 1;
        __half* As = dynh + (cur ? QSTAGE_H : 0);
        __half* Bs = As + 128 * 40;
        const bool has_next = (k0 + 32) < 1024;

        asm volatile("cp.async.wait_group 0;" ::: "memory");
        __syncthreads();   // stage k visible to all; all MMA(k-1) complete

        if (has_next) {
            const int kn = k0 + 32;
            __half* Asn = dynh + (cur ? 0 : QSTAGE_H);
            __half* Bsn = Asn + 128 * 40;
            #pragma unroll
            for (int it = 0; it < 2; it++)
                cp16h(&Asn[aR[it] * 40 + aC], &g_Xh[(m0 + aR[it]) * 1024 + kn + aC]);
            cp16h(&Bsn[bR * 40 + bC], &Wt[(ncol0 + bR) * 1024 + kn + bC]);
            asm volatile("cp.async.commit_group;");
        }

        #pragma unroll
        for (int ks = 0; ks < 2; ks++) {
            const int kk = ks * 16;
            uint32_t af[2][4];
            #pragma unroll
            for (int f = 0; f < 2; f++)
                ldsm4(af[f][0], af[f][1], af[f][2], af[f][3],
                      &As[(wm * 32 + f * 16 + arowoff + rbase) * 40 + kk + akoff]);
            #pragma unroll
            for (int jp = 0; jp < 2; jp++) {
                uint32_t b00, b01, b10, b11;
                ldsm4(b00, b01, b10, b11,
                      &Bs[(wn * 32 + (jp * 2 + jsel) * 8 + rbase) * 40 + kk + khalf]);
                mma16(cfr[0][2 * jp    ], af[0][0], af[0][1], af[0][2], af[0][3], b00, b01);
                mma16(cfr[0][2 * jp + 1], af[0][0], af[0][1], af[0][2], af[0][3], b10, b11);
                mma16(cfr[1][2 * jp    ], af[1][0], af[1][1], af[1][2], af[1][3], b00, b01);
                mma16(cfr[1][2 * jp + 1], af[1][0], af[1][1], af[1][2], af[1][3], b10, b11);
            }
        }
    }
    __syncthreads();

    // fragments -> Cs (f32) for RoPE partner exchange
    #pragma unroll
    for (int f = 0; f < 2; f++) {
        int rbm = wm * 32 + f * 16 + g;
        #pragma unroll
        for (int j = 0; j < 4; j++) {
            int col = wn * 32 + j * 8 + 2 * t;
            Cs[(rbm    ) * 68 + col    ] = cfr[f][j][0];
            Cs[(rbm    ) * 68 + col + 1] = cfr[f][j][1];
            Cs[(rbm + 8) * 68 + col    ] = cfr[f][j][2];
            Cs[(rbm + 8) * 68 + col + 1] = cfr[f][j][3];
        }
    }
    __syncthreads();

    const int head_local = (kind == 0) ? (n0g >> 6) : (ncol0 >> 6);
    const int r0e = (tid >> 4) * 8;
    const int c0e = (tid & 15) * 4;
    const bool lowhalf = (c0e < 32);
    const float qscale = SCALING * LOG2E;

    #pragma unroll
    for (int i = 0; i < 8; i++) {
        const int r = r0e + i;
        const int m = m0 + r;
        float4 val = *(const float4*)&Cs[r * 68 + c0e];
        float4 outv;
        if (kind == 2) {
            outv = val;
        } else {
            float4 par = lowhalf ? *(const float4*)&Cs[r * 68 + c0e + 32]
                                 : *(const float4*)&Cs[r * 68 + c0e - 32];
            float psgn = lowhalf ? -1.0f : 1.0f;
            float4 c4 = *(const float4*)&cs[m * HD + c0e];
            float4 s4 = *(const float4*)&sn[m * HD + c0e];
            outv.x = val.x * c4.x + psgn * par.x * s4.x;
            outv.y = val.y * c4.y + psgn * par.y * s4.y;
            outv.z = val.z * c4.z + psgn * par.z * s4.z;
            outv.w = val.w * c4.w + psgn * par.w * s4.w;
            if (kind == 0) {
                outv.x *= qscale; outv.y *= qscale;
                outv.z *= qscale; outv.w *= qscale;
            }
        }
        if (kind == 2) {
            __half* vb = g_Vt + head_local * HD * SEQ;
            vb[(c0e + 0) * SEQ + m] = __float2half_rn(outv.x);
            vb[(c0e + 1) * SEQ + m] = __float2half_rn(outv.y);
            vb[(c0e + 2) * SEQ + m] = __float2half_rn(outv.z);
            vb[(c0e + 3) * SEQ + m] = __float2half_rn(outv.w);
        } else {
            uint2 o;
            o.x = pack_h2(outv.x, outv.y);
            o.y = pack_h2(outv.z, outv.w);
            __half* dstb = (kind == 0) ? g_Qh : g_Kh;
            *reinterpret_cast<uint2*>(&dstb[head_local * SEQ * HD + m * HD + c0e]) = o;
        }
    }
}

// ---------------------------------------------------------------------------
// Flash per-KV-tile body. FA2 register P-reuse: S fragments feed PV A operands
// directly (c-layout == A-layout for same 16 rows) — no P smem round trip.
// ---------------------------------------------------------------------------
__device__ __forceinline__ void flash_tile(
    const __half* Ks, const __half* Vs,
    __half* Kn, __half* Vn, bool prefetch,
    const __half* Kgn, const __half* Vgn,
    const int* kvR, const int* kvC,
    const uint32_t (*qfr)[4], float (*ofr)[4],
    float& m1, float& m2, float& l1, float& l2,
    int rbase, int khalf, int jsel)
{
    asm volatile("cp.async.wait_group 0;" ::: "memory");
    __syncthreads();

    if (prefetch) {
        #pragma unroll
        for (int it = 0; it < 2; it++) {
            cp16h(&Kn[kvR[it] * 72 + kvC[it]], &Kgn[kvR[it] * 64 + kvC[it]]);
            cp16h(&Vn[kvR[it] * 72 + kvC[it]], &Vgn[kvR[it] * SEQ + kvC[it]]);
        }
        asm volatile("cp.async.commit_group;");
    }

    // S = Q @ K^T
    float sfr[8][4] = {};
    #pragma unroll
    for (int ks = 0; ks < 4; ks++) {
        const int kk = ks * 16;
        #pragma unroll
        for (int jp = 0; jp < 4; jp++) {
            uint32_t b00, b01, b10, b11;
            ldsm4(b00, b01, b10, b11,
                  &Ks[((jp * 2 + jsel) * 8 + rbase) * 72 + kk + khalf]);
            mma16(sfr[2 * jp    ], qfr[ks][0], qfr[ks][1], qfr[ks][2], qfr[ks][3], b00, b01);
            mma16(sfr[2 * jp + 1], qfr[ks][0], qfr[ks][1], qfr[ks][2], qfr[ks][3], b10, b11);
        }
    }

    // register online softmax (rows rw+g, rw+g+8), exp2 domain
    float mloc1 = -INFINITY, mloc2 = -INFINITY;
    #pragma unroll
    for (int j = 0; j < 8; j++) {
        mloc1 = fmaxf(mloc1, fmaxf(sfr[j][0], sfr[j][1]));
        mloc2 = fmaxf(mloc2, fmaxf(sfr[j][2], sfr[j][3]));
    }
    mloc1 = fmaxf(mloc1, __shfl_xor_sync(0xffffffffu, mloc1, 1));
    mloc1 = fmaxf(mloc1, __shfl_xor_sync(0xffffffffu, mloc1, 2));
    mloc2 = fmaxf(mloc2, __shfl_xor_sync(0xffffffffu, mloc2, 1));
    mloc2 = fmaxf(mloc2, __shfl_xor_sync(0xffffffffu, mloc2, 2));
    float mnew1 = fmaxf(m1, mloc1);
    float mnew2 = fmaxf(m2, mloc2);
    float sc1 = ex2(m1 - mnew1);   // first tile: ex2(-inf)=0
    float sc2 = ex2(m2 - mnew2);
    float ss1 = 0.0f, ss2 = 0.0f;
    #pragma unroll
    for (int j = 0; j < 8; j++) {
        sfr[j][0] = ex2(sfr[j][0] - mnew1); ss1 += sfr[j][0];
        sfr[j][1] = ex2(sfr[j][1] - mnew1); ss1 += sfr[j][1];
        sfr[j][2] = ex2(sfr[j][2] - mnew2); ss2 += sfr[j][2];
        sfr[j][3] = ex2(sfr[j][3] - mnew2); ss2 += sfr[j][3];
    }
    ss1 += __shfl_xor_sync(0xffffffffu, ss1, 1);
    ss1 += __shfl_xor_sync(0xffffffffu, ss1, 2);
    ss2 += __shfl_xor_sync(0xffffffffu, ss2, 1);
    ss2 += __shfl_xor_sync(0xffffffffu, ss2, 2);
    l1 = l1 * sc1 + ss1;  m1 = mnew1;
    l2 = l2 * sc2 + ss2;  m2 = mnew2;

    #pragma unroll
    for (int j = 0; j < 8; j++) {
        ofr[j][0] *= sc1; ofr[j][1] *= sc1;
        ofr[j][2] *= sc2; ofr[j][3] *= sc2;
    }

    // O += P @ V^T — P A-fragments packed straight from sfr registers.
    #pragma unroll
    for (int ks = 0; ks < 4; ks++) {
        const int kk = ks * 16;
        uint32_t a0 = pack_h2(sfr[2 * ks    ][0], sfr[2 * ks    ][1]);
        uint32_t a1 = pack_h2(sfr[2 * ks    ][2], sfr[2 * ks    ][3]);
        uint32_t a2 = pack_h2(sfr[2 * ks + 1][0], sfr[2 * ks + 1][1]);
        uint32_t a3 = pack_h2(sfr[2 * ks + 1][2], sfr[2 * ks + 1][3]);
        #pragma unroll
        for (int jp = 0; jp < 4; jp++) {
            uint32_t b00, b01, b10, b11;
            ldsm4(b00, b01, b10, b11,
                  &Vs[((jp * 2 + jsel) * 8 + rbase) * 72 + kk + khalf]);
            mma16(ofr[2 * jp    ], a0, a1, a2, a3, b00, b01);
            mma16(ofr[2 * jp + 1], a0, a1, a2, a3, b10, b11);
        }
    }
}

// ---------------------------------------------------------------------------
// Kernel 2: flash attention (fp16 MMA + ldmatrix + register P), 2-stage
// cp.async KV pipeline, one barrier per KV tile, manual unroll-2.
// ---------------------------------------------------------------------------
__global__ __launch_bounds__(256, 2) void flash_kernel()
{
    const int q0  = blockIdx.x * 128;
    const int h   = blockIdx.y;
    const int kvh = h >> 2;

    extern __shared__ __half smh[];
    __half* QSP = smh;                    // [128][72] (Q, then O staging)
    __half* K0  = smh + 128 * 72;
    __half* K1  = K0 + 64 * 72;
    __half* V0  = K1 + 64 * 72;
    __half* V1  = V0 + 64 * 72;

    const int tid  = threadIdx.x;
    const int lane = tid & 31, warp = tid >> 5;
    const int g = lane >> 2, t = lane & 3;
    const int rw = warp * 16;

    const int rbase = lane & 7;
    const int arowoff = ((lane >> 3) & 1) * 8;
    const int akoff   = ((lane >> 4) & 1) * 8;
    const int khalf   = ((lane >> 3) & 1) * 8;
    const int jsel    = (lane >> 4) & 1;

    const __half* Qg = g_Qh + h * SEQ * HD + q0 * HD;
    const __half* Kg = g_Kh + kvh * SEQ * HD;
    const __half* Vg = g_Vt + kvh * HD * SEQ;   // [d][m]

    const int kvR[2] = { tid >> 3, (tid + 256) >> 3 };
    const int kvC[2] = { (tid & 7) * 8, ((tid + 256) & 7) * 8 };

    #pragma unroll
    for (int it = 0; it < 4; it++) {
        int id = tid + it * 256;
        int r = id >> 3, c8 = (id & 7) * 8;
        *(uint4*)&QSP[r * 72 + c8] = *(const uint4*)&Qg[r * 64 + c8];
    }
    __syncthreads();
    uint32_t qfr[4][4];
    #pragma unroll
    for (int ks = 0; ks < 4; ks++) {
        const int kk = ks * 16;
        ldsm4(qfr[ks][0], qfr[ks][1], qfr[ks][2], qfr[ks][3],
              &QSP[(rw + arowoff + rbase) * 72 + kk + akoff]);
    }

    #pragma unroll
    for (int it = 0; it < 2; it++) {
        cp16h(&K0[kvR[it] * 72 + kvC[it]], &Kg[kvR[it] * 64 + kvC[it]]);
        cp16h(&V0[kvR[it] * 72 + kvC[it]], &Vg[kvR[it] * SEQ + kvC[it]]);
    }
    asm volatile("cp.async.commit_group;");

    float m1 = -INFINITY, m2 = -INFINITY, l1 = 0.0f, l2 = 0.0f;
    float ofr[8][4] = {};

    for (int ktp = 0; ktp < 16; ktp++) {
        const int kt0 = 2 * ktp;
        flash_tile(K0, V0, K1, V1, true,
                   Kg + (kt0 + 1) * 64 * 64, Vg + (kt0 + 1) * 64,
                   kvR, kvC, qfr, ofr, m1, m2, l1, l2, rbase, khalf, jsel);
        const bool more = (kt0 + 2) < 32;
        const __half* Kgn = Kg + (more ? (kt0 + 2) * 64 * 64 : 0);
        const __half* Vgn = Vg + (more ? (kt0 + 2) * 64 : 0);
        flash_tile(K1, V1, K0, V0, more,
                   Kgn, Vgn, kvR, kvC, qfr, ofr, m1, m2, l1, l2, rbase, khalf, jsel);
    }

    float inv1 = 1.0f / l1;
    float inv2 = 1.0f / l2;
    __syncthreads();
    #pragma unroll
    for (int j = 0; j < 8; j++) {
        int col = j * 8 + 2 * t;
        *reinterpret_cast<uint32_t*>(&QSP[(rw + g    ) * 72 + col]) =
            pack_h2(ofr[j][0] * inv1, ofr[j][1] * inv1);
        *reinterpret_cast<uint32_t*>(&QSP[(rw + g + 8) * 72 + col]) =
            pack_h2(ofr[j][2] * inv2, ofr[j][3] * inv2);
    }
    __syncthreads();
    #pragma unroll
    for (int it = 0; it < 4; it++) {
        int id = tid + it * 256;
        int r = id >> 3, c8 = (id & 7) * 8;
        *(uint4*)&g_AOh[(q0 + r) * 1024 + h * 64 + c8] = *(const uint4*)&QSP[r * 72 + c8];
    }
}

// ---------------------------------------------------------------------------
// Kernel 3: output projection (fp16 m16n8k16 + ldmatrix), one barrier/iter.
// ---------------------------------------------------------------------------
__global__ __launch_bounds__(256, 3) void oproj_kernel(float* __restrict__ out)
{
    const int n0 = blockIdx.x * 64;
    const int m0 = blockIdx.y * 128;

    extern __shared__ float dynf[];
    __half* dynh = (__half*)dynf;
    float* Cs = dynf;

    const int tid  = threadIdx.x;
    const int lane = tid & 31, warp = tid >> 5;
    const int wm = warp & 3, wn = warp >> 2;
    const int g = lane >> 2, t = lane & 3;

    const int rbase = lane & 7;
    const int arowoff = ((lane >> 3) & 1) * 8;
    const int akoff   = ((lane >> 4) & 1) * 8;
    const int khalf   = ((lane >> 3) & 1) * 8;
    const int jsel    = (lane >> 4) & 1;

    const int aR[2] = { tid >> 2, (tid + 256) >> 2 };
    const int aC    = (tid & 3) * 8;
    const int bR    = tid >> 2;
    const int bC    = (tid & 3) * 8;

    float cfr[2][4][4] = {};

    {
        __half* As = dynh;  __half* Bs = dynh + 128 * 40;
        #pragma unroll
        for (int it = 0; it < 2; it++)
            cp16h(&As[aR[it] * 40 + aC], &g_AOh[(m0 + aR[it]) * 1024 + aC]);
        cp16h(&Bs[bR * 40 + bC], &g_WoT[(n0 + bR) * 1024 + bC]);
        asm volatile("cp.async.commit_group;");
    }

    #pragma unroll 2
    for (int k0 = 0; k0 < 1024; k0 += 32) {
        const int cur = (k0 >> 5) & 1;
        __half* As = dynh + (cur ? QSTAGE_H : 0);
        __half* Bs = As + 128 * 40;
        const bool has_next = (k0 + 32) < 1024;

        asm volatile("cp.async.wait_group 0;" ::: "memory");
        __syncthreads();

        if (has_next) {
            const int kn = k0 + 32;
            __half* Asn = dynh + (cur ? 0 : QSTAGE_H);
            __half* Bsn = Asn + 128 * 40;
            #pragma unroll
            for (int it = 0; it < 2; it++)
                cp16h(&Asn[aR[it] * 40 + aC], &g_AOh[(m0 + aR[it]) * 1024 + kn + aC]);
            cp16h(&Bsn[bR * 40 + bC], &g_WoT[(n0 + bR) * 1024 + kn + bC]);
            asm volatile("cp.async.commit_group;");
        }

        #pragma unroll
        for (int ks = 0; ks < 2; ks++) {
            const int kk = ks * 16;
            uint32_t af[2][4];
            #pragma unroll
            for (int f = 0; f < 2; f++)
                ldsm4(af[f][0], af[f][1], af[f][2], af[f][3],
                      &As[(wm * 32 + f * 16 + arowoff + rbase) * 40 + kk + akoff]);
            #pragma unroll
            for (int jp = 0; jp < 2; jp++) {
                uint32_t b00, b01, b10, b11;
                ldsm4(b00, b01, b10, b11,
                      &Bs[(wn * 32 + (jp * 2 + jsel) * 8 + rbase) * 40 + kk + khalf]);
                mma16(cfr[0][2 * jp    ], af[0][0], af[0][1], af[0][2], af[0][3], b00, b01);
                mma16(cfr[0][2 * jp + 1], af[0][0], af[0][1], af[0][2], af[0][3], b10, b11);
                mma16(cfr[1][2 * jp    ], af[1][0], af[1][1], af[1][2], af[1][3], b00, b01);
                mma16(cfr[1][2 * jp + 1], af[1][0], af[1][1], af[1][2], af[1][3], b10, b11);
            }
        }
    }
    __syncthreads();

    #pragma unroll
    for (int f = 0; f < 2; f++) {
        int rbm = wm * 32 + f * 16 + g;
        #pragma unroll
        for (int j = 0; j < 4; j++) {
            int col = wn * 32 + j * 8 + 2 * t;
            Cs[(rbm    ) * 68 + col    ] = cfr[f][j][0];
            Cs[(rbm    ) * 68 + col + 1] = cfr[f][j][1];
            Cs[(rbm + 8) * 68 + col    ] = cfr[f][j][2];
            Cs[(rbm + 8) * 68 + col + 1] = cfr[f][j][3];
        }
    }
    __syncthreads();
    #pragma unroll
    for (int it = 0; it < 8; it++) {
        int id = tid + it * 256;
        int r = id >> 4, c4 = (id & 15) * 4;
        *(float4*)&out[(m0 + r) * 1024 + n0 + c4] = *(const float4*)&Cs[r * 68 + c4];
    }
}

// ---------------------------------------------------------------------------
// Launch.
// ---------------------------------------------------------------------------
extern "C" void kernel_launch(void* const* d_in, const int* in_sizes, int n_in,
                              void* d_out, int out_size)
{
    const float* X  = (const float*)d_in[0];
    const float* cs = (const float*)d_in[1];
    const float* sn = (const float*)d_in[2];
    // d_in[3] = attention_mask (all ones) — unused
    const float* Wq = (const float*)d_in[4];
    const float* Wk = (const float*)d_in[5];
    const float* Wv = (const float*)d_in[6];
    const float* Wo = (const float*)d_in[7];
    float* out = (float*)d_out;

    prep_kernel<<<3584, 256>>>(X, Wq, Wk, Wv, Wo);

    const size_t smem_gemm = 128 * 68 * sizeof(float);   // 34816 (> 2 stages 30720)
    cudaFuncSetAttribute(qkv_rope_kernel,
                         cudaFuncAttributeMaxDynamicSharedMemorySize, (int)smem_gemm);
    cudaFuncSetAttribute(oproj_kernel,
                         cudaFuncAttributeMaxDynamicSharedMemorySize, (int)smem_gemm);

    qkv_rope_kernel<<<dim3(24, 16), 256, smem_gemm>>>(cs, sn);

    const size_t smem_flash = (128 * 72 + 4 * 64 * 72) * sizeof(__half);  // 55296 B
    cudaFuncSetAttribute(flash_kernel,
                         cudaFuncAttributeMaxDynamicSharedMemorySize, (int)smem_flash);
    flash_kernel<<<dim3(16, 16), 256, smem_flash>>>();

    oproj_kernel<<<dim3(16, 16), 256, smem_gemm>>>(out);
}

// round 17
// speedup vs baseline: 8.3474x; 1.0124x over previous
#include <cuda_runtime.h>
#include <cuda_fp16.h>
#include <math.h>
#include <stdint.h>

#define SEQ 2048
#define HID 1024
#define NH 16
#define NKV 4
#define HD 64
#define SCALING 0.125f
#define LOG2E 1.4426950408889634f

// ---------------------------------------------------------------------------
// Device globals (16B-aligned)
// ---------------------------------------------------------------------------
__device__ __align__(16) __half g_Qh[NH * SEQ * HD];    // [h][m][d], RoPE'd, *0.125*log2e
__device__ __align__(16) __half g_Kh[NKV * SEQ * HD];   // [kvh][m][d], RoPE'd
__device__ __align__(16) __half g_Vt[NKV * HD * SEQ];   // [kvh][d][m]  (TRANSPOSED)
__device__ __align__(16) __half g_AOh[SEQ * HID];       // [m][h*64+d]
__device__ __align__(16) __half g_Xh[SEQ * HID];        // [m][k]
__device__ __align__(16) __half g_WqT[1024 * HID];      // [n][k]
__device__ __align__(16) __half g_WkT[256 * HID];       // [n][k]
__device__ __align__(16) __half g_WvT[256 * HID];       // [n][k]
__device__ __align__(16) __half g_WoT[HID * 1024];      // [n][k]

// ---------------------------------------------------------------------------
// Helpers
// ---------------------------------------------------------------------------
__device__ __forceinline__ float ex2(float x) {
    float r;
    asm("ex2.approx.f32 %0, %1;" : "=f"(r) : "f"(x));
    return r;
}

__device__ __forceinline__ uint32_t pack_h2(float lo, float hi) {
    __half2 h = __floats2half2_rn(lo, hi);
    return *reinterpret_cast<uint32_t*>(&h);
}

__device__ __forceinline__ void mma16(float c[4],
                                      uint32_t a0, uint32_t a1, uint32_t a2, uint32_t a3,
                                      uint32_t b0, uint32_t b1) {
    asm volatile(
        "mma.sync.aligned.m16n8k16.row.col.f32.f16.f16.f32 "
        "{%0,%1,%2,%3}, {%4,%5,%6,%7}, {%8,%9}, {%0,%1,%2,%3};"
        : "+f"(c[0]), "+f"(c[1]), "+f"(c[2]), "+f"(c[3])
        : "r"(a0), "r"(a1), "r"(a2), "r"(a3), "r"(b0), "r"(b1));
}

__device__ __forceinline__ void cp16h(__half* smem_dst, const __half* gsrc) {
    uint32_t s = (uint32_t)__cvta_generic_to_shared(smem_dst);
    asm volatile("cp.async.ca.shared.global [%0], [%1], 16;" :: "r"(s), "l"(gsrc));
}

__device__ __forceinline__ void ldsm4(uint32_t& r0, uint32_t& r1,
                                      uint32_t& r2, uint32_t& r3, const __half* p) {
    uint32_t a = (uint32_t)__cvta_generic_to_shared(p);
    asm volatile("ldmatrix.sync.aligned.m8n8.x4.shared.b16 {%0,%1,%2,%3}, [%4];"
                 : "=r"(r0), "=r"(r1), "=r"(r2), "=r"(r3) : "r"(a));
}

// ---------------------------------------------------------------------------
// Kernel 0: merged prep — X fp32->fp16 copy (blocks 0..1023) +
// weight transpose+convert (blocks 1024..3583).
// ---------------------------------------------------------------------------
__global__ __launch_bounds__(256) void prep_kernel(
    const float* __restrict__ Xf,
    const float* __restrict__ Wq, const float* __restrict__ Wk,
    const float* __restrict__ Wv, const float* __restrict__ Wo)
{
    __shared__ float tile[32][33];
    const int id = blockIdx.x;
    if (id < 1024) {
        const float4* X = (const float4*)Xf;
        const int i = id * 256 + threadIdx.x;
        float4 v0 = X[2 * i], v1 = X[2 * i + 1];
        uint4 o;
        o.x = pack_h2(v0.x, v0.y);
        o.y = pack_h2(v0.z, v0.w);
        o.z = pack_h2(v1.x, v1.y);
        o.w = pack_h2(v1.z, v1.w);
        *reinterpret_cast<uint4*>(&g_Xh[8 * i]) = o;
        return;
    }
    const int wid = id - 1024;
    const float* src; __half* dst; int ncols, local;
    if (wid < 1024)      { src = Wq; dst = g_WqT; ncols = 1024; local = wid; }
    else if (wid < 1280) { src = Wk; dst = g_WkT; ncols = 256;  local = wid - 1024; }
    else if (wid < 1536) { src = Wv; dst = g_WvT; ncols = 256;  local = wid - 1280; }
    else                 { src = Wo; dst = g_WoT; ncols = 1024; local = wid - 1536; }
    const int ntiles = ncols / 32;
    const int kb = (local / ntiles) * 32;
    const int nb = (local % ntiles) * 32;
    const int tx = threadIdx.x & 31;
    const int ty = threadIdx.x >> 5;
    #pragma unroll
    for (int j = 0; j < 4; j++)
        tile[ty + j * 8][tx] = src[(kb + ty + j * 8) * ncols + nb + tx];
    __syncthreads();
    #pragma unroll
    for (int j = 0; j < 4; j++)
        dst[(nb + ty + j * 8) * 1024 + kb + tx] = __float2half_rn(tile[tx][ty + j * 8]);
}

// ---------------------------------------------------------------------------
// Kernel 1: fused QKV projection + RoPE (fp16 + ldmatrix), 3-stage cp.async.
// Block tile 128x64, BK=32, 8 warps (4m x 2n), warp tile 32x32.
// ---------------------------------------------------------------------------
#define QSTAGE_H (128 * 40 + 64 * 40)   // 7680 halves = 15360 B per stage

__global__ __launch_bounds__(256, 3) void qkv_rope_kernel(
    const float* __restrict__ cs,
    const float* __restrict__ sn)
{
    const int n0g = blockIdx.x * 64;
    const int m0  = blockIdx.y * 128;

    const __half* Wt;
    int ncol0, kind;                       // 0=Q, 1=K, 2=V
    if (n0g < 1024)       { Wt = g_WqT; ncol0 = n0g;        kind = 0; }
    else if (n0g < 1280)  { Wt = g_WkT; ncol0 = n0g - 1024; kind = 1; }
    else                  { Wt = g_WvT; ncol0 = n0g - 1280; kind = 2; }

    extern __shared__ float dynf[];
    __half* dynh = (__half*)dynf;
    float* Cs = dynf;                      // [128][68] f32 epilogue staging (overlaps stages)

    const int tid  = threadIdx.x;
    const int lane = tid & 31, warp = tid >> 5;
    const int wm = warp & 3, wn = warp >> 2;
    const int g = lane >> 2, t = lane & 3;

    const int rbase = lane & 7;
    const int arowoff = ((lane >> 3) & 1) * 8;
    const int akoff   = ((lane >> 4) & 1) * 8;
    const int khalf   = ((lane >> 3) & 1) * 8;
    const int jsel    = (lane >> 4) & 1;

    const int aR[2] = { tid >> 2, (tid + 256) >> 2 };
    const int aC    = (tid & 3) * 8;
    const int bR    = tid >> 2;
    const int bC    = (tid & 3) * 8;

    float cfr[2][4][4] = {};

    // Prologue: stages 0 and 1
    #pragma unroll
    for (int s = 0; s < 2; s++) {
        __half* As = dynh + s * QSTAGE_H;
        __half* Bs = As + 128 * 40;
        const int kn = s * 32;
        #pragma unroll
        for (int it = 0; it < 2; it++)
            cp16h(&As[aR[it] * 40 + aC], &g_Xh[(m0 + aR[it]) * 1024 + kn + aC]);
        cp16h(&Bs[bR * 40 + bC], &Wt[(ncol0 + bR) * 1024 + kn + bC]);
        asm volatile("cp.async.commit_group;");
    }

    int stage = 0;
    for (int k0 = 0; k0 < 1024; k0 += 32) {
        __half* As = dynh + stage * QSTAGE_H;
        __half* Bs = As + 128 * 40;
        const bool last = (k0 == 992);

        if (last) asm volatile("cp.async.wait_group 0;" ::: "memory");
        else      asm volatile("cp.async.wait_group 1;" ::: "memory");
        __syncthreads();   // stage k visible; all MMA on recycled buffer done

        if (k0 + 64 < 1024) {
            const int kn = k0 + 64;
            int snx = stage + 2; if (snx >= 3) snx -= 3;
            __half* Asn = dynh + snx * QSTAGE_H;
            __half* Bsn = Asn + 128 * 40;
            #pragma unroll
            for (int it = 0; it < 2; it++)
                cp16h(&Asn[aR[it] * 40 + aC], &g_Xh[(m0 + aR[it]) * 1024 + kn + aC]);
            cp16h(&Bsn[bR * 40 + bC], &Wt[(ncol0 + bR) * 1024 + kn + bC]);
            asm volatile("cp.async.commit_group;");
        }

        #pragma unroll
        for (int ks = 0; ks < 2; ks++) {
            const int kk = ks * 16;
            uint32_t af[2][4];
            #pragma unroll
            for (int f = 0; f < 2; f++)
                ldsm4(af[f][0], af[f][1], af[f][2], af[f][3],
                      &As[(wm * 32 + f * 16 + arowoff + rbase) * 40 + kk + akoff]);
            #pragma unroll
            for (int jp = 0; jp < 2; jp++) {
                uint32_t b00, b01, b10, b11;
                ldsm4(b00, b01, b10, b11,
                      &Bs[(wn * 32 + (jp * 2 + jsel) * 8 + rbase) * 40 + kk + khalf]);
                mma16(cfr[0][2 * jp    ], af[0][0], af[0][1], af[0][2], af[0][3], b00, b01);
                mma16(cfr[0][2 * jp + 1], af[0][0], af[0][1], af[0][2], af[0][3], b10, b11);
                mma16(cfr[1][2 * jp    ], af[1][0], af[1][1], af[1][2], af[1][3], b00, b01);
                mma16(cfr[1][2 * jp + 1], af[1][0], af[1][1], af[1][2], af[1][3], b10, b11);
            }
        }
        stage++; if (stage == 3) stage = 0;
    }
    __syncthreads();

    // fragments -> Cs (f32) for RoPE partner exchange
    #pragma unroll
    for (int f = 0; f < 2; f++) {
        int rbm = wm * 32 + f * 16 + g;
        #pragma unroll
        for (int j = 0; j < 4; j++) {
            int col = wn * 32 + j * 8 + 2 * t;
            Cs[(rbm    ) * 68 + col    ] = cfr[f][j][0];
            Cs[(rbm    ) * 68 + col + 1] = cfr[f][j][1];
            Cs[(rbm + 8) * 68 + col    ] = cfr[f][j][2];
            Cs[(rbm + 8) * 68 + col + 1] = cfr[f][j][3];
        }
    }
    __syncthreads();

    const int head_local = (kind == 0) ? (n0g >> 6) : (ncol0 >> 6);
    const int r0e = (tid >> 4) * 8;
    const int c0e = (tid & 15) * 4;
    const bool lowhalf = (c0e < 32);
    const float qscale = SCALING * LOG2E;

    #pragma unroll
    for (int i = 0; i < 8; i++) {
        const int r = r0e + i;
        const int m = m0 + r;
        float4 val = *(const float4*)&Cs[r * 68 + c0e];
        float4 outv;
        if (kind == 2) {
            outv = val;
        } else {
            float4 par = lowhalf ? *(const float4*)&Cs[r * 68 + c0e + 32]
                                 : *(const float4*)&Cs[r * 68 + c0e - 32];
            float psgn = lowhalf ? -1.0f : 1.0f;
            float4 c4 = *(const float4*)&cs[m * HD + c0e];
            float4 s4 = *(const float4*)&sn[m * HD + c0e];
            outv.x = val.x * c4.x + psgn * par.x * s4.x;
            outv.y = val.y * c4.y + psgn * par.y * s4.y;
            outv.z = val.z * c4.z + psgn * par.z * s4.z;
            outv.w = val.w * c4.w + psgn * par.w * s4.w;
            if (kind == 0) {
                outv.x *= qscale; outv.y *= qscale;
                outv.z *= qscale; outv.w *= qscale;
            }
        }
        if (kind == 2) {
            __half* vb = g_Vt + head_local * HD * SEQ;
            vb[(c0e + 0) * SEQ + m] = __float2half_rn(outv.x);
            vb[(c0e + 1) * SEQ + m] = __float2half_rn(outv.y);
            vb[(c0e + 2) * SEQ + m] = __float2half_rn(outv.z);
            vb[(c0e + 3) * SEQ + m] = __float2half_rn(outv.w);
        } else {
            uint2 o;
            o.x = pack_h2(outv.x, outv.y);
            o.y = pack_h2(outv.z, outv.w);
            __half* dstb = (kind == 0) ? g_Qh : g_Kh;
            *reinterpret_cast<uint2*>(&dstb[head_local * SEQ * HD + m * HD + c0e]) = o;
        }
    }
}

// ---------------------------------------------------------------------------
// Flash per-KV-tile body (register P-reuse; unchanged from round 16).
// ---------------------------------------------------------------------------
__device__ __forceinline__ void flash_tile(
    const __half* Ks, const __half* Vs,
    __half* Kn, __half* Vn, bool prefetch,
    const __half* Kgn, const __half* Vgn,
    const int* kvR, const int* kvC,
    const uint32_t (*qfr)[4], float (*ofr)[4],
    float& m1, float& m2, float& l1, float& l2,
    int rbase, int khalf, int jsel)
{
    asm volatile("cp.async.wait_group 0;" ::: "memory");
    __syncthreads();

    if (prefetch) {
        #pragma unroll
        for (int it = 0; it < 2; it++) {
            cp16h(&Kn[kvR[it] * 72 + kvC[it]], &Kgn[kvR[it] * 64 + kvC[it]]);
            cp16h(&Vn[kvR[it] * 72 + kvC[it]], &Vgn[kvR[it] * SEQ + kvC[it]]);
        }
        asm volatile("cp.async.commit_group;");
    }

    float sfr[8][4] = {};
    #pragma unroll
    for (int ks = 0; ks < 4; ks++) {
        const int kk = ks * 16;
        #pragma unroll
        for (int jp = 0; jp < 4; jp++) {
            uint32_t b00, b01, b10, b11;
            ldsm4(b00, b01, b10, b11,
                  &Ks[((jp * 2 + jsel) * 8 + rbase) * 72 + kk + khalf]);
            mma16(sfr[2 * jp    ], qfr[ks][0], qfr[ks][1], qfr[ks][2], qfr[ks][3], b00, b01);
            mma16(sfr[2 * jp + 1], qfr[ks][0], qfr[ks][1], qfr[ks][2], qfr[ks][3], b10, b11);
        }
    }

    float mloc1 = -INFINITY, mloc2 = -INFINITY;
    #pragma unroll
    for (int j = 0; j < 8; j++) {
        mloc1 = fmaxf(mloc1, fmaxf(sfr[j][0], sfr[j][1]));
        mloc2 = fmaxf(mloc2, fmaxf(sfr[j][2], sfr[j][3]));
    }
    mloc1 = fmaxf(mloc1, __shfl_xor_sync(0xffffffffu, mloc1, 1));
    mloc1 = fmaxf(mloc1, __shfl_xor_sync(0xffffffffu, mloc1, 2));
    mloc2 = fmaxf(mloc2, __shfl_xor_sync(0xffffffffu, mloc2, 1));
    mloc2 = fmaxf(mloc2, __shfl_xor_sync(0xffffffffu, mloc2, 2));
    float mnew1 = fmaxf(m1, mloc1);
    float mnew2 = fmaxf(m2, mloc2);
    float sc1 = ex2(m1 - mnew1);
    float sc2 = ex2(m2 - mnew2);
    float ss1 = 0.0f, ss2 = 0.0f;
    #pragma unroll
    for (int j = 0; j < 8; j++) {
        sfr[j][0] = ex2(sfr[j][0] - mnew1); ss1 += sfr[j][0];
        sfr[j][1] = ex2(sfr[j][1] - mnew1); ss1 += sfr[j][1];
        sfr[j][2] = ex2(sfr[j][2] - mnew2); ss2 += sfr[j][2];
        sfr[j][3] = ex2(sfr[j][3] - mnew2); ss2 += sfr[j][3];
    }
    ss1 += __shfl_xor_sync(0xffffffffu, ss1, 1);
    ss1 += __shfl_xor_sync(0xffffffffu, ss1, 2);
    ss2 += __shfl_xor_sync(0xffffffffu, ss2, 1);
    ss2 += __shfl_xor_sync(0xffffffffu, ss2, 2);
    l1 = l1 * sc1 + ss1;  m1 = mnew1;
    l2 = l2 * sc2 + ss2;  m2 = mnew2;

    #pragma unroll
    for (int j = 0; j < 8; j++) {
        ofr[j][0] *= sc1; ofr[j][1] *= sc1;
        ofr[j][2] *= sc2; ofr[j][3] *= sc2;
    }

    #pragma unroll
    for (int ks = 0; ks < 4; ks++) {
        const int kk = ks * 16;
        uint32_t a0 = pack_h2(sfr[2 * ks    ][0], sfr[2 * ks    ][1]);
        uint32_t a1 = pack_h2(sfr[2 * ks    ][2], sfr[2 * ks    ][3]);
        uint32_t a2 = pack_h2(sfr[2 * ks + 1][0], sfr[2 * ks + 1][1]);
        uint32_t a3 = pack_h2(sfr[2 * ks + 1][2], sfr[2 * ks + 1][3]);
        #pragma unroll
        for (int jp = 0; jp < 4; jp++) {
            uint32_t b00, b01, b10, b11;
            ldsm4(b00, b01, b10, b11,
                  &Vs[((jp * 2 + jsel) * 8 + rbase) * 72 + kk + khalf]);
            mma16(ofr[2 * jp    ], a0, a1, a2, a3, b00, b01);
            mma16(ofr[2 * jp + 1], a0, a1, a2, a3, b10, b11);
        }
    }
}

// ---------------------------------------------------------------------------
// Kernel 2: flash attention (unchanged from round 16).
// ---------------------------------------------------------------------------
__global__ __launch_bounds__(256, 2) void flash_kernel()
{
    const int q0  = blockIdx.x * 128;
    const int h   = blockIdx.y;
    const int kvh = h >> 2;

    extern __shared__ __half smh[];
    __half* QSP = smh;                    // [128][72]
    __half* K0  = smh + 128 * 72;
    __half* K1  = K0 + 64 * 72;
    __half* V0  = K1 + 64 * 72;
    __half* V1  = V0 + 64 * 72;

    const int tid  = threadIdx.x;
    const int lane = tid & 31, warp = tid >> 5;
    const int g = lane >> 2, t = lane & 3;
    const int rw = warp * 16;

    const int rbase = lane & 7;
    const int arowoff = ((lane >> 3) & 1) * 8;
    const int akoff   = ((lane >> 4) & 1) * 8;
    const int khalf   = ((lane >> 3) & 1) * 8;
    const int jsel    = (lane >> 4) & 1;

    const __half* Qg = g_Qh + h * SEQ * HD + q0 * HD;
    const __half* Kg = g_Kh + kvh * SEQ * HD;
    const __half* Vg = g_Vt + kvh * HD * SEQ;

    const int kvR[2] = { tid >> 3, (tid + 256) >> 3 };
    const int kvC[2] = { (tid & 7) * 8, ((tid + 256) & 7) * 8 };

    #pragma unroll
    for (int it = 0; it < 4; it++) {
        int id = tid + it * 256;
        int r = id >> 3, c8 = (id & 7) * 8;
        *(uint4*)&QSP[r * 72 + c8] = *(const uint4*)&Qg[r * 64 + c8];
    }
    __syncthreads();
    uint32_t qfr[4][4];
    #pragma unroll
    for (int ks = 0; ks < 4; ks++) {
        const int kk = ks * 16;
        ldsm4(qfr[ks][0], qfr[ks][1], qfr[ks][2], qfr[ks][3],
              &QSP[(rw + arowoff + rbase) * 72 + kk + akoff]);
    }

    #pragma unroll
    for (int it = 0; it < 2; it++) {
        cp16h(&K0[kvR[it] * 72 + kvC[it]], &Kg[kvR[it] * 64 + kvC[it]]);
        cp16h(&V0[kvR[it] * 72 + kvC[it]], &Vg[kvR[it] * SEQ + kvC[it]]);
    }
    asm volatile("cp.async.commit_group;");

    float m1 = -INFINITY, m2 = -INFINITY, l1 = 0.0f, l2 = 0.0f;
    float ofr[8][4] = {};

    for (int ktp = 0; ktp < 16; ktp++) {
        const int kt0 = 2 * ktp;
        flash_tile(K0, V0, K1, V1, true,
                   Kg + (kt0 + 1) * 64 * 64, Vg + (kt0 + 1) * 64,
                   kvR, kvC, qfr, ofr, m1, m2, l1, l2, rbase, khalf, jsel);
        const bool more = (kt0 + 2) < 32;
        const __half* Kgn = Kg + (more ? (kt0 + 2) * 64 * 64 : 0);
        const __half* Vgn = Vg + (more ? (kt0 + 2) * 64 : 0);
        flash_tile(K1, V1, K0, V0, more,
                   Kgn, Vgn, kvR, kvC, qfr, ofr, m1, m2, l1, l2, rbase, khalf, jsel);
    }

    float inv1 = 1.0f / l1;
    float inv2 = 1.0f / l2;
    __syncthreads();
    #pragma unroll
    for (int j = 0; j < 8; j++) {
        int col = j * 8 + 2 * t;
        *reinterpret_cast<uint32_t*>(&QSP[(rw + g    ) * 72 + col]) =
            pack_h2(ofr[j][0] * inv1, ofr[j][1] * inv1);
        *reinterpret_cast<uint32_t*>(&QSP[(rw + g + 8) * 72 + col]) =
            pack_h2(ofr[j][2] * inv2, ofr[j][3] * inv2);
    }
    __syncthreads();
    #pragma unroll
    for (int it = 0; it < 4; it++) {
        int id = tid + it * 256;
        int r = id >> 3, c8 = (id & 7) * 8;
        *(uint4*)&g_AOh[(q0 + r) * 1024 + h * 64 + c8] = *(const uint4*)&QSP[r * 72 + c8];
    }
}

// ---------------------------------------------------------------------------
// Kernel 3: output projection (fp16 + ldmatrix), 3-stage cp.async.
// ---------------------------------------------------------------------------
__global__ __launch_bounds__(256, 3) void oproj_kernel(float* __restrict__ out)
{
    const int n0 = blockIdx.x * 64;
    const int m0 = blockIdx.y * 128;

    extern __shared__ float dynf[];
    __half* dynh = (__half*)dynf;
    float* Cs = dynf;

    const int tid  = threadIdx.x;
    const int lane = tid & 31, warp = tid >> 5;
    const int wm = warp & 3, wn = warp >> 2;
    const int g = lane >> 2, t = lane & 3;

    const int rbase = lane & 7;
    const int arowoff = ((lane >> 3) & 1) * 8;
    const int akoff   = ((lane >> 4) & 1) * 8;
    const int khalf   = ((lane >> 3) & 1) * 8;
    const int jsel    = (lane >> 4) & 1;

    const int aR[2] = { tid >> 2, (tid + 256) >> 2 };
    const int aC    = (tid & 3) * 8;
    const int bR    = tid >> 2;
    const int bC    = (tid & 3) * 8;

    float cfr[2][4][4] = {};

    #pragma unroll
    for (int s = 0; s < 2; s++) {
        __half* As = dynh + s * QSTAGE_H;
        __half* Bs = As + 128 * 40;
        const int kn = s * 32;
        #pragma unroll
        for (int it = 0; it < 2; it++)
            cp16h(&As[aR[it] * 40 + aC], &g_AOh[(m0 + aR[it]) * 1024 + kn + aC]);
        cp16h(&Bs[bR * 40 + bC], &g_WoT[(n0 + bR) * 1024 + kn + bC]);
        asm volatile("cp.async.commit_group;");
    }

    int stage = 0;
    for (int k0 = 0; k0 < 1024; k0 += 32) {
        __half* As = dynh + stage * QSTAGE_H;
        __half* Bs = As + 128 * 40;
        const bool last = (k0 == 992);

        if (last) asm volatile("cp.async.wait_group 0;" ::: "memory");
        else      asm volatile("cp.async.wait_group 1;" ::: "memory");
        __syncthreads();

        if (k0 + 64 < 1024) {
            const int kn = k0 + 64;
            int snx = stage + 2; if (snx >= 3) snx -= 3;
            __half* Asn = dynh + snx * QSTAGE_H;
            __half* Bsn = Asn + 128 * 40;
            #pragma unroll
            for (int it = 0; it < 2; it++)
                cp16h(&Asn[aR[it] * 40 + aC], &g_AOh[(m0 + aR[it]) * 1024 + kn + aC]);
            cp16h(&Bsn[bR * 40 + bC], &g_WoT[(n0 + bR) * 1024 + kn + bC]);
            asm volatile("cp.async.commit_group;");
        }

        #pragma unroll
        for (int ks = 0; ks < 2; ks++) {
            const int kk = ks * 16;
            uint32_t af[2][4];
            #pragma unroll
            for (int f = 0; f < 2; f++)
                ldsm4(af[f][0], af[f][1], af[f][2], af[f][3],
                      &As[(wm * 32 + f * 16 + arowoff + rbase) * 40 + kk + akoff]);
            #pragma unroll
            for (int jp = 0; jp < 2; jp++) {
                uint32_t b00, b01, b10, b11;
                ldsm4(b00, b01, b10, b11,
                      &Bs[(wn * 32 + (jp * 2 + jsel) * 8 + rbase) * 40 + kk + khalf]);
                mma16(cfr[0][2 * jp    ], af[0][0], af[0][1], af[0][2], af[0][3], b00, b01);
                mma16(cfr[0][2 * jp + 1], af[0][0], af[0][1], af[0][2], af[0][3], b10, b11);
                mma16(cfr[1][2 * jp    ], af[1][0], af[1][1], af[1][2], af[1][3], b00, b01);
                mma16(cfr[1][2 * jp + 1], af[1][0], af[1][1], af[1][2], af[1][3], b10, b11);
            }
        }
        stage++; if (stage == 3) stage = 0;
    }
    __syncthreads();

    #pragma unroll
    for (int f = 0; f < 2; f++) {
        int rbm = wm * 32 + f * 16 + g;
        #pragma unroll
        for (int j = 0; j < 4; j++) {
            int col = wn * 32 + j * 8 + 2 * t;
            Cs[(rbm    ) * 68 + col    ] = cfr[f][j][0];
            Cs[(rbm    ) * 68 + col + 1] = cfr[f][j][1];
            Cs[(rbm + 8) * 68 + col    ] = cfr[f][j][2];
            Cs[(rbm + 8) * 68 + col + 1] = cfr[f][j][3];
        }
    }
    __syncthreads();
    #pragma unroll
    for (int it = 0; it < 8; it++) {
        int id = tid + it * 256;
        int r = id >> 4, c4 = (id & 15) * 4;
        *(float4*)&out[(m0 + r) * 1024 + n0 + c4] = *(const float4*)&Cs[r * 68 + c4];
    }
}

// ---------------------------------------------------------------------------
// Launch.
// ---------------------------------------------------------------------------
extern "C" void kernel_launch(void* const* d_in, const int* in_sizes, int n_in,
                              void* d_out, int out_size)
{
    const float* X  = (const float*)d_in[0];
    const float* cs = (const float*)d_in[1];
    const float* sn = (const float*)d_in[2];
    // d_in[3] = attention_mask (all ones) — unused
    const float* Wq = (const float*)d_in[4];
    const float* Wk = (const float*)d_in[5];
    const float* Wv = (const float*)d_in[6];
    const float* Wo = (const float*)d_in[7];
    float* out = (float*)d_out;

    prep_kernel<<<3584, 256>>>(X, Wq, Wk, Wv, Wo);

    // dyn smem: max(3 stages = 46080 B, Cs = 34816 B) = 46080 B
    const size_t smem_gemm = 3 * QSTAGE_H * sizeof(__half);
    cudaFuncSetAttribute(qkv_rope_kernel,
                         cudaFuncAttributeMaxDynamicSharedMemorySize, (int)smem_gemm);
    cudaFuncSetAttribute(oproj_kernel,
                         cudaFuncAttributeMaxDynamicSharedMemorySize, (int)smem_gemm);

    qkv_rope_kernel<<<dim3(24, 16), 256, smem_gemm>>>(cs, sn);

    const size_t smem_flash = (128 * 72 + 4 * 64 * 72) * sizeof(__half);  // 55296 B
    cudaFuncSetAttribute(flash_kernel,
                         cudaFuncAttributeMaxDynamicSharedMemorySize, (int)smem_flash);
    flash_kernel<<<dim3(16, 16), 256, smem_flash>>>();

    oproj_kernel<<<dim3(16, 16), 256, smem_gemm>>>(out);
}